// round 1
// baseline (speedup 1.0000x reference)
#include <cuda_runtime.h>
#include <math.h>

#define PB  256
#define PTc 64
#define NP  16384      // N = P*PT
#define M2  32768      // 2N
#define R2C 0.09f

// ---------------- scratch (static device globals; no allocations) ------------
__device__ float g_lf_s1[PB * 256];
__device__ float g_lf_m1[PB * 512];
__device__ float g_h1[NP * 256];
__device__ float g_h2[NP * 128];
__device__ float g_npos[NP * 3];
__device__ int   g_nbr[M2 * 9];
__device__ int   g_cnt[M2];
__device__ float g_posfea[(size_t)M2 * 128];
__device__ float g_g1[(size_t)M2 * 512];
__device__ float g_g2[(size_t)M2 * 256];
__device__ float g_rot[M2 * 9];

// ---------------- generic tiled fp32 GEMM ------------------------------------
// C[M,Nn] = epilogue(A[M,K] @ B[K,Nn])
// mode 0: raw       mode 1: relu(+bias)      mode 2: relu(+bias + lfE[rowp])
__global__ void gemm_k(const float* __restrict__ A, const float* __restrict__ B,
                       const float* __restrict__ bias, const float* __restrict__ lfE,
                       float* __restrict__ C, int M, int K, int Nn, int mode)
{
    __shared__ float As[64][17];
    __shared__ float Bs[16][65];
    const int bm = blockIdx.y * 64, bn = blockIdx.x * 64;
    const int t = threadIdx.x;
    const int ty = t >> 4, tx = t & 15;
    float acc[4][4] = {};
    for (int k0 = 0; k0 < K; k0 += 16) {
        #pragma unroll
        for (int i = 0; i < 4; i++) {
            int e = t + i * 256; int r = e >> 4, c = e & 15;
            As[r][c] = A[(size_t)(bm + r) * K + k0 + c];
        }
        #pragma unroll
        for (int i = 0; i < 4; i++) {
            int e = t + i * 256; int r = e >> 6, c = e & 63;
            Bs[r][c] = B[(size_t)(k0 + r) * Nn + bn + c];
        }
        __syncthreads();
        #pragma unroll
        for (int kk = 0; kk < 16; kk++) {
            float a[4], b[4];
            #pragma unroll
            for (int i = 0; i < 4; i++) a[i] = As[ty * 4 + i][kk];
            #pragma unroll
            for (int j = 0; j < 4; j++) b[j] = Bs[kk][tx * 4 + j];
            #pragma unroll
            for (int i = 0; i < 4; i++)
                #pragma unroll
                for (int j = 0; j < 4; j++)
                    acc[i][j] += a[i] * b[j];
        }
        __syncthreads();
    }
    #pragma unroll
    for (int i = 0; i < 4; i++) {
        int row = bm + ty * 4 + i;
        int rowp = 0;
        if (mode == 2) rowp = (row < NP) ? (row >> 6) : ((row - NP) >> 6);
        #pragma unroll
        for (int j = 0; j < 4; j++) {
            int col = bn + tx * 4 + j;
            float v = acc[i][j];
            if (mode >= 1) v += bias[col];
            if (mode == 2) v += lfE[(size_t)rowp * Nn + col];
            if (mode >= 1) v = fmaxf(v, 0.f);
            C[(size_t)row * Nn + col] = v;
        }
    }
}

// ------------- stage1: h1 = relu(lf_s1[p] + pos @ sw1[768:771] + sb1) --------
__global__ void k_s1(const float* __restrict__ pos, const float* __restrict__ sw1,
                     const float* __restrict__ sb1)
{
    int p = blockIdx.x, c = threadIdx.x;   // 256 threads = 256 channels
    __shared__ float sp[PTc * 3];
    for (int e = c; e < PTc * 3; e += 256) sp[e] = pos[p * PTc * 3 + e];
    float lfv = g_lf_s1[p * 256 + c] + sb1[c];
    float w0 = sw1[768 * 256 + c], w1 = sw1[769 * 256 + c], w2 = sw1[770 * 256 + c];
    __syncthreads();
    for (int j = 0; j < PTc; j++) {
        float v = lfv + sp[j * 3] * w0 + sp[j * 3 + 1] * w1 + sp[j * 3 + 2] * w2;
        g_h1[(size_t)(p * PTc + j) * 256 + c] = fmaxf(v, 0.f);
    }
}

// ------------- stage3: n_pos = tanh(relu(h2 @ sw3 + sb3)) + pos --------------
__global__ void k_s3(const float* __restrict__ pos, const float* __restrict__ sw3,
                     const float* __restrict__ sb3)
{
    int gt = blockIdx.x * blockDim.x + threadIdx.x;
    int w = gt >> 5, lane = gt & 31;
    if (w >= NP) return;
    float a0 = 0.f, a1 = 0.f, a2 = 0.f;
    #pragma unroll
    for (int s = 0; s < 4; s++) {
        int k = lane + 32 * s;
        float hv = g_h2[(size_t)w * 128 + k];
        a0 += hv * sw3[k * 3];
        a1 += hv * sw3[k * 3 + 1];
        a2 += hv * sw3[k * 3 + 2];
    }
    #pragma unroll
    for (int off = 16; off; off >>= 1) {
        a0 += __shfl_down_sync(0xffffffffu, a0, off);
        a1 += __shfl_down_sync(0xffffffffu, a1, off);
        a2 += __shfl_down_sync(0xffffffffu, a2, off);
    }
    if (lane == 0) {
        float v0 = fmaxf(a0 + sb3[0], 0.f);
        float v1 = fmaxf(a1 + sb3[1], 0.f);
        float v2 = fmaxf(a2 + sb3[2], 0.f);
        g_npos[w * 3 + 0] = tanhf(v0) + pos[w * 3 + 0];
        g_npos[w * 3 + 1] = tanhf(v1) + pos[w * 3 + 1];
        g_npos[w * 3 + 2] = tanhf(v2) + pos[w * 3 + 2];
    }
}

// ------------- KNN: per batch, 128 pts, top-9 by d2 (<= R2), tie = low idx ---
__global__ void k_knn(const float* __restrict__ pos)
{
    __shared__ float sx[128], sy[128], sz[128];
    int p = blockIdx.x, i = threadIdx.x;
    int g = p * PTc + (i & 63);
    float x, y, z;
    if (i < 64) { x = pos[g * 3]; y = pos[g * 3 + 1]; z = pos[g * 3 + 2]; }
    else        { x = g_npos[g * 3]; y = g_npos[g * 3 + 1]; z = g_npos[g * 3 + 2]; }
    sx[i] = x; sy[i] = y; sz[i] = z;
    __syncthreads();
    float bd[9]; int bi[9];
    #pragma unroll
    for (int q = 0; q < 9; q++) { bd[q] = 1e30f; bi[q] = 0; }
    int cnt = 0;
    for (int j = 0; j < 128; j++) {
        float dx = x - sx[j], dy = y - sy[j], dz = z - sz[j];
        float d2 = dx * dx + dy * dy + dz * dz;
        if (d2 <= R2C && d2 < bd[8]) {
            int ins = 0;
            #pragma unroll
            for (int q = 0; q < 9; q++) ins += (bd[q] <= d2) ? 1 : 0;
            #pragma unroll
            for (int q = 8; q > 0; q--) if (q > ins) { bd[q] = bd[q - 1]; bi[q] = bi[q - 1]; }
            #pragma unroll
            for (int q = 0; q < 9; q++) if (q == ins) { bd[q] = d2; bi[q] = j; }
            if (cnt < 9) cnt++;
        }
    }
    int pt = p * 128 + i;
    #pragma unroll
    for (int q = 0; q < 9; q++) g_nbr[pt * 9 + q] = bi[q];
    g_cnt[pt] = cnt;
}

// ------------- edge MLP 6->64->128 + max-agg, warp per point -----------------
__global__ void k_edge(const float* __restrict__ pos,
                       const float* __restrict__ cw1, const float* __restrict__ cb1,
                       const float* __restrict__ cw2, const float* __restrict__ cb2)
{
    __shared__ float scw2[64 * 128];
    __shared__ float scw1[6 * 64];
    __shared__ float sb1s[64], sb2s[128];
    __shared__ float m1buf[4][64];
    int t = threadIdx.x;
    for (int e = t; e < 64 * 128; e += 128) scw2[e] = cw2[e];
    for (int e = t; e < 384; e += 128) scw1[e] = cw1[e];
    if (t < 64) sb1s[t] = cb1[t];
    sb2s[t] = cb2[t];
    __syncthreads();
    int warp = t >> 5, lane = t & 31;
    int gw = blockIdx.x * 4 + warp;
    int nw = gridDim.x * 4;
    for (int pt = gw; pt < M2; pt += nw) {
        int p = pt >> 7, i = pt & 127;
        int gc = p * PTc + (i & 63);
        float cx, cy, cz;
        if (i < 64) { cx = pos[gc * 3]; cy = pos[gc * 3 + 1]; cz = pos[gc * 3 + 2]; }
        else        { cx = g_npos[gc * 3]; cy = g_npos[gc * 3 + 1]; cz = g_npos[gc * 3 + 2]; }
        int cnt = g_cnt[pt];
        float m0 = 0.f, m1 = 0.f, m2 = 0.f, m3 = 0.f;  // relu outputs >= 0
        for (int q = 0; q < cnt; q++) {
            int jn = g_nbr[pt * 9 + q];
            int gj = p * PTc + (jn & 63);
            float nx, ny, nz;
            if (jn < 64) { nx = pos[gj * 3]; ny = pos[gj * 3 + 1]; nz = pos[gj * 3 + 2]; }
            else         { nx = g_npos[gj * 3]; ny = g_npos[gj * 3 + 1]; nz = g_npos[gj * 3 + 2]; }
            float f3 = nx - cx, f4 = ny - cy, f5 = nz - cz;
            float v0 = sb1s[lane]
                + nx * scw1[lane]       + ny * scw1[64 + lane]  + nz * scw1[128 + lane]
                + f3 * scw1[192 + lane] + f4 * scw1[256 + lane] + f5 * scw1[320 + lane];
            int l2 = lane + 32;
            float v1 = sb1s[l2]
                + nx * scw1[l2]       + ny * scw1[64 + l2]  + nz * scw1[128 + l2]
                + f3 * scw1[192 + l2] + f4 * scw1[256 + l2] + f5 * scw1[320 + l2];
            m1buf[warp][lane]      = fmaxf(v0, 0.f);
            m1buf[warp][lane + 32] = fmaxf(v1, 0.f);
            __syncwarp();
            float a0 = sb2s[lane], a1 = sb2s[lane + 32], a2 = sb2s[lane + 64], a3 = sb2s[lane + 96];
            #pragma unroll
            for (int c = 0; c < 64; c++) {
                float mv = m1buf[warp][c];
                a0 += mv * scw2[c * 128 + lane];
                a1 += mv * scw2[c * 128 + lane + 32];
                a2 += mv * scw2[c * 128 + lane + 64];
                a3 += mv * scw2[c * 128 + lane + 96];
            }
            m0 = fmaxf(m0, a0); m1 = fmaxf(m1, a1); m2 = fmaxf(m2, a2); m3 = fmaxf(m3, a3);
            __syncwarp();
        }
        int row = (i < 64) ? (p * PTc + i) : (NP + p * PTc + (i - 64));
        g_posfea[(size_t)row * 128 + lane]      = m0;
        g_posfea[(size_t)row * 128 + lane + 32] = m1;
        g_posfea[(size_t)row * 128 + lane + 64] = m2;
        g_posfea[(size_t)row * 128 + lane + 96] = m3;
    }
}

// ------------- rot = relu(g2 @ mw3 + mb3), warp per row ----------------------
__global__ void k_rot(const float* __restrict__ mw3, const float* __restrict__ mb3)
{
    int gt = blockIdx.x * blockDim.x + threadIdx.x;
    int w = gt >> 5, lane = gt & 31;
    if (w >= M2) return;
    float a[9] = {};
    #pragma unroll
    for (int s = 0; s < 8; s++) {
        int k = lane + 32 * s;
        float gv = g_g2[(size_t)w * 256 + k];
        #pragma unroll
        for (int i = 0; i < 9; i++) a[i] += gv * mw3[k * 9 + i];
    }
    #pragma unroll
    for (int off = 16; off; off >>= 1)
        #pragma unroll
        for (int i = 0; i < 9; i++) a[i] += __shfl_down_sync(0xffffffffu, a[i], off);
    if (lane == 0) {
        #pragma unroll
        for (int i = 0; i < 9; i++) g_rot[w * 9 + i] = fmaxf(a[i] + mb3[i], 0.f);
    }
}

// ------------- outputs: plane_init then rot_constrain ------------------------
__global__ void k_out(const float* __restrict__ pos, float* __restrict__ out)
{
    int tid = blockIdx.x * blockDim.x + threadIdx.x;
    if (tid < 16 * M2) {
        int n = tid >> 4, t4 = tid & 15;
        const float XV[4] = {-0.2f, -0.066666666666666666f, 0.066666666666666666f, 0.2f};
        float nx = XV[t4 & 3], ny = XV[t4 >> 2];
        int m = tid & (M2 - 1);
        const float* rr = g_rot + (size_t)n * 9;
        float cx, cy, cz;
        if (m < NP) { cx = pos[m * 3]; cy = pos[m * 3 + 1]; cz = pos[m * 3 + 2]; }
        else { int mm = m - NP; cx = g_npos[mm * 3]; cy = g_npos[mm * 3 + 1]; cz = g_npos[mm * 3 + 2]; }
        out[(size_t)tid * 3 + 0] = rr[0] * nx + rr[1] * ny + cx;
        out[(size_t)tid * 3 + 1] = rr[3] * nx + rr[4] * ny + cy;
        out[(size_t)tid * 3 + 2] = rr[6] * nx + rr[7] * ny + cz;
    } else if (tid < 16 * M2 + M2) {
        int r = tid - 16 * M2;
        float rr[9];
        #pragma unroll
        for (int i = 0; i < 9; i++) rr[i] = g_rot[r * 9 + i];
        float* o = out + (size_t)16 * M2 * 3 + (size_t)r * 9;
        #pragma unroll
        for (int i = 0; i < 3; i++)
            #pragma unroll
            for (int j = 0; j < 3; j++)
                o[i * 3 + j] = rr[0 + i] * rr[0 + j] + rr[3 + i] * rr[3 + j] + rr[6 + i] * rr[6 + j];
    }
}

// ---------------- host launcher ----------------------------------------------
extern "C" void kernel_launch(void* const* d_in, const int* in_sizes, int n_in,
                              void* d_out, int out_size)
{
    const float* pos = (const float*)d_in[1];
    const float* lfea = (const float*)d_in[4];
    const float* sw1 = (const float*)d_in[5];
    const float* sb1 = (const float*)d_in[6];
    const float* sw2 = (const float*)d_in[7];
    const float* sb2 = (const float*)d_in[8];
    const float* sw3 = (const float*)d_in[9];
    const float* sb3 = (const float*)d_in[10];
    const float* cw1 = (const float*)d_in[11];
    const float* cb1 = (const float*)d_in[12];
    const float* cw2 = (const float*)d_in[13];
    const float* cb2 = (const float*)d_in[14];
    const float* mw1 = (const float*)d_in[15];
    const float* mb1 = (const float*)d_in[16];
    const float* mw2 = (const float*)d_in[17];
    const float* mb2 = (const float*)d_in[18];
    const float* mw3 = (const float*)d_in[19];
    const float* mb3 = (const float*)d_in[20];
    float* out = (float*)d_out;

    float *p_lf_s1, *p_lf_m1, *p_h1, *p_h2, *p_posfea, *p_g1, *p_g2;
    cudaGetSymbolAddress((void**)&p_lf_s1, g_lf_s1);
    cudaGetSymbolAddress((void**)&p_lf_m1, g_lf_m1);
    cudaGetSymbolAddress((void**)&p_h1, g_h1);
    cudaGetSymbolAddress((void**)&p_h2, g_h2);
    cudaGetSymbolAddress((void**)&p_posfea, g_posfea);
    cudaGetSymbolAddress((void**)&p_g1, g_g1);
    cudaGetSymbolAddress((void**)&p_g2, g_g2);

    // lf-part GEMMs (exploit row repetition)
    gemm_k<<<dim3(4, 4), 256>>>(lfea, sw1, nullptr, nullptr, p_lf_s1, 256, 768, 256, 0);
    gemm_k<<<dim3(8, 4), 256>>>(lfea, mw1, nullptr, nullptr, p_lf_m1, 256, 768, 512, 0);
    // h1 = relu(lf_s1[p] + pos-part + sb1)
    k_s1<<<256, 256>>>(pos, sw1, sb1);
    // h2 = relu(h1 @ sw2 + sb2)
    gemm_k<<<dim3(2, 256), 256>>>(p_h1, sw2, sb2, nullptr, p_h2, NP, 256, 128, 1);
    // n_pos
    k_s3<<<(NP * 32) / 256, 256>>>(pos, sw3, sb3);
    // knn
    k_knn<<<256, 128>>>(pos);
    // edge MLP + max aggregation -> pos_fea
    k_edge<<<1024, 128>>>(pos, cw1, cb1, cw2, cb2);
    // g1 = relu(pos_fea @ mw1[768:] + lf_m1[p] + mb1)
    gemm_k<<<dim3(8, 512), 256>>>(p_posfea, mw1 + 768 * 512, mb1, p_lf_m1, p_g1, M2, 128, 512, 2);
    // g2 = relu(g1 @ mw2 + mb2)
    gemm_k<<<dim3(4, 512), 256>>>(p_g1, mw2, mb2, nullptr, p_g2, M2, 512, 256, 1);
    // rot = relu(g2 @ mw3 + mb3)
    k_rot<<<(M2 * 32) / 256, 256>>>(mw3, mb3);
    // outputs
    k_out<<<(16 * M2 + M2 + 255) / 256, 256>>>(pos, out);
}

// round 2
// speedup vs baseline: 3.3056x; 3.3056x over previous
#include <cuda_runtime.h>
#include <math.h>

#define PB  256
#define PTc 64
#define NP  16384      // N = P*PT
#define M2  32768      // 2N
#define R2C 0.09f

// ---------------- scratch (static device globals; no allocations) ------------
__device__ float g_lf_s1[PB * 256];
__device__ float g_lf_m1[PB * 512];
__device__ float g_h1[NP * 256];
__device__ float g_h2[NP * 128];
__device__ float g_npos[NP * 3];
__device__ int   g_nbr[M2 * 9];
__device__ float g_posfea[(size_t)M2 * 128];
__device__ float g_g1[(size_t)M2 * 512];
__device__ float g_g2[(size_t)M2 * 256];
__device__ float g_rot[M2 * 9];

// ---------------- generic tiled fp32 GEMM (small / precision-critical) -------
// mode 0: raw       mode 1: relu(+bias)
__global__ void gemm_k(const float* __restrict__ A, const float* __restrict__ B,
                       const float* __restrict__ bias,
                       float* __restrict__ C, int M, int K, int Nn, int mode)
{
    __shared__ float As[64][17];
    __shared__ float Bs[16][65];
    const int bm = blockIdx.y * 64, bn = blockIdx.x * 64;
    const int t = threadIdx.x;
    const int ty = t >> 4, tx = t & 15;
    float acc[4][4] = {};
    for (int k0 = 0; k0 < K; k0 += 16) {
        #pragma unroll
        for (int i = 0; i < 4; i++) {
            int e = t + i * 256; int r = e >> 4, c = e & 15;
            As[r][c] = A[(size_t)(bm + r) * K + k0 + c];
        }
        #pragma unroll
        for (int i = 0; i < 4; i++) {
            int e = t + i * 256; int r = e >> 6, c = e & 63;
            Bs[r][c] = B[(size_t)(k0 + r) * Nn + bn + c];
        }
        __syncthreads();
        #pragma unroll
        for (int kk = 0; kk < 16; kk++) {
            float a[4], b[4];
            #pragma unroll
            for (int i = 0; i < 4; i++) a[i] = As[ty * 4 + i][kk];
            #pragma unroll
            for (int j = 0; j < 4; j++) b[j] = Bs[kk][tx * 4 + j];
            #pragma unroll
            for (int i = 0; i < 4; i++)
                #pragma unroll
                for (int j = 0; j < 4; j++)
                    acc[i][j] += a[i] * b[j];
        }
        __syncthreads();
    }
    #pragma unroll
    for (int i = 0; i < 4; i++) {
        int row = bm + ty * 4 + i;
        #pragma unroll
        for (int j = 0; j < 4; j++) {
            int col = bn + tx * 4 + j;
            float v = acc[i][j];
            if (mode >= 1) { v += bias[col]; v = fmaxf(v, 0.f); }
            C[(size_t)row * Nn + col] = v;
        }
    }
}

// ---------------- tf32 tensor-core GEMM (128x128 tile, BK=32) ----------------
// C = epilogue(A @ B); mode 1: relu(+bias), mode 2: relu(+bias + lfE[batch(row)])
__device__ __forceinline__ unsigned f2tf(float f) {
    unsigned r; asm("cvt.rna.tf32.f32 %0, %1;" : "=r"(r) : "f"(f)); return r;
}
__global__ void __launch_bounds__(256)
gemm_tc(const float* __restrict__ A, const float* __restrict__ B,
        const float* __restrict__ bias, const float* __restrict__ lfE,
        float* __restrict__ C, int M, int K, int Nn, int mode)
{
    __shared__ unsigned As[128][36];   // padded: frag loads conflict-free
    __shared__ unsigned Bs[32][136];   // stride%32==8 banks: conflict-free
    const int t = threadIdx.x;
    const int warp = t >> 5, lane = t & 31;
    const int g = lane >> 2, q = lane & 3;
    const int wm = warp >> 1, wn = warp & 1;   // 4x2 warp grid
    const int bm = blockIdx.y * 128, bn = blockIdx.x * 128;

    float c[2][8][4];
    #pragma unroll
    for (int i = 0; i < 2; i++)
        #pragma unroll
        for (int j = 0; j < 8; j++)
            #pragma unroll
            for (int e = 0; e < 4; e++) c[i][j][e] = 0.f;

    for (int k0 = 0; k0 < K; k0 += 32) {
        #pragma unroll
        for (int i = 0; i < 4; i++) {
            int e = t + i * 256; int r = e >> 3, c4 = e & 7;
            float4 v = *(const float4*)(A + (size_t)(bm + r) * K + k0 + c4 * 4);
            uint4 u = make_uint4(f2tf(v.x), f2tf(v.y), f2tf(v.z), f2tf(v.w));
            *(uint4*)&As[r][c4 * 4] = u;
        }
        #pragma unroll
        for (int i = 0; i < 4; i++) {
            int e = t + i * 256; int r = e >> 5, c4 = e & 31;
            float4 v = *(const float4*)(B + (size_t)(k0 + r) * Nn + bn + c4 * 4);
            uint4 u = make_uint4(f2tf(v.x), f2tf(v.y), f2tf(v.z), f2tf(v.w));
            *(uint4*)&Bs[r][c4 * 4] = u;
        }
        __syncthreads();
        #pragma unroll
        for (int ks = 0; ks < 4; ks++) {
            int k8 = ks * 8;
            unsigned a[2][4], b[8][2];
            #pragma unroll
            for (int mt = 0; mt < 2; mt++) {
                int r = wm * 32 + mt * 16 + g;
                a[mt][0] = As[r][k8 + q];
                a[mt][1] = As[r + 8][k8 + q];
                a[mt][2] = As[r][k8 + q + 4];
                a[mt][3] = As[r + 8][k8 + q + 4];
            }
            #pragma unroll
            for (int nt = 0; nt < 8; nt++) {
                int cn = wn * 64 + nt * 8 + g;
                b[nt][0] = Bs[k8 + q][cn];
                b[nt][1] = Bs[k8 + q + 4][cn];
            }
            #pragma unroll
            for (int mt = 0; mt < 2; mt++)
                #pragma unroll
                for (int nt = 0; nt < 8; nt++) {
                    asm volatile(
                        "mma.sync.aligned.m16n8k8.row.col.f32.tf32.tf32.f32 "
                        "{%0,%1,%2,%3},{%4,%5,%6,%7},{%8,%9},{%0,%1,%2,%3};"
                        : "+f"(c[mt][nt][0]), "+f"(c[mt][nt][1]),
                          "+f"(c[mt][nt][2]), "+f"(c[mt][nt][3])
                        : "r"(a[mt][0]), "r"(a[mt][1]), "r"(a[mt][2]), "r"(a[mt][3]),
                          "r"(b[nt][0]), "r"(b[nt][1]));
                }
        }
        __syncthreads();
    }

    #pragma unroll
    for (int mt = 0; mt < 2; mt++) {
        int row0 = bm + wm * 32 + mt * 16 + g;
        #pragma unroll
        for (int half = 0; half < 2; half++) {
            int row = row0 + half * 8;
            int rowp = 0;
            if (mode == 2) rowp = (row < NP) ? (row >> 6) : ((row - NP) >> 6);
            #pragma unroll
            for (int nt = 0; nt < 8; nt++) {
                int col = bn + wn * 64 + nt * 8 + q * 2;
                float v0 = c[mt][nt][half * 2 + 0] + bias[col];
                float v1 = c[mt][nt][half * 2 + 1] + bias[col + 1];
                if (mode == 2) {
                    v0 += lfE[(size_t)rowp * Nn + col];
                    v1 += lfE[(size_t)rowp * Nn + col + 1];
                }
                float2 o = make_float2(fmaxf(v0, 0.f), fmaxf(v1, 0.f));
                *(float2*)&C[(size_t)row * Nn + col] = o;
            }
        }
    }
}

// ------------- stage1: h1 = relu(lf_s1[p] + pos @ sw1[768:771] + sb1) --------
__global__ void k_s1(const float* __restrict__ pos, const float* __restrict__ sw1,
                     const float* __restrict__ sb1)
{
    int p = blockIdx.x, c = threadIdx.x;
    __shared__ float sp[PTc * 3];
    for (int e = c; e < PTc * 3; e += 256) sp[e] = pos[p * PTc * 3 + e];
    float lfv = g_lf_s1[p * 256 + c] + sb1[c];
    float w0 = sw1[768 * 256 + c], w1 = sw1[769 * 256 + c], w2 = sw1[770 * 256 + c];
    __syncthreads();
    for (int j = 0; j < PTc; j++) {
        float v = lfv + sp[j * 3] * w0 + sp[j * 3 + 1] * w1 + sp[j * 3 + 2] * w2;
        g_h1[(size_t)(p * PTc + j) * 256 + c] = fmaxf(v, 0.f);
    }
}

// ------------- stage3: n_pos = tanh(relu(h2 @ sw3 + sb3)) + pos --------------
__global__ void k_s3(const float* __restrict__ pos, const float* __restrict__ sw3,
                     const float* __restrict__ sb3)
{
    int gt = blockIdx.x * blockDim.x + threadIdx.x;
    int w = gt >> 5, lane = gt & 31;
    if (w >= NP) return;
    float a0 = 0.f, a1 = 0.f, a2 = 0.f;
    #pragma unroll
    for (int s = 0; s < 4; s++) {
        int k = lane + 32 * s;
        float hv = g_h2[(size_t)w * 128 + k];
        a0 += hv * sw3[k * 3];
        a1 += hv * sw3[k * 3 + 1];
        a2 += hv * sw3[k * 3 + 2];
    }
    #pragma unroll
    for (int off = 16; off; off >>= 1) {
        a0 += __shfl_down_sync(0xffffffffu, a0, off);
        a1 += __shfl_down_sync(0xffffffffu, a1, off);
        a2 += __shfl_down_sync(0xffffffffu, a2, off);
    }
    if (lane == 0) {
        g_npos[w * 3 + 0] = tanhf(fmaxf(a0 + sb3[0], 0.f)) + pos[w * 3 + 0];
        g_npos[w * 3 + 1] = tanhf(fmaxf(a1 + sb3[1], 0.f)) + pos[w * 3 + 1];
        g_npos[w * 3 + 2] = tanhf(fmaxf(a2 + sb3[2], 0.f)) + pos[w * 3 + 2];
    }
}

// ------------- KNN: per batch, 128 pts, top-9 (d2 <= R2), pad with bi[0] -----
__global__ void k_knn(const float* __restrict__ pos)
{
    __shared__ float sx[128], sy[128], sz[128];
    int p = blockIdx.x, i = threadIdx.x;
    int g = p * PTc + (i & 63);
    float x, y, z;
    if (i < 64) { x = pos[g * 3]; y = pos[g * 3 + 1]; z = pos[g * 3 + 2]; }
    else        { x = g_npos[g * 3]; y = g_npos[g * 3 + 1]; z = g_npos[g * 3 + 2]; }
    sx[i] = x; sy[i] = y; sz[i] = z;
    __syncthreads();
    float bd[9]; int bi[9];
    #pragma unroll
    for (int qq = 0; qq < 9; qq++) { bd[qq] = 1e30f; bi[qq] = 0; }
    int cnt = 0;
    for (int j = 0; j < 128; j++) {
        float dx = x - sx[j], dy = y - sy[j], dz = z - sz[j];
        float d2 = dx * dx + dy * dy + dz * dz;
        if (d2 <= R2C && d2 < bd[8]) {
            int ins = 0;
            #pragma unroll
            for (int qq = 0; qq < 9; qq++) ins += (bd[qq] <= d2) ? 1 : 0;
            #pragma unroll
            for (int qq = 8; qq > 0; qq--) if (qq > ins) { bd[qq] = bd[qq - 1]; bi[qq] = bi[qq - 1]; }
            #pragma unroll
            for (int qq = 0; qq < 9; qq++) if (qq == ins) { bd[qq] = d2; bi[qq] = j; }
            if (cnt < 9) cnt++;
        }
    }
    // pad invalid slots with neighbor 0 (self; duplicates are no-ops under max)
    #pragma unroll
    for (int qq = 1; qq < 9; qq++) if (qq >= cnt) bi[qq] = bi[0];
    int pt = p * 128 + i;
    #pragma unroll
    for (int qq = 0; qq < 9; qq++) g_nbr[pt * 9 + qq] = bi[qq];
}

// ------------- edge MLP 6->64->128 + max-agg, warp/point, 9 nbrs at once -----
__global__ void k_edge(const float* __restrict__ pos,
                       const float* __restrict__ cw1, const float* __restrict__ cb1,
                       const float* __restrict__ cw2, const float* __restrict__ cb2)
{
    __shared__ float scw2[64 * 128];
    __shared__ float scw1[6 * 64];
    __shared__ float sb1s[64], sb2s[128];
    __shared__ float m1buf[4][9][64];
    int t = threadIdx.x;
    for (int e = t; e < 64 * 128; e += 128) scw2[e] = cw2[e];
    for (int e = t; e < 384; e += 128) scw1[e] = cw1[e];
    if (t < 64) sb1s[t] = cb1[t];
    sb2s[t] = cb2[t];
    __syncthreads();
    int warp = t >> 5, lane = t & 31;
    int gw = blockIdx.x * 4 + warp;
    int nw = gridDim.x * 4;
    for (int pt = gw; pt < M2; pt += nw) {
        int p = pt >> 7, i = pt & 127;
        int gc = p * PTc + (i & 63);
        float cx, cy, cz;
        if (i < 64) { cx = pos[gc * 3]; cy = pos[gc * 3 + 1]; cz = pos[gc * 3 + 2]; }
        else        { cx = g_npos[gc * 3]; cy = g_npos[gc * 3 + 1]; cz = g_npos[gc * 3 + 2]; }
        // phase A: first layer for all 9 neighbors
        #pragma unroll
        for (int qn = 0; qn < 9; qn++) {
            int jn = g_nbr[pt * 9 + qn];
            int gj = p * PTc + (jn & 63);
            float nx, ny, nz;
            if (jn < 64) { nx = pos[gj * 3]; ny = pos[gj * 3 + 1]; nz = pos[gj * 3 + 2]; }
            else         { nx = g_npos[gj * 3]; ny = g_npos[gj * 3 + 1]; nz = g_npos[gj * 3 + 2]; }
            float f3 = nx - cx, f4 = ny - cy, f5 = nz - cz;
            float v0 = sb1s[lane]
                + nx * scw1[lane]       + ny * scw1[64 + lane]  + nz * scw1[128 + lane]
                + f3 * scw1[192 + lane] + f4 * scw1[256 + lane] + f5 * scw1[320 + lane];
            int l2 = lane + 32;
            float v1 = sb1s[l2]
                + nx * scw1[l2]       + ny * scw1[64 + l2]  + nz * scw1[128 + l2]
                + f3 * scw1[192 + l2] + f4 * scw1[256 + l2] + f5 * scw1[320 + l2];
            m1buf[warp][qn][lane]      = fmaxf(v0, 0.f);
            m1buf[warp][qn][lane + 32] = fmaxf(v1, 0.f);
        }
        __syncwarp();
        // phase B: second layer, all 9 neighbors share each cw2 column load
        float acc[9][4];
        #pragma unroll
        for (int qn = 0; qn < 9; qn++)
            #pragma unroll
            for (int j = 0; j < 4; j++) acc[qn][j] = 0.f;
        #pragma unroll 4
        for (int c = 0; c < 64; c++) {
            float w0 = scw2[c * 128 + lane];
            float w1 = scw2[c * 128 + lane + 32];
            float w2 = scw2[c * 128 + lane + 64];
            float w3 = scw2[c * 128 + lane + 96];
            #pragma unroll
            for (int qn = 0; qn < 9; qn++) {
                float mv = m1buf[warp][qn][c];
                acc[qn][0] += mv * w0;
                acc[qn][1] += mv * w1;
                acc[qn][2] += mv * w2;
                acc[qn][3] += mv * w3;
            }
        }
        float r0 = acc[0][0], r1 = acc[0][1], r2 = acc[0][2], r3 = acc[0][3];
        #pragma unroll
        for (int qn = 1; qn < 9; qn++) {
            r0 = fmaxf(r0, acc[qn][0]); r1 = fmaxf(r1, acc[qn][1]);
            r2 = fmaxf(r2, acc[qn][2]); r3 = fmaxf(r3, acc[qn][3]);
        }
        int row = (i < 64) ? (p * PTc + i) : (NP + p * PTc + (i - 64));
        g_posfea[(size_t)row * 128 + lane]      = fmaxf(r0 + sb2s[lane], 0.f);
        g_posfea[(size_t)row * 128 + lane + 32] = fmaxf(r1 + sb2s[lane + 32], 0.f);
        g_posfea[(size_t)row * 128 + lane + 64] = fmaxf(r2 + sb2s[lane + 64], 0.f);
        g_posfea[(size_t)row * 128 + lane + 96] = fmaxf(r3 + sb2s[lane + 96], 0.f);
        __syncwarp();
    }
}

// ------------- rot = relu(g2 @ mw3 + mb3), warp per row ----------------------
__global__ void k_rot(const float* __restrict__ mw3, const float* __restrict__ mb3)
{
    int gt = blockIdx.x * blockDim.x + threadIdx.x;
    int w = gt >> 5, lane = gt & 31;
    if (w >= M2) return;
    float a[9] = {};
    #pragma unroll
    for (int s = 0; s < 8; s++) {
        int k = lane + 32 * s;
        float gv = g_g2[(size_t)w * 256 + k];
        #pragma unroll
        for (int i = 0; i < 9; i++) a[i] += gv * mw3[k * 9 + i];
    }
    #pragma unroll
    for (int off = 16; off; off >>= 1)
        #pragma unroll
        for (int i = 0; i < 9; i++) a[i] += __shfl_down_sync(0xffffffffu, a[i], off);
    if (lane == 0) {
        #pragma unroll
        for (int i = 0; i < 9; i++) g_rot[w * 9 + i] = fmaxf(a[i] + mb3[i], 0.f);
    }
}

// ------------- outputs: plane_init then rot_constrain ------------------------
__global__ void k_out(const float* __restrict__ pos, float* __restrict__ out)
{
    int tid = blockIdx.x * blockDim.x + threadIdx.x;
    if (tid < 16 * M2) {
        int n = tid >> 4, t4 = tid & 15;
        const float XV[4] = {-0.2f, -0.066666666666666666f, 0.066666666666666666f, 0.2f};
        float nx = XV[t4 & 3], ny = XV[t4 >> 2];
        int m = tid & (M2 - 1);
        const float* rr = g_rot + (size_t)n * 9;
        float cx, cy, cz;
        if (m < NP) { cx = pos[m * 3]; cy = pos[m * 3 + 1]; cz = pos[m * 3 + 2]; }
        else { int mm = m - NP; cx = g_npos[mm * 3]; cy = g_npos[mm * 3 + 1]; cz = g_npos[mm * 3 + 2]; }
        out[(size_t)tid * 3 + 0] = rr[0] * nx + rr[1] * ny + cx;
        out[(size_t)tid * 3 + 1] = rr[3] * nx + rr[4] * ny + cy;
        out[(size_t)tid * 3 + 2] = rr[6] * nx + rr[7] * ny + cz;
    } else if (tid < 16 * M2 + M2) {
        int r = tid - 16 * M2;
        float rr[9];
        #pragma unroll
        for (int i = 0; i < 9; i++) rr[i] = g_rot[r * 9 + i];
        float* o = out + (size_t)16 * M2 * 3 + (size_t)r * 9;
        #pragma unroll
        for (int i = 0; i < 3; i++)
            #pragma unroll
            for (int j = 0; j < 3; j++)
                o[i * 3 + j] = rr[0 + i] * rr[0 + j] + rr[3 + i] * rr[3 + j] + rr[6 + i] * rr[6 + j];
    }
}

// ---------------- host launcher ----------------------------------------------
extern "C" void kernel_launch(void* const* d_in, const int* in_sizes, int n_in,
                              void* d_out, int out_size)
{
    const float* pos = (const float*)d_in[1];
    const float* lfea = (const float*)d_in[4];
    const float* sw1 = (const float*)d_in[5];
    const float* sb1 = (const float*)d_in[6];
    const float* sw2 = (const float*)d_in[7];
    const float* sb2 = (const float*)d_in[8];
    const float* sw3 = (const float*)d_in[9];
    const float* sb3 = (const float*)d_in[10];
    const float* cw1 = (const float*)d_in[11];
    const float* cb1 = (const float*)d_in[12];
    const float* cw2 = (const float*)d_in[13];
    const float* cb2 = (const float*)d_in[14];
    const float* mw1 = (const float*)d_in[15];
    const float* mb1 = (const float*)d_in[16];
    const float* mw2 = (const float*)d_in[17];
    const float* mb2 = (const float*)d_in[18];
    const float* mw3 = (const float*)d_in[19];
    const float* mb3 = (const float*)d_in[20];
    float* out = (float*)d_out;

    float *p_lf_s1, *p_lf_m1, *p_h1, *p_h2, *p_posfea, *p_g1, *p_g2;
    cudaGetSymbolAddress((void**)&p_lf_s1, g_lf_s1);
    cudaGetSymbolAddress((void**)&p_lf_m1, g_lf_m1);
    cudaGetSymbolAddress((void**)&p_h1, g_h1);
    cudaGetSymbolAddress((void**)&p_h2, g_h2);
    cudaGetSymbolAddress((void**)&p_posfea, g_posfea);
    cudaGetSymbolAddress((void**)&p_g1, g_g1);
    cudaGetSymbolAddress((void**)&p_g2, g_g2);

    // lf-part GEMMs (exploit row repetition) — fp32
    gemm_k<<<dim3(4, 4), 256>>>(lfea, sw1, nullptr, p_lf_s1, 256, 768, 256, 0);
    gemm_k<<<dim3(8, 4), 256>>>(lfea, mw1, nullptr, p_lf_m1, 256, 768, 512, 0);
    // h1 = relu(lf_s1[p] + pos-part + sb1)
    k_s1<<<256, 256>>>(pos, sw1, sb1);
    // h2 = relu(h1 @ sw2 + sb2) — fp32 (feeds KNN; keep exact)
    gemm_k<<<dim3(2, 256), 256>>>(p_h1, sw2, sb2, p_h2, NP, 256, 128, 1);
    // n_pos
    k_s3<<<(NP * 32) / 256, 256>>>(pos, sw3, sb3);
    // knn
    k_knn<<<256, 128>>>(pos);
    // edge MLP + max aggregation -> pos_fea
    k_edge<<<1024, 128>>>(pos, cw1, cb1, cw2, cb2);
    // g1 = relu(pos_fea @ mw1[768:] + lf_m1[p] + mb1) — tf32 tensor cores
    gemm_tc<<<dim3(4, 256), 256>>>(p_posfea, mw1 + 768 * 512, mb1, p_lf_m1, p_g1, M2, 128, 512, 2);
    // g2 = relu(g1 @ mw2 + mb2) — tf32 tensor cores
    gemm_tc<<<dim3(2, 256), 256>>>(p_g1, mw2, mb2, nullptr, p_g2, M2, 512, 256, 1);
    // rot = relu(g2 @ mw3 + mb3)
    k_rot<<<(M2 * 32) / 256, 256>>>(mw3, mb3);
    // outputs
    k_out<<<(16 * M2 + M2 + 255) / 256, 256>>>(pos, out);
}

// round 4
// speedup vs baseline: 5.0929x; 1.5407x over previous
#include <cuda_runtime.h>
#include <math.h>

#define PB  256
#define PTc 64
#define NP  16384      // N = P*PT
#define M2  32768      // 2N
#define R2C 0.09f

// ---------------- scratch (static device globals; no allocations) ------------
__device__ float g_lf_s1[PB * 256];
__device__ float g_lf_m1[PB * 512];
__device__ float g_h1[NP * 256];
__device__ float g_h2[NP * 128];
__device__ float g_npos[NP * 3];
__device__ int   g_nbr[M2 * 9];
__device__ float g_U[(size_t)M2 * 64];
__device__ float g_V[(size_t)M2 * 64];
__device__ float g_posfea[(size_t)M2 * 128];
__device__ float g_g1[(size_t)M2 * 512];
__device__ float g_g2[(size_t)M2 * 256];
__device__ float g_rot[M2 * 9];
__device__ float g_part[6 * 256 * 512];

__device__ __forceinline__ unsigned f2tf(float f) {
    unsigned r; asm("cvt.rna.tf32.f32 %0, %1;" : "=r"(r) : "f"(f)); return r;
}
#define MMA_TF32(cc, aa, bb) \
    asm volatile("mma.sync.aligned.m16n8k8.row.col.f32.tf32.tf32.f32 " \
        "{%0,%1,%2,%3},{%4,%5,%6,%7},{%8,%9},{%0,%1,%2,%3};" \
        : "+f"(cc[0]), "+f"(cc[1]), "+f"(cc[2]), "+f"(cc[3]) \
        : "r"(aa[0]), "r"(aa[1]), "r"(aa[2]), "r"(aa[3]), "r"(bb[0]), "r"(bb[1]))

// ---------------- split-K fp32 GEMM + reduce (small lf GEMMs) ----------------
__global__ void gemm_sk(const float* __restrict__ A, const float* __restrict__ B,
                        float* __restrict__ Cp, int M, int K, int Nn)
{
    __shared__ float As[64][17];
    __shared__ float Bs[16][65];
    const int bm = blockIdx.y * 64, bn = blockIdx.x * 64;
    const int t = threadIdx.x;
    const int ty = t >> 4, tx = t & 15;
    float acc[4][4] = {};
    int kbeg = blockIdx.z * 128, kend = kbeg + 128;
    for (int k0 = kbeg; k0 < kend; k0 += 16) {
        #pragma unroll
        for (int i = 0; i < 4; i++) {
            int e = t + i * 256; int r = e >> 4, c = e & 15;
            As[r][c] = A[(size_t)(bm + r) * K + k0 + c];
        }
        #pragma unroll
        for (int i = 0; i < 4; i++) {
            int e = t + i * 256; int r = e >> 6, c = e & 63;
            Bs[r][c] = B[(size_t)(k0 + r) * Nn + bn + c];
        }
        __syncthreads();
        #pragma unroll
        for (int kk = 0; kk < 16; kk++) {
            float a[4], b[4];
            #pragma unroll
            for (int i = 0; i < 4; i++) a[i] = As[ty * 4 + i][kk];
            #pragma unroll
            for (int j = 0; j < 4; j++) b[j] = Bs[kk][tx * 4 + j];
            #pragma unroll
            for (int i = 0; i < 4; i++)
                #pragma unroll
                for (int j = 0; j < 4; j++)
                    acc[i][j] += a[i] * b[j];
        }
        __syncthreads();
    }
    float* Cz = Cp + (size_t)blockIdx.z * M * Nn;
    #pragma unroll
    for (int i = 0; i < 4; i++)
        #pragma unroll
        for (int j = 0; j < 4; j++)
            Cz[(size_t)(bm + ty * 4 + i) * Nn + bn + tx * 4 + j] = acc[i][j];
}

__global__ void k_red(const float* __restrict__ Cp, float* __restrict__ C, int total)
{
    int e = blockIdx.x * 256 + threadIdx.x;
    if (e < total) {
        float s = 0.f;
        #pragma unroll
        for (int z = 0; z < 6; z++) s += Cp[(size_t)z * total + e];
        C[e] = s;
    }
}

// ---------------- tf32 tensor-core GEMM (128x128 tile, BK=32) ----------------
// mode 1: relu(+bias), mode 2: relu(+bias + lfE[batch(row)])
__global__ void __launch_bounds__(256)
gemm_tc(const float* __restrict__ A, const float* __restrict__ B,
        const float* __restrict__ bias, const float* __restrict__ lfE,
        float* __restrict__ C, int M, int K, int Nn, int mode)
{
    __shared__ unsigned As[128][36];
    __shared__ unsigned Bs[32][136];
    const int t = threadIdx.x;
    const int warp = t >> 5, lane = t & 31;
    const int g = lane >> 2, q = lane & 3;
    const int wm = warp >> 1, wn = warp & 1;
    const int bm = blockIdx.y * 128, bn = blockIdx.x * 128;

    float c[2][8][4];
    #pragma unroll
    for (int i = 0; i < 2; i++)
        #pragma unroll
        for (int j = 0; j < 8; j++)
            #pragma unroll
            for (int e = 0; e < 4; e++) c[i][j][e] = 0.f;

    for (int k0 = 0; k0 < K; k0 += 32) {
        #pragma unroll
        for (int i = 0; i < 4; i++) {
            int e = t + i * 256; int r = e >> 3, c4 = e & 7;
            float4 v = *(const float4*)(A + (size_t)(bm + r) * K + k0 + c4 * 4);
            uint4 u = make_uint4(f2tf(v.x), f2tf(v.y), f2tf(v.z), f2tf(v.w));
            *(uint4*)&As[r][c4 * 4] = u;
        }
        #pragma unroll
        for (int i = 0; i < 4; i++) {
            int e = t + i * 256; int r = e >> 5, c4 = e & 31;
            float4 v = *(const float4*)(B + (size_t)(k0 + r) * Nn + bn + c4 * 4);
            uint4 u = make_uint4(f2tf(v.x), f2tf(v.y), f2tf(v.z), f2tf(v.w));
            *(uint4*)&Bs[r][c4 * 4] = u;
        }
        __syncthreads();
        #pragma unroll
        for (int ks = 0; ks < 4; ks++) {
            int k8 = ks * 8;
            unsigned a[2][4], b[8][2];
            #pragma unroll
            for (int mt = 0; mt < 2; mt++) {
                int r = wm * 32 + mt * 16 + g;
                a[mt][0] = As[r][k8 + q];
                a[mt][1] = As[r + 8][k8 + q];
                a[mt][2] = As[r][k8 + q + 4];
                a[mt][3] = As[r + 8][k8 + q + 4];
            }
            #pragma unroll
            for (int nt = 0; nt < 8; nt++) {
                int cn = wn * 64 + nt * 8 + g;
                b[nt][0] = Bs[k8 + q][cn];
                b[nt][1] = Bs[k8 + q + 4][cn];
            }
            #pragma unroll
            for (int mt = 0; mt < 2; mt++)
                #pragma unroll
                for (int nt = 0; nt < 8; nt++)
                    MMA_TF32(c[mt][nt], a[mt], b[nt]);
        }
        __syncthreads();
    }

    #pragma unroll
    for (int mt = 0; mt < 2; mt++) {
        int row0 = bm + wm * 32 + mt * 16 + g;
        #pragma unroll
        for (int half = 0; half < 2; half++) {
            int row = row0 + half * 8;
            int rowp = 0;
            if (mode == 2) rowp = (row < NP) ? (row >> 6) : ((row - NP) >> 6);
            #pragma unroll
            for (int nt = 0; nt < 8; nt++) {
                int col = bn + wn * 64 + nt * 8 + q * 2;
                float v0 = c[mt][nt][half * 2 + 0] + bias[col];
                float v1 = c[mt][nt][half * 2 + 1] + bias[col + 1];
                if (mode == 2) {
                    v0 += lfE[(size_t)rowp * Nn + col];
                    v1 += lfE[(size_t)rowp * Nn + col + 1];
                }
                *(float2*)&C[(size_t)row * Nn + col] =
                    make_float2(fmaxf(v0, 0.f), fmaxf(v1, 0.f));
            }
        }
    }
}

// ---------------- 3xTF32 GEMM for h2 (fp32-grade, feeds KNN path) ------------
// Fixed Nn=128, tile 128x128, grid (1, M/128). relu(+bias).
__global__ void __launch_bounds__(256)
gemm_tc3(const float* __restrict__ A, const float* __restrict__ B,
         const float* __restrict__ bias, float* __restrict__ C, int M, int K)
{
    extern __shared__ unsigned sm3[];
    unsigned* Ah = sm3;                 // [128][36]
    unsigned* Al = Ah + 128 * 36;
    unsigned* Bh = Al + 128 * 36;       // [32][136]
    unsigned* Bl = Bh + 32 * 136;
    const int t = threadIdx.x;
    const int warp = t >> 5, lane = t & 31;
    const int g = lane >> 2, q = lane & 3;
    const int wm = warp >> 1, wn = warp & 1;
    const int bm = blockIdx.y * 128;

    float c[2][8][4];
    #pragma unroll
    for (int i = 0; i < 2; i++)
        #pragma unroll
        for (int j = 0; j < 8; j++)
            #pragma unroll
            for (int e = 0; e < 4; e++) c[i][j][e] = 0.f;

    for (int k0 = 0; k0 < K; k0 += 32) {
        #pragma unroll
        for (int i = 0; i < 4; i++) {
            int e = t + i * 256; int r = e >> 3, c4 = e & 7;
            float4 v = *(const float4*)(A + (size_t)(bm + r) * K + k0 + c4 * 4);
            unsigned h0 = f2tf(v.x), h1 = f2tf(v.y), h2v = f2tf(v.z), h3 = f2tf(v.w);
            *(uint4*)&Ah[r * 36 + c4 * 4] = make_uint4(h0, h1, h2v, h3);
            *(uint4*)&Al[r * 36 + c4 * 4] = make_uint4(
                f2tf(v.x - __uint_as_float(h0)), f2tf(v.y - __uint_as_float(h1)),
                f2tf(v.z - __uint_as_float(h2v)), f2tf(v.w - __uint_as_float(h3)));
        }
        #pragma unroll
        for (int i = 0; i < 4; i++) {
            int e = t + i * 256; int r = e >> 5, c4 = e & 31;
            float4 v = *(const float4*)(B + (size_t)(k0 + r) * 128 + c4 * 4);
            unsigned h0 = f2tf(v.x), h1 = f2tf(v.y), h2v = f2tf(v.z), h3 = f2tf(v.w);
            *(uint4*)&Bh[r * 136 + c4 * 4] = make_uint4(h0, h1, h2v, h3);
            *(uint4*)&Bl[r * 136 + c4 * 4] = make_uint4(
                f2tf(v.x - __uint_as_float(h0)), f2tf(v.y - __uint_as_float(h1)),
                f2tf(v.z - __uint_as_float(h2v)), f2tf(v.w - __uint_as_float(h3)));
        }
        __syncthreads();
        #pragma unroll
        for (int ks = 0; ks < 4; ks++) {
            int k8 = ks * 8;
            unsigned ah[2][4], al[2][4];
            #pragma unroll
            for (int mt = 0; mt < 2; mt++) {
                int r = wm * 32 + mt * 16 + g;
                ah[mt][0] = Ah[r * 36 + k8 + q];       al[mt][0] = Al[r * 36 + k8 + q];
                ah[mt][1] = Ah[(r + 8) * 36 + k8 + q]; al[mt][1] = Al[(r + 8) * 36 + k8 + q];
                ah[mt][2] = Ah[r * 36 + k8 + q + 4];   al[mt][2] = Al[r * 36 + k8 + q + 4];
                ah[mt][3] = Ah[(r + 8) * 36 + k8 + q + 4]; al[mt][3] = Al[(r + 8) * 36 + k8 + q + 4];
            }
            #pragma unroll
            for (int nt = 0; nt < 8; nt++) {
                int cn = wn * 64 + nt * 8 + g;
                unsigned bh[2], bl[2];
                bh[0] = Bh[(k8 + q) * 136 + cn];     bh[1] = Bh[(k8 + q + 4) * 136 + cn];
                bl[0] = Bl[(k8 + q) * 136 + cn];     bl[1] = Bl[(k8 + q + 4) * 136 + cn];
                #pragma unroll
                for (int mt = 0; mt < 2; mt++) {
                    MMA_TF32(c[mt][nt], al[mt], bh);
                    MMA_TF32(c[mt][nt], ah[mt], bl);
                    MMA_TF32(c[mt][nt], ah[mt], bh);
                }
            }
        }
        __syncthreads();
    }

    #pragma unroll
    for (int mt = 0; mt < 2; mt++) {
        int row0 = bm + wm * 32 + mt * 16 + g;
        #pragma unroll
        for (int half = 0; half < 2; half++) {
            int row = row0 + half * 8;
            #pragma unroll
            for (int nt = 0; nt < 8; nt++) {
                int col = wn * 64 + nt * 8 + q * 2;
                float v0 = c[mt][nt][half * 2 + 0] + bias[col];
                float v1 = c[mt][nt][half * 2 + 1] + bias[col + 1];
                *(float2*)&C[(size_t)row * 128 + col] =
                    make_float2(fmaxf(v0, 0.f), fmaxf(v1, 0.f));
            }
        }
    }
}

// ------------- stage1: h1 = relu(lf_s1[p] + pos @ sw1[768:771] + sb1) --------
__global__ void k_s1(const float* __restrict__ pos, const float* __restrict__ sw1,
                     const float* __restrict__ sb1)
{
    int p = blockIdx.x, c = threadIdx.x;
    __shared__ float sp[PTc * 3];
    for (int e = c; e < PTc * 3; e += 256) sp[e] = pos[p * PTc * 3 + e];
    float lfv = g_lf_s1[p * 256 + c] + sb1[c];
    float w0 = sw1[768 * 256 + c], w1 = sw1[769 * 256 + c], w2 = sw1[770 * 256 + c];
    __syncthreads();
    for (int j = 0; j < PTc; j++) {
        float v = lfv + sp[j * 3] * w0 + sp[j * 3 + 1] * w1 + sp[j * 3 + 2] * w2;
        g_h1[(size_t)(p * PTc + j) * 256 + c] = fmaxf(v, 0.f);
    }
}

// ------------- stage3: n_pos = tanh(relu(h2 @ sw3 + sb3)) + pos --------------
__global__ void k_s3(const float* __restrict__ pos, const float* __restrict__ sw3,
                     const float* __restrict__ sb3)
{
    int gt = blockIdx.x * blockDim.x + threadIdx.x;
    int w = gt >> 5, lane = gt & 31;
    if (w >= NP) return;
    float a0 = 0.f, a1 = 0.f, a2 = 0.f;
    #pragma unroll
    for (int s = 0; s < 4; s++) {
        int k = lane + 32 * s;
        float hv = g_h2[(size_t)w * 128 + k];
        a0 += hv * sw3[k * 3];
        a1 += hv * sw3[k * 3 + 1];
        a2 += hv * sw3[k * 3 + 2];
    }
    #pragma unroll
    for (int off = 16; off; off >>= 1) {
        a0 += __shfl_down_sync(0xffffffffu, a0, off);
        a1 += __shfl_down_sync(0xffffffffu, a1, off);
        a2 += __shfl_down_sync(0xffffffffu, a2, off);
    }
    if (lane == 0) {
        g_npos[w * 3 + 0] = tanhf(fmaxf(a0 + sb3[0], 0.f)) + pos[w * 3 + 0];
        g_npos[w * 3 + 1] = tanhf(fmaxf(a1 + sb3[1], 0.f)) + pos[w * 3 + 1];
        g_npos[w * 3 + 2] = tanhf(fmaxf(a2 + sb3[2], 0.f)) + pos[w * 3 + 2];
    }
}

// ------------- KNN: per batch, 128 pts, top-9 (d2 <= R2), pad with bi[0] -----
__global__ void k_knn(const float* __restrict__ pos)
{
    __shared__ float sx[128], sy[128], sz[128];
    int p = blockIdx.x, i = threadIdx.x;
    int g = p * PTc + (i & 63);
    float x, y, z;
    if (i < 64) { x = pos[g * 3]; y = pos[g * 3 + 1]; z = pos[g * 3 + 2]; }
    else        { x = g_npos[g * 3]; y = g_npos[g * 3 + 1]; z = g_npos[g * 3 + 2]; }
    sx[i] = x; sy[i] = y; sz[i] = z;
    __syncthreads();
    float bd[9]; int bi[9];
    #pragma unroll
    for (int qq = 0; qq < 9; qq++) { bd[qq] = 1e30f; bi[qq] = 0; }
    int cnt = 0;
    for (int j = 0; j < 128; j++) {
        float dx = x - sx[j], dy = y - sy[j], dz = z - sz[j];
        float d2 = dx * dx + dy * dy + dz * dz;
        if (d2 <= R2C && d2 < bd[8]) {
            int ins = 0;
            #pragma unroll
            for (int qq = 0; qq < 9; qq++) ins += (bd[qq] <= d2) ? 1 : 0;
            #pragma unroll
            for (int qq = 8; qq > 0; qq--) if (qq > ins) { bd[qq] = bd[qq - 1]; bi[qq] = bi[qq - 1]; }
            #pragma unroll
            for (int qq = 0; qq < 9; qq++) if (qq == ins) { bd[qq] = d2; bi[qq] = j; }
            if (cnt < 9) cnt++;
        }
    }
    #pragma unroll
    for (int qq = 1; qq < 9; qq++) if (qq >= cnt) bi[qq] = bi[0];
    int pt = p * 128 + i;
    #pragma unroll
    for (int qq = 0; qq < 9; qq++) g_nbr[pt * 9 + qq] = bi[qq];
}

// ------------- U/V precompute: U = cb1 + n.(wn+wr), V = c.wr -----------------
__global__ void k_uv(const float* __restrict__ pos, const float* __restrict__ cw1,
                     const float* __restrict__ cb1)
{
    int tid = blockIdx.x * 256 + threadIdx.x;   // M2*64
    int pt = tid >> 6, k = tid & 63;
    int p = pt >> 7, i = pt & 127;
    int gi = p * PTc + (i & 63);
    float x, y, z;
    if (i < 64) { x = pos[gi * 3]; y = pos[gi * 3 + 1]; z = pos[gi * 3 + 2]; }
    else        { x = g_npos[gi * 3]; y = g_npos[gi * 3 + 1]; z = g_npos[gi * 3 + 2]; }
    float wn0 = cw1[k],       wn1 = cw1[64 + k],  wn2 = cw1[128 + k];
    float wr0 = cw1[192 + k], wr1 = cw1[256 + k], wr2 = cw1[320 + k];
    g_U[tid] = cb1[k] + x * (wn0 + wr0) + y * (wn1 + wr1) + z * (wn2 + wr2);
    g_V[tid] = x * wr0 + y * wr1 + z * wr2;
}

// ------------- edge MLP phase-B as tf32 mma with max over 9 qn-blocks --------
// block = 64 points (half a batch); A = m1 [9*64 rows][64], B = cw2 [64][128]
__global__ void __launch_bounds__(256)
k_edge2(const float* __restrict__ cw2, const float* __restrict__ cb2)
{
    extern __shared__ unsigned esm[];
    unsigned* As = esm;               // [576][68]
    unsigned* Bs = esm + 576 * 68;    // [64][136]
    const int t = threadIdx.x;
    const int warp = t >> 5, lane = t & 31;
    const int p = blockIdx.x >> 1, half = blockIdx.x & 1;

    for (int e = t; e < 64 * 128; e += 256) {
        int r = e >> 7, cc = e & 127;
        Bs[r * 136 + cc] = f2tf(cw2[e]);
    }
    for (int row = warp; row < 576; row += 8) {
        int qn = row >> 6, pl = row & 63;
        int i = half * 64 + pl;
        int pt = p * 128 + i;
        int nb = g_nbr[pt * 9 + qn];
        const float* Ur = g_U + (size_t)(p * 128 + nb) * 64;
        const float* Vr = g_V + (size_t)pt * 64;
        As[row * 68 + lane]      = f2tf(fmaxf(Ur[lane] - Vr[lane], 0.f));
        As[row * 68 + lane + 32] = f2tf(fmaxf(Ur[lane + 32] - Vr[lane + 32], 0.f));
    }
    __syncthreads();

    const int g = lane >> 2, q = lane & 3;
    float mx[4][2][4];
    #pragma unroll 1
    for (int qn = 0; qn < 9; qn++) {
        float acc[4][2][4];
        #pragma unroll
        for (int mt = 0; mt < 4; mt++)
            #pragma unroll
            for (int nt = 0; nt < 2; nt++)
                #pragma unroll
                for (int e = 0; e < 4; e++) acc[mt][nt][e] = 0.f;
        #pragma unroll
        for (int ks = 0; ks < 8; ks++) {
            int k8 = ks * 8;
            unsigned a[4][4];
            #pragma unroll
            for (int mt = 0; mt < 4; mt++) {
                int r = qn * 64 + mt * 16 + g;
                a[mt][0] = As[r * 68 + k8 + q];
                a[mt][1] = As[(r + 8) * 68 + k8 + q];
                a[mt][2] = As[r * 68 + k8 + q + 4];
                a[mt][3] = As[(r + 8) * 68 + k8 + q + 4];
            }
            unsigned b[2][2];
            #pragma unroll
            for (int nt = 0; nt < 2; nt++) {
                int cn = warp * 16 + nt * 8 + g;
                b[nt][0] = Bs[(k8 + q) * 136 + cn];
                b[nt][1] = Bs[(k8 + q + 4) * 136 + cn];
            }
            #pragma unroll
            for (int mt = 0; mt < 4; mt++)
                #pragma unroll
                for (int nt = 0; nt < 2; nt++)
                    MMA_TF32(acc[mt][nt], a[mt], b[nt]);
        }
        if (qn == 0) {
            #pragma unroll
            for (int mt = 0; mt < 4; mt++)
                #pragma unroll
                for (int nt = 0; nt < 2; nt++)
                    #pragma unroll
                    for (int e = 0; e < 4; e++) mx[mt][nt][e] = acc[mt][nt][e];
        } else {
            #pragma unroll
            for (int mt = 0; mt < 4; mt++)
                #pragma unroll
                for (int nt = 0; nt < 2; nt++)
                    #pragma unroll
                    for (int e = 0; e < 4; e++)
                        mx[mt][nt][e] = fmaxf(mx[mt][nt][e], acc[mt][nt][e]);
        }
    }

    #pragma unroll
    for (int mt = 0; mt < 4; mt++) {
        #pragma unroll
        for (int hh = 0; hh < 2; hh++) {
            int pl = mt * 16 + g + hh * 8;
            size_t row = (half == 0) ? (size_t)(p * 64 + pl)
                                     : (size_t)(NP + p * 64 + pl);
            #pragma unroll
            for (int nt = 0; nt < 2; nt++) {
                int col = warp * 16 + nt * 8 + q * 2;
                float v0 = fmaxf(mx[mt][nt][hh * 2 + 0] + cb2[col], 0.f);
                float v1 = fmaxf(mx[mt][nt][hh * 2 + 1] + cb2[col + 1], 0.f);
                *(float2*)&g_posfea[row * 128 + col] = make_float2(v0, v1);
            }
        }
    }
}

// ------------- rot = relu(g2 @ mw3 + mb3), warp per row ----------------------
__global__ void k_rot(const float* __restrict__ mw3, const float* __restrict__ mb3)
{
    int gt = blockIdx.x * blockDim.x + threadIdx.x;
    int w = gt >> 5, lane = gt & 31;
    if (w >= M2) return;
    float a[9] = {};
    #pragma unroll
    for (int s = 0; s < 8; s++) {
        int k = lane + 32 * s;
        float gv = g_g2[(size_t)w * 256 + k];
        #pragma unroll
        for (int i = 0; i < 9; i++) a[i] += gv * mw3[k * 9 + i];
    }
    #pragma unroll
    for (int off = 16; off; off >>= 1)
        #pragma unroll
        for (int i = 0; i < 9; i++) a[i] += __shfl_down_sync(0xffffffffu, a[i], off);
    if (lane == 0) {
        #pragma unroll
        for (int i = 0; i < 9; i++) g_rot[w * 9 + i] = fmaxf(a[i] + mb3[i], 0.f);
    }
}

// ------------- outputs: plane_init then rot_constrain ------------------------
__global__ void k_out(const float* __restrict__ pos, float* __restrict__ out)
{
    int tid = blockIdx.x * blockDim.x + threadIdx.x;
    if (tid < 16 * M2) {
        int n = tid >> 4, t4 = tid & 15;
        const float XV[4] = {-0.2f, -0.066666666666666666f, 0.066666666666666666f, 0.2f};
        float nx = XV[t4 & 3], ny = XV[t4 >> 2];
        int m = tid & (M2 - 1);
        const float* rr = g_rot + (size_t)n * 9;
        float cx, cy, cz;
        if (m < NP) { cx = pos[m * 3]; cy = pos[m * 3 + 1]; cz = pos[m * 3 + 2]; }
        else { int mm = m - NP; cx = g_npos[mm * 3]; cy = g_npos[mm * 3 + 1]; cz = g_npos[mm * 3 + 2]; }
        out[(size_t)tid * 3 + 0] = rr[0] * nx + rr[1] * ny + cx;
        out[(size_t)tid * 3 + 1] = rr[3] * nx + rr[4] * ny + cy;
        out[(size_t)tid * 3 + 2] = rr[6] * nx + rr[7] * ny + cz;
    } else if (tid < 16 * M2 + M2) {
        int r = tid - 16 * M2;
        float rr[9];
        #pragma unroll
        for (int i = 0; i < 9; i++) rr[i] = g_rot[r * 9 + i];
        float* o = out + (size_t)16 * M2 * 3 + (size_t)r * 9;
        #pragma unroll
        for (int i = 0; i < 3; i++)
            #pragma unroll
            for (int j = 0; j < 3; j++)
                o[i * 3 + j] = rr[0 + i] * rr[0 + j] + rr[3 + i] * rr[3 + j] + rr[6 + i] * rr[6 + j];
    }
}

// ---------------- host launcher ----------------------------------------------
extern "C" void kernel_launch(void* const* d_in, const int* in_sizes, int n_in,
                              void* d_out, int out_size)
{
    const float* pos = (const float*)d_in[1];
    const float* lfea = (const float*)d_in[4];
    const float* sw1 = (const float*)d_in[5];
    const float* sb1 = (const float*)d_in[6];
    const float* sw2 = (const float*)d_in[7];
    const float* sb2 = (const float*)d_in[8];
    const float* sw3 = (const float*)d_in[9];
    const float* sb3 = (const float*)d_in[10];
    const float* cw1 = (const float*)d_in[11];
    const float* cb1 = (const float*)d_in[12];
    const float* cw2 = (const float*)d_in[13];
    const float* cb2 = (const float*)d_in[14];
    const float* mw1 = (const float*)d_in[15];
    const float* mb1 = (const float*)d_in[16];
    const float* mw2 = (const float*)d_in[17];
    const float* mb2 = (const float*)d_in[18];
    const float* mw3 = (const float*)d_in[19];
    const float* mb3 = (const float*)d_in[20];
    float* out = (float*)d_out;

    float *p_lf_s1, *p_lf_m1, *p_h1, *p_h2, *p_posfea, *p_g1, *p_g2, *p_part;
    cudaGetSymbolAddress((void**)&p_lf_s1, g_lf_s1);
    cudaGetSymbolAddress((void**)&p_lf_m1, g_lf_m1);
    cudaGetSymbolAddress((void**)&p_h1, g_h1);
    cudaGetSymbolAddress((void**)&p_h2, g_h2);
    cudaGetSymbolAddress((void**)&p_posfea, g_posfea);
    cudaGetSymbolAddress((void**)&p_g1, g_g1);
    cudaGetSymbolAddress((void**)&p_g2, g_g2);
    cudaGetSymbolAddress((void**)&p_part, g_part);

    cudaFuncSetAttribute(gemm_tc3, cudaFuncAttributeMaxDynamicSharedMemorySize, 71680);
    cudaFuncSetAttribute(k_edge2, cudaFuncAttributeMaxDynamicSharedMemorySize, 191488);

    // lf GEMMs with split-K (6 chunks of 128) + deterministic reduce
    gemm_sk<<<dim3(4, 4, 6), 256>>>(lfea, sw1, p_part, 256, 768, 256);
    k_red<<<256, 256>>>(p_part, p_lf_s1, 256 * 256);
    gemm_sk<<<dim3(8, 4, 6), 256>>>(lfea, mw1, p_part, 256, 768, 512);
    k_red<<<512, 256>>>(p_part, p_lf_m1, 256 * 512);
    // h1 = relu(lf_s1[p] + pos-part + sb1)
    k_s1<<<256, 256>>>(pos, sw1, sb1);
    // h2 = relu(h1 @ sw2 + sb2) — 3xTF32 (fp32-grade, feeds KNN)
    gemm_tc3<<<dim3(1, 128), 256, 71680>>>(p_h1, sw2, sb2, p_h2, NP, 256);
    // n_pos
    k_s3<<<(NP * 32) / 256, 256>>>(pos, sw3, sb3);
    // knn
    k_knn<<<256, 128>>>(pos);
    // edge MLP: U/V precompute, then mma phase-B with max over neighbors
    k_uv<<<(M2 * 64) / 256, 256>>>(pos, cw1, cb1);
    k_edge2<<<512, 256, 191488>>>(cw2, cb2);
    // g1 = relu(pos_fea @ mw1[768:] + lf_m1[p] + mb1) — tf32
    gemm_tc<<<dim3(4, 256), 256>>>(p_posfea, mw1 + 768 * 512, mb1, p_lf_m1, p_g1, M2, 128, 512, 2);
    // g2 = relu(g1 @ mw2 + mb2) — tf32
    gemm_tc<<<dim3(2, 256), 256>>>(p_g1, mw2, mb2, nullptr, p_g2, M2, 512, 256, 1);
    // rot
    k_rot<<<(M2 * 32) / 256, 256>>>(mw3, mb3);
    // outputs
    k_out<<<(16 * M2 + M2 + 255) / 256, 256>>>(pos, out);
}

// round 5
// speedup vs baseline: 5.1805x; 1.0172x over previous
#include <cuda_runtime.h>
#include <math.h>

#define PB  256
#define PTc 64
#define NP  16384      // N = P*PT
#define M2  32768      // 2N
#define R2C 0.09f

// ---------------- scratch (static device globals; no allocations) ------------
__device__ float g_lf_s1[PB * 256];
__device__ float g_lf_m1[PB * 512];
__device__ float g_npos[NP * 3];
__device__ int   g_nbr[M2 * 9];
__device__ float g_U[(size_t)M2 * 64];
__device__ float g_V[(size_t)M2 * 64];
__device__ float g_posfea[(size_t)M2 * 128];
__device__ float g_g1[(size_t)M2 * 512];
__device__ float g_g2[(size_t)M2 * 256];
__device__ float g_rot[M2 * 9];
__device__ float g_part[6 * 256 * 512];
__device__ float g_wt1[128 * 512];    // tf32-rounded mw1[768:]
__device__ float g_wt2[512 * 256];    // tf32-rounded mw2
__device__ float g_wt3[64 * 128];     // tf32-rounded cw2

__device__ __forceinline__ unsigned f2tf(float f) {
    unsigned r; asm("cvt.rna.tf32.f32 %0, %1;" : "=r"(r) : "f"(f)); return r;
}
#define MMA_TF32(cc, aa, bb) \
    asm volatile("mma.sync.aligned.m16n8k8.row.col.f32.tf32.tf32.f32 " \
        "{%0,%1,%2,%3},{%4,%5,%6,%7},{%8,%9},{%0,%1,%2,%3};" \
        : "+f"(cc[0]), "+f"(cc[1]), "+f"(cc[2]), "+f"(cc[3]) \
        : "r"(aa[0]), "r"(aa[1]), "r"(aa[2]), "r"(aa[3]), "r"(bb[0]), "r"(bb[1]))

__device__ __forceinline__ void cp16(void* dst, const void* src) {
    unsigned d = (unsigned)__cvta_generic_to_shared(dst);
    asm volatile("cp.async.cg.shared.global [%0], [%1], 16;" :: "r"(d), "l"(src));
}

// ---------------- tf32 round of weights into scratch -------------------------
__global__ void k_cvt(const float* __restrict__ src, float* __restrict__ dst, int n)
{
    int i = blockIdx.x * 256 + threadIdx.x;
    if (i < n) dst[i] = __uint_as_float(f2tf(src[i]));
}

// ---------------- split-K fp32 GEMM + reduce (small lf GEMMs) ----------------
__global__ void gemm_sk(const float* __restrict__ A, const float* __restrict__ B,
                        float* __restrict__ Cp, int M, int K, int Nn)
{
    __shared__ float As[64][17];
    __shared__ float Bs[16][65];
    const int bm = blockIdx.y * 64, bn = blockIdx.x * 64;
    const int t = threadIdx.x;
    const int ty = t >> 4, tx = t & 15;
    float acc[4][4] = {};
    int kbeg = blockIdx.z * 128, kend = kbeg + 128;
    for (int k0 = kbeg; k0 < kend; k0 += 16) {
        #pragma unroll
        for (int i = 0; i < 4; i++) {
            int e = t + i * 256; int r = e >> 4, c = e & 15;
            As[r][c] = A[(size_t)(bm + r) * K + k0 + c];
        }
        #pragma unroll
        for (int i = 0; i < 4; i++) {
            int e = t + i * 256; int r = e >> 6, c = e & 63;
            Bs[r][c] = B[(size_t)(k0 + r) * Nn + bn + c];
        }
        __syncthreads();
        #pragma unroll
        for (int kk = 0; kk < 16; kk++) {
            float a[4], b[4];
            #pragma unroll
            for (int i = 0; i < 4; i++) a[i] = As[ty * 4 + i][kk];
            #pragma unroll
            for (int j = 0; j < 4; j++) b[j] = Bs[kk][tx * 4 + j];
            #pragma unroll
            for (int i = 0; i < 4; i++)
                #pragma unroll
                for (int j = 0; j < 4; j++)
                    acc[i][j] += a[i] * b[j];
        }
        __syncthreads();
    }
    float* Cz = Cp + (size_t)blockIdx.z * M * Nn;
    #pragma unroll
    for (int i = 0; i < 4; i++)
        #pragma unroll
        for (int j = 0; j < 4; j++)
            Cz[(size_t)(bm + ty * 4 + i) * Nn + bn + tx * 4 + j] = acc[i][j];
}

__global__ void k_red(const float* __restrict__ Cp, float* __restrict__ C, int total)
{
    int e = blockIdx.x * 256 + threadIdx.x;
    if (e < total) {
        float s = 0.f;
        #pragma unroll
        for (int z = 0; z < 6; z++) s += Cp[(size_t)z * total + e];
        C[e] = s;
    }
}

// ------- pipelined tf32 GEMM (pre-rounded inputs, cp.async, 2-stage) ---------
// mode 1: relu(+bias)  store fp32;  mode 2: relu(+bias + lfE[batch]) store tf32-rounded
__global__ void __launch_bounds__(256)
gemm_tcp(const float* __restrict__ A, const float* __restrict__ B,
         const float* __restrict__ bias, const float* __restrict__ lfE,
         float* __restrict__ C, int M, int K, int Nn, int mode)
{
    extern __shared__ float psm[];
    float* Asm[2] = { psm, psm + 128 * 36 };
    float* Bsm[2] = { psm + 2 * 128 * 36, psm + 2 * 128 * 36 + 32 * 136 };
    const int t = threadIdx.x;
    const int warp = t >> 5, lane = t & 31;
    const int g = lane >> 2, q = lane & 3;
    const int wm = warp >> 1, wn = warp & 1;
    const int bm = blockIdx.y * 128, bn = blockIdx.x * 128;
    const int T = K >> 5;

    float c[2][8][4];
    #pragma unroll
    for (int i = 0; i < 2; i++)
        #pragma unroll
        for (int j = 0; j < 8; j++)
            #pragma unroll
            for (int e = 0; e < 4; e++) c[i][j][e] = 0.f;

    // prologue: stage 0
    {
        const float* Ab = A + (size_t)bm * K;
        const float* Bb = B + bn;
        #pragma unroll
        for (int i = 0; i < 4; i++) {
            int e = t + i * 256; int r = e >> 3, c4 = e & 7;
            cp16(&Asm[0][r * 36 + c4 * 4], Ab + (size_t)r * K + c4 * 4);
        }
        #pragma unroll
        for (int i = 0; i < 4; i++) {
            int e = t + i * 256; int r = e >> 5, c4 = e & 31;
            cp16(&Bsm[0][r * 136 + c4 * 4], Bb + (size_t)r * Nn + c4 * 4);
        }
        asm volatile("cp.async.commit_group;");
    }

    for (int tt = 0; tt < T; tt++) {
        if (tt + 1 < T) {
            int s = (tt + 1) & 1;
            const float* Ab = A + (size_t)bm * K + (tt + 1) * 32;
            const float* Bb = B + (size_t)(tt + 1) * 32 * Nn + bn;
            #pragma unroll
            for (int i = 0; i < 4; i++) {
                int e = t + i * 256; int r = e >> 3, c4 = e & 7;
                cp16(&Asm[s][r * 36 + c4 * 4], Ab + (size_t)r * K + c4 * 4);
            }
            #pragma unroll
            for (int i = 0; i < 4; i++) {
                int e = t + i * 256; int r = e >> 5, c4 = e & 31;
                cp16(&Bsm[s][r * 136 + c4 * 4], Bb + (size_t)r * Nn + c4 * 4);
            }
            asm volatile("cp.async.commit_group;");
            asm volatile("cp.async.wait_group 1;");
        } else {
            asm volatile("cp.async.wait_group 0;");
        }
        __syncthreads();
        const unsigned* As = (const unsigned*)Asm[tt & 1];
        const unsigned* Bs = (const unsigned*)Bsm[tt & 1];
        #pragma unroll
        for (int ks = 0; ks < 4; ks++) {
            int k8 = ks * 8;
            unsigned a[2][4], b[8][2];
            #pragma unroll
            for (int mt = 0; mt < 2; mt++) {
                int r = wm * 32 + mt * 16 + g;
                a[mt][0] = As[r * 36 + k8 + q];
                a[mt][1] = As[(r + 8) * 36 + k8 + q];
                a[mt][2] = As[r * 36 + k8 + q + 4];
                a[mt][3] = As[(r + 8) * 36 + k8 + q + 4];
            }
            #pragma unroll
            for (int nt = 0; nt < 8; nt++) {
                int cn = wn * 64 + nt * 8 + g;
                b[nt][0] = Bs[(k8 + q) * 136 + cn];
                b[nt][1] = Bs[(k8 + q + 4) * 136 + cn];
            }
            #pragma unroll
            for (int mt = 0; mt < 2; mt++)
                #pragma unroll
                for (int nt = 0; nt < 8; nt++)
                    MMA_TF32(c[mt][nt], a[mt], b[nt]);
        }
        __syncthreads();
    }

    #pragma unroll
    for (int mt = 0; mt < 2; mt++) {
        int row0 = bm + wm * 32 + mt * 16 + g;
        #pragma unroll
        for (int half = 0; half < 2; half++) {
            int row = row0 + half * 8;
            int rowp = 0;
            if (mode == 2) rowp = (row < NP) ? (row >> 6) : ((row - NP) >> 6);
            #pragma unroll
            for (int nt = 0; nt < 8; nt++) {
                int col = bn + wn * 64 + nt * 8 + q * 2;
                float v0 = c[mt][nt][half * 2 + 0] + bias[col];
                float v1 = c[mt][nt][half * 2 + 1] + bias[col + 1];
                if (mode == 2) {
                    v0 += lfE[(size_t)rowp * Nn + col];
                    v1 += lfE[(size_t)rowp * Nn + col + 1];
                }
                v0 = fmaxf(v0, 0.f); v1 = fmaxf(v1, 0.f);
                if (mode == 2) { v0 = __uint_as_float(f2tf(v0)); v1 = __uint_as_float(f2tf(v1)); }
                *(float2*)&C[(size_t)row * Nn + col] = make_float2(v0, v1);
            }
        }
    }
}

// ------- fused h-chain: h1 on-the-fly, 3xTF32 GEMM (K=256,N=128), s3 epilogue
__global__ void __launch_bounds__(256)
gemm_tc3(const float* __restrict__ pos, const float* __restrict__ sw1,
         const float* __restrict__ sb1, const float* __restrict__ sw2,
         const float* __restrict__ sb2, const float* __restrict__ sw3,
         const float* __restrict__ sb3)
{
    extern __shared__ unsigned sm3[];
    unsigned* Ah = sm3;                 // [128][36]
    unsigned* Al = Ah + 128 * 36;
    unsigned* Bh = Al + 128 * 36;       // [32][136]
    unsigned* Bl = Bh + 32 * 136;
    const int t = threadIdx.x;
    const int warp = t >> 5, lane = t & 31;
    const int g = lane >> 2, q = lane & 3;
    const int wm = warp >> 1, wn = warp & 1;
    const int bm = blockIdx.y * 128;

    float c[2][8][4];
    #pragma unroll
    for (int i = 0; i < 2; i++)
        #pragma unroll
        for (int j = 0; j < 8; j++)
            #pragma unroll
            for (int e = 0; e < 4; e++) c[i][j][e] = 0.f;

    for (int k0 = 0; k0 < 256; k0 += 32) {
        #pragma unroll
        for (int i = 0; i < 4; i++) {
            int e = t + i * 256; int r = e >> 3, c4 = e & 7;
            int row = bm + r, cc = k0 + c4 * 4;
            int p = row >> 6;
            float4 lf = *(const float4*)(g_lf_s1 + p * 256 + cc);
            float4 b1 = *(const float4*)(sb1 + cc);
            float4 w0 = *(const float4*)(sw1 + 768 * 256 + cc);
            float4 w1 = *(const float4*)(sw1 + 769 * 256 + cc);
            float4 w2 = *(const float4*)(sw1 + 770 * 256 + cc);
            float px = pos[row * 3], py = pos[row * 3 + 1], pz = pos[row * 3 + 2];
            float h0 = fmaxf(lf.x + b1.x + px * w0.x + py * w1.x + pz * w2.x, 0.f);
            float h1v = fmaxf(lf.y + b1.y + px * w0.y + py * w1.y + pz * w2.y, 0.f);
            float h2v = fmaxf(lf.z + b1.z + px * w0.z + py * w1.z + pz * w2.z, 0.f);
            float h3 = fmaxf(lf.w + b1.w + px * w0.w + py * w1.w + pz * w2.w, 0.f);
            unsigned u0 = f2tf(h0), u1 = f2tf(h1v), u2 = f2tf(h2v), u3 = f2tf(h3);
            *(uint4*)&Ah[r * 36 + c4 * 4] = make_uint4(u0, u1, u2, u3);
            *(uint4*)&Al[r * 36 + c4 * 4] = make_uint4(
                f2tf(h0 - __uint_as_float(u0)), f2tf(h1v - __uint_as_float(u1)),
                f2tf(h2v - __uint_as_float(u2)), f2tf(h3 - __uint_as_float(u3)));
        }
        #pragma unroll
        for (int i = 0; i < 4; i++) {
            int e = t + i * 256; int r = e >> 5, c4 = e & 31;
            float4 v = *(const float4*)(sw2 + (size_t)(k0 + r) * 128 + c4 * 4);
            unsigned h0 = f2tf(v.x), h1 = f2tf(v.y), h2v = f2tf(v.z), h3 = f2tf(v.w);
            *(uint4*)&Bh[r * 136 + c4 * 4] = make_uint4(h0, h1, h2v, h3);
            *(uint4*)&Bl[r * 136 + c4 * 4] = make_uint4(
                f2tf(v.x - __uint_as_float(h0)), f2tf(v.y - __uint_as_float(h1)),
                f2tf(v.z - __uint_as_float(h2v)), f2tf(v.w - __uint_as_float(h3)));
        }
        __syncthreads();
        #pragma unroll
        for (int ks = 0; ks < 4; ks++) {
            int k8 = ks * 8;
            unsigned ah[2][4], al[2][4];
            #pragma unroll
            for (int mt = 0; mt < 2; mt++) {
                int r = wm * 32 + mt * 16 + g;
                ah[mt][0] = Ah[r * 36 + k8 + q];       al[mt][0] = Al[r * 36 + k8 + q];
                ah[mt][1] = Ah[(r + 8) * 36 + k8 + q]; al[mt][1] = Al[(r + 8) * 36 + k8 + q];
                ah[mt][2] = Ah[r * 36 + k8 + q + 4];   al[mt][2] = Al[r * 36 + k8 + q + 4];
                ah[mt][3] = Ah[(r + 8) * 36 + k8 + q + 4]; al[mt][3] = Al[(r + 8) * 36 + k8 + q + 4];
            }
            #pragma unroll
            for (int nt = 0; nt < 8; nt++) {
                int cn = wn * 64 + nt * 8 + g;
                unsigned bh[2], bl[2];
                bh[0] = Bh[(k8 + q) * 136 + cn];     bh[1] = Bh[(k8 + q + 4) * 136 + cn];
                bl[0] = Bl[(k8 + q) * 136 + cn];     bl[1] = Bl[(k8 + q + 4) * 136 + cn];
                #pragma unroll
                for (int mt = 0; mt < 2; mt++) {
                    MMA_TF32(c[mt][nt], al[mt], bh);
                    MMA_TF32(c[mt][nt], ah[mt], bl);
                    MMA_TF32(c[mt][nt], ah[mt], bh);
                }
            }
        }
        __syncthreads();
    }

    // epilogue: h2 = relu(c + sb2); partial dot with sw3; reduce 8 slots/row
    float* sred = (float*)sm3;   // 128 rows * 8 slots * 3 = 12KB (aliases Ah)
    #pragma unroll
    for (int mt = 0; mt < 2; mt++) {
        #pragma unroll
        for (int half = 0; half < 2; half++) {
            int row_l = wm * 32 + mt * 16 + half * 8 + g;
            float p0 = 0.f, p1 = 0.f, p2 = 0.f;
            #pragma unroll
            for (int nt = 0; nt < 8; nt++) {
                int col = wn * 64 + nt * 8 + q * 2;
                float v0 = fmaxf(c[mt][nt][half * 2 + 0] + sb2[col], 0.f);
                float v1 = fmaxf(c[mt][nt][half * 2 + 1] + sb2[col + 1], 0.f);
                p0 += v0 * sw3[col * 3]     + v1 * sw3[(col + 1) * 3];
                p1 += v0 * sw3[col * 3 + 1] + v1 * sw3[(col + 1) * 3 + 1];
                p2 += v0 * sw3[col * 3 + 2] + v1 * sw3[(col + 1) * 3 + 2];
            }
            int slot = wn * 4 + q;
            sred[(row_l * 8 + slot) * 3 + 0] = p0;
            sred[(row_l * 8 + slot) * 3 + 1] = p1;
            sred[(row_l * 8 + slot) * 3 + 2] = p2;
        }
    }
    __syncthreads();
    if (t < 128) {
        float a0 = 0.f, a1 = 0.f, a2 = 0.f;
        #pragma unroll
        for (int s = 0; s < 8; s++) {
            a0 += sred[(t * 8 + s) * 3 + 0];
            a1 += sred[(t * 8 + s) * 3 + 1];
            a2 += sred[(t * 8 + s) * 3 + 2];
        }
        int row = bm + t;
        g_npos[row * 3 + 0] = tanhf(fmaxf(a0 + sb3[0], 0.f)) + pos[row * 3 + 0];
        g_npos[row * 3 + 1] = tanhf(fmaxf(a1 + sb3[1], 0.f)) + pos[row * 3 + 1];
        g_npos[row * 3 + 2] = tanhf(fmaxf(a2 + sb3[2], 0.f)) + pos[row * 3 + 2];
    }
}

// ------------- KNN: per batch, 128 pts, top-9 (d2 <= R2), pad with bi[0] -----
__global__ void k_knn(const float* __restrict__ pos)
{
    __shared__ float sx[128], sy[128], sz[128];
    int p = blockIdx.x, i = threadIdx.x;
    int g = p * PTc + (i & 63);
    float x, y, z;
    if (i < 64) { x = pos[g * 3]; y = pos[g * 3 + 1]; z = pos[g * 3 + 2]; }
    else        { x = g_npos[g * 3]; y = g_npos[g * 3 + 1]; z = g_npos[g * 3 + 2]; }
    sx[i] = x; sy[i] = y; sz[i] = z;
    __syncthreads();
    float bd[9]; int bi[9];
    #pragma unroll
    for (int qq = 0; qq < 9; qq++) { bd[qq] = 1e30f; bi[qq] = 0; }
    int cnt = 0;
    for (int j = 0; j < 128; j++) {
        float dx = x - sx[j], dy = y - sy[j], dz = z - sz[j];
        float d2 = dx * dx + dy * dy + dz * dz;
        if (d2 <= R2C && d2 < bd[8]) {
            int ins = 0;
            #pragma unroll
            for (int qq = 0; qq < 9; qq++) ins += (bd[qq] <= d2) ? 1 : 0;
            #pragma unroll
            for (int qq = 8; qq > 0; qq--) if (qq > ins) { bd[qq] = bd[qq - 1]; bi[qq] = bi[qq - 1]; }
            #pragma unroll
            for (int qq = 0; qq < 9; qq++) if (qq == ins) { bd[qq] = d2; bi[qq] = j; }
            if (cnt < 9) cnt++;
        }
    }
    #pragma unroll
    for (int qq = 1; qq < 9; qq++) if (qq >= cnt) bi[qq] = bi[0];
    int pt = p * 128 + i;
    #pragma unroll
    for (int qq = 0; qq < 9; qq++) g_nbr[pt * 9 + qq] = bi[qq];
}

// ------------- U/V precompute: U = cb1 + n.(wn+wr), V = c.wr -----------------
__global__ void k_uv(const float* __restrict__ pos, const float* __restrict__ cw1,
                     const float* __restrict__ cb1)
{
    int tid = blockIdx.x * 256 + threadIdx.x;   // M2*64
    int pt = tid >> 6, k = tid & 63;
    int p = pt >> 7, i = pt & 127;
    int gi = p * PTc + (i & 63);
    float x, y, z;
    if (i < 64) { x = pos[gi * 3]; y = pos[gi * 3 + 1]; z = pos[gi * 3 + 2]; }
    else        { x = g_npos[gi * 3]; y = g_npos[gi * 3 + 1]; z = g_npos[gi * 3 + 2]; }
    float wn0 = cw1[k],       wn1 = cw1[64 + k],  wn2 = cw1[128 + k];
    float wr0 = cw1[192 + k], wr1 = cw1[256 + k], wr2 = cw1[320 + k];
    g_U[tid] = cb1[k] + x * (wn0 + wr0) + y * (wn1 + wr1) + z * (wn2 + wr2);
    g_V[tid] = x * wr0 + y * wr1 + z * wr2;
}

// ------------- edge MLP phase-B: per-qn A slices, V in registers -------------
// block = 64 points; As [64][68], Bs [64][136]; max over 9 qn in registers
__global__ void __launch_bounds__(256)
k_edge2(const float* __restrict__ cb2)
{
    extern __shared__ unsigned esm[];
    unsigned* Bs = esm;               // [64][136]
    unsigned* As = esm + 64 * 136;    // [64][68]
    const int t = threadIdx.x;
    const int warp = t >> 5, lane = t & 31;
    const int g = lane >> 2, q = lane & 3;
    const int wm = warp >> 1, wn = warp & 1;
    const int p = blockIdx.x >> 1, half = blockIdx.x & 1;
    const int ptbase = p * 128 + half * 64;

    for (int e = t; e < 64 * 128; e += 256)
        Bs[(e >> 7) * 136 + (e & 127)] = __float_as_uint(g_wt3[e]);

    // per-thread V slice: row r4 = t>>2, cols q4*16..q4*16+15
    const int r4 = t >> 2, q4 = t & 3;
    float vv[16];
    {
        const float4* Vr = (const float4*)(g_V + (size_t)(ptbase + r4) * 64 + q4 * 16);
        #pragma unroll
        for (int j4 = 0; j4 < 4; j4++) {
            float4 v = Vr[j4];
            vv[j4 * 4 + 0] = v.x; vv[j4 * 4 + 1] = v.y;
            vv[j4 * 4 + 2] = v.z; vv[j4 * 4 + 3] = v.w;
        }
    }
    __syncthreads();

    float mx[8][4];
    #pragma unroll 1
    for (int qn = 0; qn < 9; qn++) {
        // fill As for this qn
        {
            int nb = g_nbr[(ptbase + r4) * 9 + qn];
            const float4* Ur = (const float4*)(g_U + (size_t)(p * 128 + nb) * 64 + q4 * 16);
            #pragma unroll
            for (int j4 = 0; j4 < 4; j4++) {
                float4 u = Ur[j4];
                int k = q4 * 16 + j4 * 4;
                uint4 o = make_uint4(
                    f2tf(fmaxf(u.x - vv[j4 * 4 + 0], 0.f)),
                    f2tf(fmaxf(u.y - vv[j4 * 4 + 1], 0.f)),
                    f2tf(fmaxf(u.z - vv[j4 * 4 + 2], 0.f)),
                    f2tf(fmaxf(u.w - vv[j4 * 4 + 3], 0.f)));
                *(uint4*)&As[r4 * 68 + k] = o;
            }
        }
        __syncthreads();
        float acc[8][4];
        #pragma unroll
        for (int nt = 0; nt < 8; nt++)
            #pragma unroll
            for (int e = 0; e < 4; e++) acc[nt][e] = 0.f;
        #pragma unroll
        for (int ks = 0; ks < 8; ks++) {
            int k8 = ks * 8;
            unsigned a[4];
            int rr = wm * 16 + g;
            a[0] = As[rr * 68 + k8 + q];
            a[1] = As[(rr + 8) * 68 + k8 + q];
            a[2] = As[rr * 68 + k8 + q + 4];
            a[3] = As[(rr + 8) * 68 + k8 + q + 4];
            #pragma unroll
            for (int nt = 0; nt < 8; nt++) {
                int cn = wn * 64 + nt * 8 + g;
                unsigned b[2];
                b[0] = Bs[(k8 + q) * 136 + cn];
                b[1] = Bs[(k8 + q + 4) * 136 + cn];
                MMA_TF32(acc[nt], a, b);
            }
        }
        if (qn == 0) {
            #pragma unroll
            for (int nt = 0; nt < 8; nt++)
                #pragma unroll
                for (int e = 0; e < 4; e++) mx[nt][e] = acc[nt][e];
        } else {
            #pragma unroll
            for (int nt = 0; nt < 8; nt++)
                #pragma unroll
                for (int e = 0; e < 4; e++) mx[nt][e] = fmaxf(mx[nt][e], acc[nt][e]);
        }
        __syncthreads();
    }

    #pragma unroll
    for (int hh = 0; hh < 2; hh++) {
        int pl = wm * 16 + g + hh * 8;
        size_t row = (half == 0) ? (size_t)(p * 64 + pl)
                                 : (size_t)(NP + p * 64 + pl);
        #pragma unroll
        for (int nt = 0; nt < 8; nt++) {
            int col = wn * 64 + nt * 8 + q * 2;
            float v0 = fmaxf(mx[nt][hh * 2 + 0] + cb2[col], 0.f);
            float v1 = fmaxf(mx[nt][hh * 2 + 1] + cb2[col + 1], 0.f);
            // store tf32-rounded for the cp.async g1 GEMM
            *(float2*)&g_posfea[row * 128 + col] =
                make_float2(__uint_as_float(f2tf(v0)), __uint_as_float(f2tf(v1)));
        }
    }
}

// ------------- rot = relu(g2 @ mw3 + mb3), warp per row ----------------------
__global__ void k_rot(const float* __restrict__ mw3, const float* __restrict__ mb3)
{
    int gt = blockIdx.x * blockDim.x + threadIdx.x;
    int w = gt >> 5, lane = gt & 31;
    if (w >= M2) return;
    float a[9] = {};
    #pragma unroll
    for (int s = 0; s < 8; s++) {
        int k = lane + 32 * s;
        float gv = g_g2[(size_t)w * 256 + k];
        #pragma unroll
        for (int i = 0; i < 9; i++) a[i] += gv * mw3[k * 9 + i];
    }
    #pragma unroll
    for (int off = 16; off; off >>= 1)
        #pragma unroll
        for (int i = 0; i < 9; i++) a[i] += __shfl_down_sync(0xffffffffu, a[i], off);
    if (lane == 0) {
        #pragma unroll
        for (int i = 0; i < 9; i++) g_rot[w * 9 + i] = fmaxf(a[i] + mb3[i], 0.f);
    }
}

// ------------- outputs: plane_init then rot_constrain ------------------------
__global__ void k_out(const float* __restrict__ pos, float* __restrict__ out)
{
    int tid = blockIdx.x * blockDim.x + threadIdx.x;
    if (tid < 16 * M2) {
        int n = tid >> 4, t4 = tid & 15;
        const float XV[4] = {-0.2f, -0.066666666666666666f, 0.066666666666666666f, 0.2f};
        float nx = XV[t4 & 3], ny = XV[t4 >> 2];
        int m = tid & (M2 - 1);
        const float* rr = g_rot + (size_t)n * 9;
        float cx, cy, cz;
        if (m < NP) { cx = pos[m * 3]; cy = pos[m * 3 + 1]; cz = pos[m * 3 + 2]; }
        else { int mm = m - NP; cx = g_npos[mm * 3]; cy = g_npos[mm * 3 + 1]; cz = g_npos[mm * 3 + 2]; }
        out[(size_t)tid * 3 + 0] = rr[0] * nx + rr[1] * ny + cx;
        out[(size_t)tid * 3 + 1] = rr[3] * nx + rr[4] * ny + cy;
        out[(size_t)tid * 3 + 2] = rr[6] * nx + rr[7] * ny + cz;
    } else if (tid < 16 * M2 + M2) {
        int r = tid - 16 * M2;
        float rr[9];
        #pragma unroll
        for (int i = 0; i < 9; i++) rr[i] = g_rot[r * 9 + i];
        float* o = out + (size_t)16 * M2 * 3 + (size_t)r * 9;
        #pragma unroll
        for (int i = 0; i < 3; i++)
            #pragma unroll
            for (int j = 0; j < 3; j++)
                o[i * 3 + j] = rr[0 + i] * rr[0 + j] + rr[3 + i] * rr[3 + j] + rr[6 + i] * rr[6 + j];
    }
}

// ---------------- host launcher ----------------------------------------------
extern "C" void kernel_launch(void* const* d_in, const int* in_sizes, int n_in,
                              void* d_out, int out_size)
{
    const float* pos = (const float*)d_in[1];
    const float* lfea = (const float*)d_in[4];
    const float* sw1 = (const float*)d_in[5];
    const float* sb1 = (const float*)d_in[6];
    const float* sw2 = (const float*)d_in[7];
    const float* sb2 = (const float*)d_in[8];
    const float* sw3 = (const float*)d_in[9];
    const float* sb3 = (const float*)d_in[10];
    const float* cw1 = (const float*)d_in[11];
    const float* cb1 = (const float*)d_in[12];
    const float* cw2 = (const float*)d_in[13];
    const float* cb2 = (const float*)d_in[14];
    const float* mw1 = (const float*)d_in[15];
    const float* mb1 = (const float*)d_in[16];
    const float* mw2 = (const float*)d_in[17];
    const float* mb2 = (const float*)d_in[18];
    const float* mw3 = (const float*)d_in[19];
    const float* mb3 = (const float*)d_in[20];
    float* out = (float*)d_out;

    float *p_lf_s1, *p_lf_m1, *p_posfea, *p_g1, *p_g2, *p_part, *p_wt1, *p_wt2, *p_wt3;
    cudaGetSymbolAddress((void**)&p_lf_s1, g_lf_s1);
    cudaGetSymbolAddress((void**)&p_lf_m1, g_lf_m1);
    cudaGetSymbolAddress((void**)&p_posfea, g_posfea);
    cudaGetSymbolAddress((void**)&p_g1, g_g1);
    cudaGetSymbolAddress((void**)&p_g2, g_g2);
    cudaGetSymbolAddress((void**)&p_part, g_part);
    cudaGetSymbolAddress((void**)&p_wt1, g_wt1);
    cudaGetSymbolAddress((void**)&p_wt2, g_wt2);
    cudaGetSymbolAddress((void**)&p_wt3, g_wt3);

    cudaFuncSetAttribute(gemm_tc3, cudaFuncAttributeMaxDynamicSharedMemorySize, 71680);
    cudaFuncSetAttribute(gemm_tcp, cudaFuncAttributeMaxDynamicSharedMemorySize, 71680);
    cudaFuncSetAttribute(k_edge2, cudaFuncAttributeMaxDynamicSharedMemorySize, 52224);

    // round weights to tf32 grid (once per launch; cheap)
    k_cvt<<<256, 256>>>(mw1 + 768 * 512, p_wt1, 128 * 512);
    k_cvt<<<512, 256>>>(mw2, p_wt2, 512 * 256);
    k_cvt<<<32, 256>>>(cw2, p_wt3, 64 * 128);

    // lf GEMMs with split-K (6 chunks of 128) + deterministic reduce
    gemm_sk<<<dim3(4, 4, 6), 256>>>(lfea, sw1, p_part, 256, 768, 256);
    k_red<<<256, 256>>>(p_part, p_lf_s1, 256 * 256);
    gemm_sk<<<dim3(8, 4, 6), 256>>>(lfea, mw1, p_part, 256, 768, 512);
    k_red<<<512, 256>>>(p_part, p_lf_m1, 256 * 512);
    // fused h1 -> h2 -> n_pos (3xTF32, fp32-grade; feeds KNN)
    gemm_tc3<<<dim3(1, 128), 256, 71680>>>(pos, sw1, sb1, sw2, sb2, sw3, sb3);
    // knn
    k_knn<<<256, 128>>>(pos);
    // edge MLP: U/V precompute, then per-qn mma with register max
    k_uv<<<(M2 * 64) / 256, 256>>>(pos, cw1, cb1);
    k_edge2<<<512, 256, 52224>>>(cb2);
    // g1 = relu(pos_fea @ mw1[768:] + lf_m1[p] + mb1) — pipelined tf32
    gemm_tcp<<<dim3(4, 256), 256, 71680>>>(p_posfea, p_wt1, mb1, p_lf_m1, p_g1, M2, 128, 512, 2);
    // g2 = relu(g1 @ mw2 + mb2) — pipelined tf32
    gemm_tcp<<<dim3(2, 256), 256, 71680>>>(p_g1, p_wt2, mb2, nullptr, p_g2, M2, 512, 256, 1);
    // rot
    k_rot<<<(M2 * 32) / 256, 256>>>(mw3, mb3);
    // outputs
    k_out<<<(16 * M2 + M2 + 255) / 256, 256>>>(pos, out);
}

// round 7
// speedup vs baseline: 5.7410x; 1.1082x over previous
#include <cuda_runtime.h>
#include <math.h>

#define PB  256
#define PTc 64
#define NP  16384      // N = P*PT
#define M2  32768      // 2N
#define R2C 0.09f

// ---------------- scratch (static device globals; no allocations) ------------
__device__ float g_lf_s1[PB * 256];
__device__ float g_lf_m1[PB * 512];
__device__ float g_npos[NP * 3];
__device__ int   g_nbr[M2 * 9];
__device__ float g_U[(size_t)M2 * 64];
__device__ float g_V[(size_t)M2 * 64];
__device__ float g_posfea[(size_t)M2 * 128];
__device__ float g_g1[(size_t)M2 * 512];
__device__ float g_part[6 * 256 * 768];
__device__ float g_wt1[128 * 512];    // tf32-rounded mw1[768:]
__device__ float g_wt2[512 * 256];    // tf32-rounded mw2
__device__ float g_wt3[64 * 128];     // tf32-rounded cw2

__device__ __forceinline__ unsigned f2tf(float f) {
    unsigned r; asm("cvt.rna.tf32.f32 %0, %1;" : "=r"(r) : "f"(f)); return r;
}
#define MMA_TF32(cc, aa, bb) \
    asm volatile("mma.sync.aligned.m16n8k8.row.col.f32.tf32.tf32.f32 " \
        "{%0,%1,%2,%3},{%4,%5,%6,%7},{%8,%9},{%0,%1,%2,%3};" \
        : "+f"(cc[0]), "+f"(cc[1]), "+f"(cc[2]), "+f"(cc[3]) \
        : "r"(aa[0]), "r"(aa[1]), "r"(aa[2]), "r"(aa[3]), "r"(bb[0]), "r"(bb[1]))

__device__ __forceinline__ void cp16(void* dst, const void* src) {
    unsigned d = (unsigned)__cvta_generic_to_shared(dst);
    asm volatile("cp.async.cg.shared.global [%0], [%1], 16;" :: "r"(d), "l"(src));
}

// ---------------- one cvt kernel for all three weight arrays -----------------
__global__ void k_cvt_all(const float* __restrict__ w1, const float* __restrict__ w2,
                          const float* __restrict__ w3)
{
    int i = blockIdx.x * 256 + threadIdx.x;
    if (i < 65536) g_wt1[i] = __uint_as_float(f2tf(w1[i]));
    else if (i < 65536 + 131072) g_wt2[i - 65536] = __uint_as_float(f2tf(w2[i - 65536]));
    else if (i < 204800) g_wt3[i - 196608] = __uint_as_float(f2tf(w3[i - 196608]));
}

// ------- fused lf GEMM: A=lfea[256x768], virtual B = [sw1 | mw1] (N=768) -----
__global__ void gemm_sk2(const float* __restrict__ A, const float* __restrict__ sw1,
                         const float* __restrict__ mw1)
{
    __shared__ float As[64][17];
    __shared__ float Bs[16][65];
    const int bm = blockIdx.y * 64, bn = blockIdx.x * 64;
    const float* B; int Nn, coloff;
    if (bn < 256) { B = sw1; Nn = 256; coloff = bn; }
    else          { B = mw1; Nn = 512; coloff = bn - 256; }
    const int t = threadIdx.x;
    const int ty = t >> 4, tx = t & 15;
    float acc[4][4] = {};
    int kbeg = blockIdx.z * 128, kend = kbeg + 128;
    for (int k0 = kbeg; k0 < kend; k0 += 16) {
        #pragma unroll
        for (int i = 0; i < 4; i++) {
            int e = t + i * 256; int r = e >> 4, c = e & 15;
            As[r][c] = A[(size_t)(bm + r) * 768 + k0 + c];
        }
        #pragma unroll
        for (int i = 0; i < 4; i++) {
            int e = t + i * 256; int r = e >> 6, c = e & 63;
            Bs[r][c] = B[(size_t)(k0 + r) * Nn + coloff + c];
        }
        __syncthreads();
        #pragma unroll
        for (int kk = 0; kk < 16; kk++) {
            float a[4], b[4];
            #pragma unroll
            for (int i = 0; i < 4; i++) a[i] = As[ty * 4 + i][kk];
            #pragma unroll
            for (int j = 0; j < 4; j++) b[j] = Bs[kk][tx * 4 + j];
            #pragma unroll
            for (int i = 0; i < 4; i++)
                #pragma unroll
                for (int j = 0; j < 4; j++)
                    acc[i][j] += a[i] * b[j];
        }
        __syncthreads();
    }
    float* Cz = g_part + (size_t)blockIdx.z * 256 * 768;
    #pragma unroll
    for (int i = 0; i < 4; i++)
        #pragma unroll
        for (int j = 0; j < 4; j++)
            Cz[(size_t)(bm + ty * 4 + i) * 768 + bn + tx * 4 + j] = acc[i][j];
}

__global__ void k_red2()
{
    int e = blockIdx.x * 256 + threadIdx.x;   // < 256*768
    float s = 0.f;
    #pragma unroll
    for (int z = 0; z < 6; z++) s += g_part[(size_t)z * 196608 + e];
    int row = e / 768, col = e - row * 768;
    if (col < 256) g_lf_s1[row * 256 + col] = s;
    else           g_lf_m1[row * 512 + col - 256] = s;
}

// ------- pipelined tf32 GEMM (pre-rounded inputs, cp.async, 2-stage) ---------
// mode 2: relu(+bias + lfE[batch]) store tf32-rounded  (used for g1)
__global__ void __launch_bounds__(256)
gemm_tcp(const float* __restrict__ A, const float* __restrict__ B,
         const float* __restrict__ bias, const float* __restrict__ lfE,
         float* __restrict__ C, int M, int K, int Nn, int mode)
{
    extern __shared__ float psm[];
    float* Asm[2] = { psm, psm + 128 * 36 };
    float* Bsm[2] = { psm + 2 * 128 * 36, psm + 2 * 128 * 36 + 32 * 136 };
    const int t = threadIdx.x;
    const int warp = t >> 5, lane = t & 31;
    const int g = lane >> 2, q = lane & 3;
    const int wm = warp >> 1, wn = warp & 1;
    const int bm = blockIdx.y * 128, bn = blockIdx.x * 128;
    const int T = K >> 5;

    float c[2][8][4];
    #pragma unroll
    for (int i = 0; i < 2; i++)
        #pragma unroll
        for (int j = 0; j < 8; j++)
            #pragma unroll
            for (int e = 0; e < 4; e++) c[i][j][e] = 0.f;

    {
        const float* Ab = A + (size_t)bm * K;
        const float* Bb = B + bn;
        #pragma unroll
        for (int i = 0; i < 4; i++) {
            int e = t + i * 256; int r = e >> 3, c4 = e & 7;
            cp16(&Asm[0][r * 36 + c4 * 4], Ab + (size_t)r * K + c4 * 4);
        }
        #pragma unroll
        for (int i = 0; i < 4; i++) {
            int e = t + i * 256; int r = e >> 5, c4 = e & 31;
            cp16(&Bsm[0][r * 136 + c4 * 4], Bb + (size_t)r * Nn + c4 * 4);
        }
        asm volatile("cp.async.commit_group;");
    }

    for (int tt = 0; tt < T; tt++) {
        if (tt + 1 < T) {
            int s = (tt + 1) & 1;
            const float* Ab = A + (size_t)bm * K + (tt + 1) * 32;
            const float* Bb = B + (size_t)(tt + 1) * 32 * Nn + bn;
            #pragma unroll
            for (int i = 0; i < 4; i++) {
                int e = t + i * 256; int r = e >> 3, c4 = e & 7;
                cp16(&Asm[s][r * 36 + c4 * 4], Ab + (size_t)r * K + c4 * 4);
            }
            #pragma unroll
            for (int i = 0; i < 4; i++) {
                int e = t + i * 256; int r = e >> 5, c4 = e & 31;
                cp16(&Bsm[s][r * 136 + c4 * 4], Bb + (size_t)r * Nn + c4 * 4);
            }
            asm volatile("cp.async.commit_group;");
            asm volatile("cp.async.wait_group 1;");
        } else {
            asm volatile("cp.async.wait_group 0;");
        }
        __syncthreads();
        const unsigned* As = (const unsigned*)Asm[tt & 1];
        const unsigned* Bs = (const unsigned*)Bsm[tt & 1];
        #pragma unroll
        for (int ks = 0; ks < 4; ks++) {
            int k8 = ks * 8;
            unsigned a[2][4], b[8][2];
            #pragma unroll
            for (int mt = 0; mt < 2; mt++) {
                int r = wm * 32 + mt * 16 + g;
                a[mt][0] = As[r * 36 + k8 + q];
                a[mt][1] = As[(r + 8) * 36 + k8 + q];
                a[mt][2] = As[r * 36 + k8 + q + 4];
                a[mt][3] = As[(r + 8) * 36 + k8 + q + 4];
            }
            #pragma unroll
            for (int nt = 0; nt < 8; nt++) {
                int cn = wn * 64 + nt * 8 + g;
                b[nt][0] = Bs[(k8 + q) * 136 + cn];
                b[nt][1] = Bs[(k8 + q + 4) * 136 + cn];
            }
            #pragma unroll
            for (int mt = 0; mt < 2; mt++)
                #pragma unroll
                for (int nt = 0; nt < 8; nt++)
                    MMA_TF32(c[mt][nt], a[mt], b[nt]);
        }
        __syncthreads();
    }

    #pragma unroll
    for (int mt = 0; mt < 2; mt++) {
        int row0 = bm + wm * 32 + mt * 16 + g;
        #pragma unroll
        for (int half = 0; half < 2; half++) {
            int row = row0 + half * 8;
            int rowp = 0;
            if (mode == 2) rowp = (row < NP) ? (row >> 6) : ((row - NP) >> 6);
            #pragma unroll
            for (int nt = 0; nt < 8; nt++) {
                int col = bn + wn * 64 + nt * 8 + q * 2;
                float v0 = c[mt][nt][half * 2 + 0] + bias[col];
                float v1 = c[mt][nt][half * 2 + 1] + bias[col + 1];
                if (mode == 2) {
                    v0 += lfE[(size_t)rowp * Nn + col];
                    v1 += lfE[(size_t)rowp * Nn + col + 1];
                }
                v0 = fmaxf(v0, 0.f); v1 = fmaxf(v1, 0.f);
                if (mode == 2) { v0 = __uint_as_float(f2tf(v0)); v1 = __uint_as_float(f2tf(v1)); }
                *(float2*)&C[(size_t)row * Nn + col] = make_float2(v0, v1);
            }
        }
    }
}

// ------- mega: h1 on-the-fly -> 3xTF32 h2 GEMM -> n_pos -> KNN -> U/V --------
// block = 128 rows = 2 complete batches (p0, p0+1)
__global__ void __launch_bounds__(256)
tc3mega(const float* __restrict__ pos, const float* __restrict__ sw1,
        const float* __restrict__ sb1, const float* __restrict__ sw2,
        const float* __restrict__ sb2, const float* __restrict__ sw3,
        const float* __restrict__ sb3, const float* __restrict__ cw1,
        const float* __restrict__ cb1)
{
    extern __shared__ unsigned sm3[];
    unsigned* Ah = sm3;                 // [128][36]
    unsigned* Al = Ah + 128 * 36;
    unsigned* Bh = Al + 128 * 36;       // [32][136]
    unsigned* Bl = Bh + 32 * 136;
    const int t = threadIdx.x;
    const int warp = t >> 5, lane = t & 31;
    const int g = lane >> 2, q = lane & 3;
    const int wm = warp >> 1, wn = warp & 1;
    const int bm = blockIdx.y * 128;
    const int p0 = bm >> 6;

    float c[2][8][4];
    #pragma unroll
    for (int i = 0; i < 2; i++)
        #pragma unroll
        for (int j = 0; j < 8; j++)
            #pragma unroll
            for (int e = 0; e < 4; e++) c[i][j][e] = 0.f;

    for (int k0 = 0; k0 < 256; k0 += 32) {
        #pragma unroll
        for (int i = 0; i < 4; i++) {
            int e = t + i * 256; int r = e >> 3, c4 = e & 7;
            int row = bm + r, cc = k0 + c4 * 4;
            int p = row >> 6;
            float4 lf = *(const float4*)(g_lf_s1 + p * 256 + cc);
            float4 b1 = *(const float4*)(sb1 + cc);
            float4 w0 = *(const float4*)(sw1 + 768 * 256 + cc);
            float4 w1 = *(const float4*)(sw1 + 769 * 256 + cc);
            float4 w2 = *(const float4*)(sw1 + 770 * 256 + cc);
            float px = pos[row * 3], py = pos[row * 3 + 1], pz = pos[row * 3 + 2];
            float h0 = fmaxf(lf.x + b1.x + px * w0.x + py * w1.x + pz * w2.x, 0.f);
            float h1v = fmaxf(lf.y + b1.y + px * w0.y + py * w1.y + pz * w2.y, 0.f);
            float h2v = fmaxf(lf.z + b1.z + px * w0.z + py * w1.z + pz * w2.z, 0.f);
            float h3 = fmaxf(lf.w + b1.w + px * w0.w + py * w1.w + pz * w2.w, 0.f);
            unsigned u0 = f2tf(h0), u1 = f2tf(h1v), u2 = f2tf(h2v), u3 = f2tf(h3);
            *(uint4*)&Ah[r * 36 + c4 * 4] = make_uint4(u0, u1, u2, u3);
            *(uint4*)&Al[r * 36 + c4 * 4] = make_uint4(
                f2tf(h0 - __uint_as_float(u0)), f2tf(h1v - __uint_as_float(u1)),
                f2tf(h2v - __uint_as_float(u2)), f2tf(h3 - __uint_as_float(u3)));
        }
        #pragma unroll
        for (int i = 0; i < 4; i++) {
            int e = t + i * 256; int r = e >> 5, c4 = e & 31;
            float4 v = *(const float4*)(sw2 + (size_t)(k0 + r) * 128 + c4 * 4);
            unsigned h0 = f2tf(v.x), h1 = f2tf(v.y), h2v = f2tf(v.z), h3 = f2tf(v.w);
            *(uint4*)&Bh[r * 136 + c4 * 4] = make_uint4(h0, h1, h2v, h3);
            *(uint4*)&Bl[r * 136 + c4 * 4] = make_uint4(
                f2tf(v.x - __uint_as_float(h0)), f2tf(v.y - __uint_as_float(h1)),
                f2tf(v.z - __uint_as_float(h2v)), f2tf(v.w - __uint_as_float(h3)));
        }
        __syncthreads();
        #pragma unroll
        for (int ks = 0; ks < 4; ks++) {
            int k8 = ks * 8;
            unsigned ah[2][4], al[2][4];
            #pragma unroll
            for (int mt = 0; mt < 2; mt++) {
                int r = wm * 32 + mt * 16 + g;
                ah[mt][0] = Ah[r * 36 + k8 + q];       al[mt][0] = Al[r * 36 + k8 + q];
                ah[mt][1] = Ah[(r + 8) * 36 + k8 + q]; al[mt][1] = Al[(r + 8) * 36 + k8 + q];
                ah[mt][2] = Ah[r * 36 + k8 + q + 4];   al[mt][2] = Al[r * 36 + k8 + q + 4];
                ah[mt][3] = Ah[(r + 8) * 36 + k8 + q + 4]; al[mt][3] = Al[(r + 8) * 36 + k8 + q + 4];
            }
            #pragma unroll
            for (int nt = 0; nt < 8; nt++) {
                int cn = wn * 64 + nt * 8 + g;
                unsigned bh[2], bl[2];
                bh[0] = Bh[(k8 + q) * 136 + cn];     bh[1] = Bh[(k8 + q + 4) * 136 + cn];
                bl[0] = Bl[(k8 + q) * 136 + cn];     bl[1] = Bl[(k8 + q + 4) * 136 + cn];
                #pragma unroll
                for (int mt = 0; mt < 2; mt++) {
                    MMA_TF32(c[mt][nt], al[mt], bh);
                    MMA_TF32(c[mt][nt], ah[mt], bl);
                    MMA_TF32(c[mt][nt], ah[mt], bh);
                }
            }
        }
        __syncthreads();
    }

    // ---- phase 2: n_pos via smem reduction ----
    float* fsm = (float*)sm3;
    float* sred = fsm;                 // 128*8*3
    float* snp  = fsm + 3072;          // 128*3
    float* sx   = fsm + 3456;          // 256
    float* sy   = fsm + 3712;
    float* sz   = fsm + 3968;
    float* scw1 = fsm + 4224;          // 384
    float* scb1 = fsm + 4608;          // 64
    #pragma unroll
    for (int mt = 0; mt < 2; mt++) {
        #pragma unroll
        for (int half = 0; half < 2; half++) {
            int row_l = wm * 32 + mt * 16 + half * 8 + g;
            float p0v = 0.f, p1 = 0.f, p2 = 0.f;
            #pragma unroll
            for (int nt = 0; nt < 8; nt++) {
                int col = wn * 64 + nt * 8 + q * 2;
                float v0 = fmaxf(c[mt][nt][half * 2 + 0] + sb2[col], 0.f);
                float v1 = fmaxf(c[mt][nt][half * 2 + 1] + sb2[col + 1], 0.f);
                p0v += v0 * sw3[col * 3]     + v1 * sw3[(col + 1) * 3];
                p1 += v0 * sw3[col * 3 + 1] + v1 * sw3[(col + 1) * 3 + 1];
                p2 += v0 * sw3[col * 3 + 2] + v1 * sw3[(col + 1) * 3 + 2];
            }
            int slot = wn * 4 + q;
            sred[(row_l * 8 + slot) * 3 + 0] = p0v;
            sred[(row_l * 8 + slot) * 3 + 1] = p1;
            sred[(row_l * 8 + slot) * 3 + 2] = p2;
        }
    }
    __syncthreads();
    if (t < 128) {
        float a0 = 0.f, a1 = 0.f, a2 = 0.f;
        #pragma unroll
        for (int s = 0; s < 8; s++) {
            a0 += sred[(t * 8 + s) * 3 + 0];
            a1 += sred[(t * 8 + s) * 3 + 1];
            a2 += sred[(t * 8 + s) * 3 + 2];
        }
        int row = bm + t;
        float n0 = tanhf(fmaxf(a0 + sb3[0], 0.f)) + pos[row * 3 + 0];
        float n1 = tanhf(fmaxf(a1 + sb3[1], 0.f)) + pos[row * 3 + 1];
        float n2 = tanhf(fmaxf(a2 + sb3[2], 0.f)) + pos[row * 3 + 2];
        g_npos[row * 3 + 0] = n0; g_npos[row * 3 + 1] = n1; g_npos[row * 3 + 2] = n2;
        snp[t * 3 + 0] = n0; snp[t * 3 + 1] = n1; snp[t * 3 + 2] = n2;
    }
    __syncthreads();

    // ---- phase 3: KNN for the 2 batches + U/V ----
    int b = t >> 7, i = t & 127;
    int rowl = b * 64 + (i & 63);
    float x, y, z;
    if (i < 64) {
        int gr = bm + rowl;
        x = pos[gr * 3]; y = pos[gr * 3 + 1]; z = pos[gr * 3 + 2];
    } else {
        x = snp[rowl * 3]; y = snp[rowl * 3 + 1]; z = snp[rowl * 3 + 2];
    }
    sx[b * 128 + i] = x; sy[b * 128 + i] = y; sz[b * 128 + i] = z;
    for (int e = t; e < 448; e += 256) {
        if (e < 384) scw1[e] = cw1[e]; else scb1[e - 384] = cb1[e - 384];
    }
    __syncthreads();

    float bd[9]; int bi[9];
    #pragma unroll
    for (int qq = 0; qq < 9; qq++) { bd[qq] = 1e30f; bi[qq] = 0; }
    int cnt = 0;
    const float* sxb = sx + b * 128; const float* syb = sy + b * 128; const float* szb = sz + b * 128;
    for (int j = 0; j < 128; j++) {
        float dx = x - sxb[j], dy = y - syb[j], dz = z - szb[j];
        float d2 = dx * dx + dy * dy + dz * dz;
        if (d2 <= R2C && d2 < bd[8]) {
            int ins = 0;
            #pragma unroll
            for (int qq = 0; qq < 9; qq++) ins += (bd[qq] <= d2) ? 1 : 0;
            #pragma unroll
            for (int qq = 8; qq > 0; qq--) if (qq > ins) { bd[qq] = bd[qq - 1]; bi[qq] = bi[qq - 1]; }
            #pragma unroll
            for (int qq = 0; qq < 9; qq++) if (qq == ins) { bd[qq] = d2; bi[qq] = j; }
            if (cnt < 9) cnt++;
        }
    }
    #pragma unroll
    for (int qq = 1; qq < 9; qq++) if (qq >= cnt) bi[qq] = bi[0];
    int ptg = (p0 + b) * 128 + i;
    #pragma unroll
    for (int qq = 0; qq < 9; qq++) g_nbr[ptg * 9 + qq] = bi[qq];

    // U/V cooperative (coalesced): e over 256 pts * 64 ch
    for (int e = t; e < 256 * 64; e += 256) {
        int ptl = e >> 6, k = e & 63;
        float xx = sx[ptl], yy = sy[ptl], zz = sz[ptl];
        float wn0 = scw1[k],       wn1 = scw1[64 + k],  wn2 = scw1[128 + k];
        float wr0 = scw1[192 + k], wr1 = scw1[256 + k], wr2 = scw1[320 + k];
        int ptgl = (p0 + (ptl >> 7)) * 128 + (ptl & 127);
        g_U[(size_t)ptgl * 64 + k] = scb1[k] + xx * (wn0 + wr0) + yy * (wn1 + wr1) + zz * (wn2 + wr2);
        g_V[(size_t)ptgl * 64 + k] = xx * wr0 + yy * wr1 + zz * wr2;
    }
}

// ------------- edge MLP phase-B: double-buffered per-qn A slices -------------
__global__ void __launch_bounds__(256)
k_edge2(const float* __restrict__ cb2)
{
    extern __shared__ unsigned esm[];
    unsigned* Bs = esm;                       // [64][136]
    unsigned* Abuf[2] = { esm + 64 * 136, esm + 64 * 136 + 64 * 68 };
    const int t = threadIdx.x;
    const int warp = t >> 5, lane = t & 31;
    const int g = lane >> 2, q = lane & 3;
    const int wm = warp >> 1, wn = warp & 1;
    const int p = blockIdx.x >> 1, half = blockIdx.x & 1;
    const int ptbase = p * 128 + half * 64;

    for (int e = t; e < 64 * 128; e += 256)
        Bs[(e >> 7) * 136 + (e & 127)] = __float_as_uint(g_wt3[e]);

    const int r4 = t >> 2, q4 = t & 3;
    float vv[16];
    {
        const float4* Vr = (const float4*)(g_V + (size_t)(ptbase + r4) * 64 + q4 * 16);
        #pragma unroll
        for (int j4 = 0; j4 < 4; j4++) {
            float4 v = Vr[j4];
            vv[j4 * 4 + 0] = v.x; vv[j4 * 4 + 1] = v.y;
            vv[j4 * 4 + 2] = v.z; vv[j4 * 4 + 3] = v.w;
        }
    }
    // fill qn=0
    {
        int nb = g_nbr[(ptbase + r4) * 9 + 0];
        const float4* Ur = (const float4*)(g_U + (size_t)(p * 128 + nb) * 64 + q4 * 16);
        #pragma unroll
        for (int j4 = 0; j4 < 4; j4++) {
            float4 u = Ur[j4];
            *(uint4*)&Abuf[0][r4 * 68 + q4 * 16 + j4 * 4] = make_uint4(
                f2tf(fmaxf(u.x - vv[j4 * 4 + 0], 0.f)),
                f2tf(fmaxf(u.y - vv[j4 * 4 + 1], 0.f)),
                f2tf(fmaxf(u.z - vv[j4 * 4 + 2], 0.f)),
                f2tf(fmaxf(u.w - vv[j4 * 4 + 3], 0.f)));
        }
    }

    float mx[8][4];
    #pragma unroll 1
    for (int qn = 0; qn < 9; qn++) {
        __syncthreads();
        if (qn < 8) {
            int nb = g_nbr[(ptbase + r4) * 9 + qn + 1];
            const float4* Ur = (const float4*)(g_U + (size_t)(p * 128 + nb) * 64 + q4 * 16);
            unsigned* dst = Abuf[(qn + 1) & 1];
            #pragma unroll
            for (int j4 = 0; j4 < 4; j4++) {
                float4 u = Ur[j4];
                *(uint4*)&dst[r4 * 68 + q4 * 16 + j4 * 4] = make_uint4(
                    f2tf(fmaxf(u.x - vv[j4 * 4 + 0], 0.f)),
                    f2tf(fmaxf(u.y - vv[j4 * 4 + 1], 0.f)),
                    f2tf(fmaxf(u.z - vv[j4 * 4 + 2], 0.f)),
                    f2tf(fmaxf(u.w - vv[j4 * 4 + 3], 0.f)));
            }
        }
        const unsigned* As = Abuf[qn & 1];
        float acc[8][4];
        #pragma unroll
        for (int nt = 0; nt < 8; nt++)
            #pragma unroll
            for (int e = 0; e < 4; e++) acc[nt][e] = 0.f;
        #pragma unroll
        for (int ks = 0; ks < 8; ks++) {
            int k8 = ks * 8;
            unsigned a[4];
            int rr = wm * 16 + g;
            a[0] = As[rr * 68 + k8 + q];
            a[1] = As[(rr + 8) * 68 + k8 + q];
            a[2] = As[rr * 68 + k8 + q + 4];
            a[3] = As[(rr + 8) * 68 + k8 + q + 4];
            #pragma unroll
            for (int nt = 0; nt < 8; nt++) {
                int cn = wn * 64 + nt * 8 + g;
                unsigned b[2];
                b[0] = Bs[(k8 + q) * 136 + cn];
                b[1] = Bs[(k8 + q + 4) * 136 + cn];
                MMA_TF32(acc[nt], a, b);
            }
        }
        if (qn == 0) {
            #pragma unroll
            for (int nt = 0; nt < 8; nt++)
                #pragma unroll
                for (int e = 0; e < 4; e++) mx[nt][e] = acc[nt][e];
        } else {
            #pragma unroll
            for (int nt = 0; nt < 8; nt++)
                #pragma unroll
                for (int e = 0; e < 4; e++) mx[nt][e] = fmaxf(mx[nt][e], acc[nt][e]);
        }
    }

    #pragma unroll
    for (int hh = 0; hh < 2; hh++) {
        int pl = wm * 16 + g + hh * 8;
        size_t row = (half == 0) ? (size_t)(p * 64 + pl)
                                 : (size_t)(NP + p * 64 + pl);
        #pragma unroll
        for (int nt = 0; nt < 8; nt++) {
            int col = wn * 64 + nt * 8 + q * 2;
            float v0 = fmaxf(mx[nt][hh * 2 + 0] + cb2[col], 0.f);
            float v1 = fmaxf(mx[nt][hh * 2 + 1] + cb2[col + 1], 0.f);
            *(float2*)&g_posfea[row * 128 + col] =
                make_float2(__uint_as_float(f2tf(v0)), __uint_as_float(f2tf(v1)));
        }
    }
}

// ------- g2 (128x256 tile, K=512) fused with rot + both outputs --------------
__global__ void __launch_bounds__(256)
gemm_g2rot(const float* __restrict__ A, const float* __restrict__ B,
           const float* __restrict__ mb2, const float* __restrict__ mw3,
           const float* __restrict__ mb3, const float* __restrict__ pos,
           float* __restrict__ out)
{
    extern __shared__ float psm[];
    float* Asm[2] = { psm, psm + 128 * 36 };
    float* Bsm[2] = { psm + 2 * 128 * 36, psm + 2 * 128 * 36 + 32 * 264 };
    const int t = threadIdx.x;
    const int warp = t >> 5, lane = t & 31;
    const int g = lane >> 2, q = lane & 3;
    const int wm = warp >> 1, wn = warp & 1;   // 4 row-warps x 2 col-warps
    const int bm = blockIdx.x * 128;

    float c[2][16][4];
    #pragma unroll
    for (int i = 0; i < 2; i++)
        #pragma unroll
        for (int j = 0; j < 16; j++)
            #pragma unroll
            for (int e = 0; e < 4; e++) c[i][j][e] = 0.f;

    {
        const float* Ab = A + (size_t)bm * 512;
        #pragma unroll
        for (int i = 0; i < 4; i++) {
            int e = t + i * 256; int r = e >> 3, c4 = e & 7;
            cp16(&Asm[0][r * 36 + c4 * 4], Ab + (size_t)r * 512 + c4 * 4);
        }
        #pragma unroll
        for (int i = 0; i < 8; i++) {
            int e = t + i * 256; int r = e >> 6, c4 = e & 63;
            cp16(&Bsm[0][r * 264 + c4 * 4], B + (size_t)r * 256 + c4 * 4);
        }
        asm volatile("cp.async.commit_group;");
    }

    for (int tt = 0; tt < 16; tt++) {
        if (tt + 1 < 16) {
            int s = (tt + 1) & 1;
            const float* Ab = A + (size_t)bm * 512 + (tt + 1) * 32;
            const float* Bb = B + (size_t)(tt + 1) * 32 * 256;
            #pragma unroll
            for (int i = 0; i < 4; i++) {
                int e = t + i * 256; int r = e >> 3, c4 = e & 7;
                cp16(&Asm[s][r * 36 + c4 * 4], Ab + (size_t)r * 512 + c4 * 4);
            }
            #pragma unroll
            for (int i = 0; i < 8; i++) {
                int e = t + i * 256; int r = e >> 6, c4 = e & 63;
                cp16(&Bsm[s][r * 264 + c4 * 4], Bb + (size_t)r * 256 + c4 * 4);
            }
            asm volatile("cp.async.commit_group;");
            asm volatile("cp.async.wait_group 1;");
        } else {
            asm volatile("cp.async.wait_group 0;");
        }
        __syncthreads();
        const unsigned* As = (const unsigned*)Asm[tt & 1];
        const unsigned* Bs = (const unsigned*)Bsm[tt & 1];
        #pragma unroll
        for (int ks = 0; ks < 4; ks++) {
            int k8 = ks * 8;
            unsigned a[2][4];
            #pragma unroll
            for (int mt = 0; mt < 2; mt++) {
                int r = wm * 32 + mt * 16 + g;
                a[mt][0] = As[r * 36 + k8 + q];
                a[mt][1] = As[(r + 8) * 36 + k8 + q];
                a[mt][2] = As[r * 36 + k8 + q + 4];
                a[mt][3] = As[(r + 8) * 36 + k8 + q + 4];
            }
            #pragma unroll
            for (int nt = 0; nt < 16; nt++) {
                int cn = wn * 128 + nt * 8 + g;
                unsigned b[2];
                b[0] = Bs[(k8 + q) * 264 + cn];
                b[1] = Bs[(k8 + q + 4) * 264 + cn];
                MMA_TF32(c[0][nt], a[0], b);
                MMA_TF32(c[1][nt], a[1], b);
            }
        }
        __syncthreads();
    }

    // epilogue: v = relu(c + mb2); partial dots with mw3; reduce 8 slots/row
    float* sred = psm;   // 128 rows * 8 slots * 9 = 9216 floats
    #pragma unroll
    for (int mt = 0; mt < 2; mt++) {
        #pragma unroll
        for (int half = 0; half < 2; half++) {
            int row_l = wm * 32 + mt * 16 + half * 8 + g;
            float p9[9];
            #pragma unroll
            for (int j = 0; j < 9; j++) p9[j] = 0.f;
            #pragma unroll
            for (int nt = 0; nt < 16; nt++) {
                int col = wn * 128 + nt * 8 + q * 2;
                float v0 = fmaxf(c[mt][nt][half * 2 + 0] + mb2[col], 0.f);
                float v1 = fmaxf(c[mt][nt][half * 2 + 1] + mb2[col + 1], 0.f);
                #pragma unroll
                for (int j = 0; j < 9; j++)
                    p9[j] += v0 * mw3[col * 9 + j] + v1 * mw3[(col + 1) * 9 + j];
            }
            int slot = wn * 4 + q;
            #pragma unroll
            for (int j = 0; j < 9; j++)
                sred[(row_l * 8 + slot) * 9 + j] = p9[j];
        }
    }
    __syncthreads();
    if (t < 128) {
        float r9[9];
        #pragma unroll
        for (int j = 0; j < 9; j++) {
            float s = 0.f;
            #pragma unroll
            for (int sl = 0; sl < 8; sl++) s += sred[(t * 8 + sl) * 9 + j];
            r9[j] = fmaxf(s + mb3[j], 0.f);
        }
        int n = bm + t;
        // rot_constrain
        float* oc = out + (size_t)16 * M2 * 3 + (size_t)n * 9;
        #pragma unroll
        for (int i = 0; i < 3; i++)
            #pragma unroll
            for (int j = 0; j < 3; j++)
                oc[i * 3 + j] = r9[0 + i] * r9[0 + j] + r9[3 + i] * r9[3 + j] + r9[6 + i] * r9[6 + j];
        // plane_init: 16 entries for this n
        const float XV[4] = {-0.2f, -0.066666666666666666f, 0.066666666666666666f, 0.2f};
        #pragma unroll
        for (int t4 = 0; t4 < 16; t4++) {
            float nx = XV[t4 & 3], ny = XV[t4 >> 2];
            int m = (n * 16 + t4) & (M2 - 1);
            float cx, cy, cz;
            if (m < NP) { cx = pos[m * 3]; cy = pos[m * 3 + 1]; cz = pos[m * 3 + 2]; }
            else { int mm = m - NP; cx = g_npos[mm * 3]; cy = g_npos[mm * 3 + 1]; cz = g_npos[mm * 3 + 2]; }
            float* op = out + (size_t)(n * 16 + t4) * 3;
            op[0] = r9[0] * nx + r9[1] * ny + cx;
            op[1] = r9[3] * nx + r9[4] * ny + cy;
            op[2] = r9[6] * nx + r9[7] * ny + cz;
        }
    }
}

// ---------------- host launcher ----------------------------------------------
extern "C" void kernel_launch(void* const* d_in, const int* in_sizes, int n_in,
                              void* d_out, int out_size)
{
    const float* pos = (const float*)d_in[1];
    const float* lfea = (const float*)d_in[4];
    const float* sw1 = (const float*)d_in[5];
    const float* sb1 = (const float*)d_in[6];
    const float* sw2 = (const float*)d_in[7];
    const float* sb2 = (const float*)d_in[8];
    const float* sw3 = (const float*)d_in[9];
    const float* sb3 = (const float*)d_in[10];
    const float* cw1 = (const float*)d_in[11];
    const float* cb1 = (const float*)d_in[12];
    const float* cw2 = (const float*)d_in[13];
    const float* cb2 = (const float*)d_in[14];
    const float* mw1 = (const float*)d_in[15];
    const float* mb1 = (const float*)d_in[16];
    const float* mw2 = (const float*)d_in[17];
    const float* mb2 = (const float*)d_in[18];
    const float* mw3 = (const float*)d_in[19];
    const float* mb3 = (const float*)d_in[20];
    float* out = (float*)d_out;

    float *p_lf_m1, *p_posfea, *p_g1, *p_wt1, *p_wt2;
    cudaGetSymbolAddress((void**)&p_lf_m1, g_lf_m1);
    cudaGetSymbolAddress((void**)&p_posfea, g_posfea);
    cudaGetSymbolAddress((void**)&p_g1, g_g1);
    cudaGetSymbolAddress((void**)&p_wt1, g_wt1);
    cudaGetSymbolAddress((void**)&p_wt2, g_wt2);

    cudaFuncSetAttribute(tc3mega, cudaFuncAttributeMaxDynamicSharedMemorySize, 71680);
    cudaFuncSetAttribute(gemm_tcp, cudaFuncAttributeMaxDynamicSharedMemorySize, 71680);
    cudaFuncSetAttribute(k_edge2, cudaFuncAttributeMaxDynamicSharedMemorySize, 69632);
    cudaFuncSetAttribute(gemm_g2rot, cudaFuncAttributeMaxDynamicSharedMemorySize, 104448);

    // 1. round weights to tf32 grid
    k_cvt_all<<<800, 256>>>(mw1 + 768 * 512, mw2, cw2);
    // 2-3. fused lf GEMM (virtual N=768) split-K + reduce
    gemm_sk2<<<dim3(12, 4, 6), 256>>>(lfea, sw1, mw1);
    k_red2<<<768, 256>>>();
    // 4. mega: h1 -> h2 -> n_pos -> KNN -> U/V
    tc3mega<<<dim3(1, 128), 256, 71680>>>(pos, sw1, sb1, sw2, sb2, sw3, sb3, cw1, cb1);
    // 5. edge MLP phase-B (double-buffered)
    k_edge2<<<512, 256, 69632>>>(cb2);
    // 6. g1 = relu(pos_fea @ wt1 + lf_m1[p] + mb1) — pipelined tf32
    gemm_tcp<<<dim3(4, 256), 256, 71680>>>(p_posfea, p_wt1, mb1, p_lf_m1, p_g1, M2, 128, 512, 2);
    // 7. g2 + rot + outputs, all fused
    gemm_g2rot<<<256, 256, 104448>>>(p_g1, p_wt2, mb2, mw3, mb3, pos, out);
}

// round 8
// speedup vs baseline: 5.9567x; 1.0376x over previous
#include <cuda_runtime.h>
#include <math.h>

#define PB  256
#define PTc 64
#define NP  16384      // N = P*PT
#define M2  32768      // 2N
#define R2C 0.09f

// ---------------- scratch (static device globals; no allocations) ------------
__device__ float g_lf_s1[PB * 256];
__device__ float g_lf_m1[PB * 512];
__device__ float g_npos[NP * 3];
__device__ int   g_nbr[M2 * 9];
__device__ float g_U[(size_t)M2 * 64];
__device__ float g_V[(size_t)M2 * 64];
__device__ float g_posfea[(size_t)M2 * 128];
__device__ float g_g1[(size_t)M2 * 512];
__device__ float g_part[6 * 256 * 768];
__device__ float g_wt1[128 * 512];    // tf32-rounded mw1[768:]
__device__ float g_wt2[512 * 256];    // tf32-rounded mw2
__device__ float g_wt3[64 * 128];     // tf32-rounded cw2
__device__ float g_w2h[256 * 128];    // sw2 hi (tf32 grid)
__device__ float g_w2l[256 * 128];    // sw2 lo residual (tf32 grid)

__device__ __forceinline__ unsigned f2tf(float f) {
    unsigned r; asm("cvt.rna.tf32.f32 %0, %1;" : "=r"(r) : "f"(f)); return r;
}
#define MMA_TF32(cc, aa, bb) \
    asm volatile("mma.sync.aligned.m16n8k8.row.col.f32.tf32.tf32.f32 " \
        "{%0,%1,%2,%3},{%4,%5,%6,%7},{%8,%9},{%0,%1,%2,%3};" \
        : "+f"(cc[0]), "+f"(cc[1]), "+f"(cc[2]), "+f"(cc[3]) \
        : "r"(aa[0]), "r"(aa[1]), "r"(aa[2]), "r"(aa[3]), "r"(bb[0]), "r"(bb[1]))

__device__ __forceinline__ void cp16(void* dst, const void* src) {
    unsigned d = (unsigned)__cvta_generic_to_shared(dst);
    asm volatile("cp.async.cg.shared.global [%0], [%1], 16;" :: "r"(d), "l"(src));
}

// ------------- cvt kernel: tf32-round wt1/wt2/wt3, hi/lo split of sw2 --------
__global__ void k_cvt_all(const float* __restrict__ w1, const float* __restrict__ w2,
                          const float* __restrict__ w3, const float* __restrict__ sw2)
{
    int i = blockIdx.x * 256 + threadIdx.x;
    if (i < 65536) g_wt1[i] = __uint_as_float(f2tf(w1[i]));
    else if (i < 196608) g_wt2[i - 65536] = __uint_as_float(f2tf(w2[i - 65536]));
    else if (i < 204800) g_wt3[i - 196608] = __uint_as_float(f2tf(w3[i - 196608]));
    else if (i < 237568) {
        int e = i - 204800;
        float f = sw2[e];
        float hi = __uint_as_float(__float_as_uint(f) & 0xffffe000u);
        g_w2h[e] = hi;
        g_w2l[e] = __uint_as_float(f2tf(f - hi));
    }
}

// ------- fused lf GEMM: A=lfea[256x768], virtual B = [sw1 | mw1] (N=768) -----
__global__ void gemm_sk2(const float* __restrict__ A, const float* __restrict__ sw1,
                         const float* __restrict__ mw1)
{
    __shared__ float As[64][17];
    __shared__ float Bs[16][65];
    const int bm = blockIdx.y * 64, bn = blockIdx.x * 64;
    const float* B; int Nn, coloff;
    if (bn < 256) { B = sw1; Nn = 256; coloff = bn; }
    else          { B = mw1; Nn = 512; coloff = bn - 256; }
    const int t = threadIdx.x;
    const int ty = t >> 4, tx = t & 15;
    float acc[4][4] = {};
    int kbeg = blockIdx.z * 128, kend = kbeg + 128;
    for (int k0 = kbeg; k0 < kend; k0 += 16) {
        #pragma unroll
        for (int i = 0; i < 4; i++) {
            int e = t + i * 256; int r = e >> 4, c = e & 15;
            As[r][c] = A[(size_t)(bm + r) * 768 + k0 + c];
        }
        #pragma unroll
        for (int i = 0; i < 4; i++) {
            int e = t + i * 256; int r = e >> 6, c = e & 63;
            Bs[r][c] = B[(size_t)(k0 + r) * Nn + coloff + c];
        }
        __syncthreads();
        #pragma unroll
        for (int kk = 0; kk < 16; kk++) {
            float a[4], b[4];
            #pragma unroll
            for (int i = 0; i < 4; i++) a[i] = As[ty * 4 + i][kk];
            #pragma unroll
            for (int j = 0; j < 4; j++) b[j] = Bs[kk][tx * 4 + j];
            #pragma unroll
            for (int i = 0; i < 4; i++)
                #pragma unroll
                for (int j = 0; j < 4; j++)
                    acc[i][j] += a[i] * b[j];
        }
        __syncthreads();
    }
    float* Cz = g_part + (size_t)blockIdx.z * 256 * 768;
    #pragma unroll
    for (int i = 0; i < 4; i++)
        #pragma unroll
        for (int j = 0; j < 4; j++)
            Cz[(size_t)(bm + ty * 4 + i) * 768 + bn + tx * 4 + j] = acc[i][j];
}

__global__ void k_red2()
{
    int e = blockIdx.x * 256 + threadIdx.x;   // < 256*768
    float s = 0.f;
    #pragma unroll
    for (int z = 0; z < 6; z++) s += g_part[(size_t)z * 196608 + e];
    int row = e / 768, col = e - row * 768;
    if (col < 256) g_lf_s1[row * 256 + col] = s;
    else           g_lf_m1[row * 512 + col - 256] = s;
}

// ------- mega: h1 on-the-fly -> 3xTF32 h2 GEMM -> n_pos -> KNN -> U/V --------
// block = 128 rows = 2 complete batches (p0, p0+1)
__global__ void __launch_bounds__(256)
tc3mega(const float* __restrict__ pos, const float* __restrict__ sw1,
        const float* __restrict__ sb1, const float* __restrict__ sb2,
        const float* __restrict__ sw3, const float* __restrict__ sb3,
        const float* __restrict__ cw1, const float* __restrict__ cb1)
{
    extern __shared__ unsigned sm3[];
    unsigned* Ah = sm3;                 // [128][36]
    unsigned* Al = Ah + 128 * 36;
    unsigned* Bh = Al + 128 * 36;       // [32][136]
    unsigned* Bl = Bh + 32 * 136;
    const int t = threadIdx.x;
    const int warp = t >> 5, lane = t & 31;
    const int g = lane >> 2, q = lane & 3;
    const int wm = warp >> 1, wn = warp & 1;
    const int bm = blockIdx.y * 128;
    const int p0 = bm >> 6;

    float c[2][8][4];
    #pragma unroll
    for (int i = 0; i < 2; i++)
        #pragma unroll
        for (int j = 0; j < 8; j++)
            #pragma unroll
            for (int e = 0; e < 4; e++) c[i][j][e] = 0.f;

    // hoisted per-row pos (rows fixed across k0)
    const int rA = t >> 3, c4A = (t & 7) * 4;
    float pxr[4], pyr[4], pzr[4];
    #pragma unroll
    for (int i = 0; i < 4; i++) {
        int row = bm + rA + i * 32;
        pxr[i] = pos[row * 3]; pyr[i] = pos[row * 3 + 1]; pzr[i] = pos[row * 3 + 2];
    }

    for (int k0 = 0; k0 < 256; k0 += 32) {
        // prefetch B hi/lo (pre-split) via cp.async — overlaps A compute
        #pragma unroll
        for (int i = 0; i < 4; i++) {
            int e = t + i * 256; int r = e >> 5, c4 = (e & 31) * 4;
            cp16(&Bh[r * 136 + c4], g_w2h + (size_t)(k0 + r) * 128 + c4);
            cp16(&Bl[r * 136 + c4], g_w2l + (size_t)(k0 + r) * 128 + c4);
        }
        asm volatile("cp.async.commit_group;");
        // A fill: h1 on the fly, mask-split hi, cvt only for lo
        #pragma unroll
        for (int i = 0; i < 4; i++) {
            int r = rA + i * 32;
            int row = bm + r, cc = k0 + c4A;
            int p = row >> 6;
            float4 lf = *(const float4*)(g_lf_s1 + p * 256 + cc);
            float4 b1 = *(const float4*)(sb1 + cc);
            float4 w0 = *(const float4*)(sw1 + 768 * 256 + cc);
            float4 w1 = *(const float4*)(sw1 + 769 * 256 + cc);
            float4 w2 = *(const float4*)(sw1 + 770 * 256 + cc);
            float px = pxr[i], py = pyr[i], pz = pzr[i];
            float h0 = fmaxf(lf.x + b1.x + px * w0.x + py * w1.x + pz * w2.x, 0.f);
            float h1v = fmaxf(lf.y + b1.y + px * w0.y + py * w1.y + pz * w2.y, 0.f);
            float h2v = fmaxf(lf.z + b1.z + px * w0.z + py * w1.z + pz * w2.z, 0.f);
            float h3 = fmaxf(lf.w + b1.w + px * w0.w + py * w1.w + pz * w2.w, 0.f);
            unsigned u0 = __float_as_uint(h0) & 0xffffe000u;
            unsigned u1 = __float_as_uint(h1v) & 0xffffe000u;
            unsigned u2 = __float_as_uint(h2v) & 0xffffe000u;
            unsigned u3 = __float_as_uint(h3) & 0xffffe000u;
            *(uint4*)&Ah[r * 36 + c4A] = make_uint4(u0, u1, u2, u3);
            *(uint4*)&Al[r * 36 + c4A] = make_uint4(
                f2tf(h0 - __uint_as_float(u0)), f2tf(h1v - __uint_as_float(u1)),
                f2tf(h2v - __uint_as_float(u2)), f2tf(h3 - __uint_as_float(u3)));
        }
        asm volatile("cp.async.wait_group 0;");
        __syncthreads();
        #pragma unroll
        for (int ks = 0; ks < 4; ks++) {
            int k8 = ks * 8;
            unsigned ah[2][4], al[2][4];
            #pragma unroll
            for (int mt = 0; mt < 2; mt++) {
                int r = wm * 32 + mt * 16 + g;
                ah[mt][0] = Ah[r * 36 + k8 + q];       al[mt][0] = Al[r * 36 + k8 + q];
                ah[mt][1] = Ah[(r + 8) * 36 + k8 + q]; al[mt][1] = Al[(r + 8) * 36 + k8 + q];
                ah[mt][2] = Ah[r * 36 + k8 + q + 4];   al[mt][2] = Al[r * 36 + k8 + q + 4];
                ah[mt][3] = Ah[(r + 8) * 36 + k8 + q + 4]; al[mt][3] = Al[(r + 8) * 36 + k8 + q + 4];
            }
            #pragma unroll
            for (int nt = 0; nt < 8; nt++) {
                int cn = wn * 64 + nt * 8 + g;
                unsigned bh[2], bl[2];
                bh[0] = Bh[(k8 + q) * 136 + cn];     bh[1] = Bh[(k8 + q + 4) * 136 + cn];
                bl[0] = Bl[(k8 + q) * 136 + cn];     bl[1] = Bl[(k8 + q + 4) * 136 + cn];
                #pragma unroll
                for (int mt = 0; mt < 2; mt++) {
                    MMA_TF32(c[mt][nt], al[mt], bh);
                    MMA_TF32(c[mt][nt], ah[mt], bl);
                    MMA_TF32(c[mt][nt], ah[mt], bh);
                }
            }
        }
        __syncthreads();
    }

    // ---- phase 2: n_pos via smem reduction ----
    float* fsm = (float*)sm3;
    float* sred = fsm;                 // 128*8*3
    float* snp  = fsm + 3072;          // 128*3
    float* sx   = fsm + 3456;          // 256
    float* sy   = fsm + 3712;
    float* sz   = fsm + 3968;
    float* scw1 = fsm + 4224;          // 384
    float* scb1 = fsm + 4608;          // 64
    #pragma unroll
    for (int mt = 0; mt < 2; mt++) {
        #pragma unroll
        for (int half = 0; half < 2; half++) {
            int row_l = wm * 32 + mt * 16 + half * 8 + g;
            float p0v = 0.f, p1 = 0.f, p2 = 0.f;
            #pragma unroll
            for (int nt = 0; nt < 8; nt++) {
                int col = wn * 64 + nt * 8 + q * 2;
                float v0 = fmaxf(c[mt][nt][half * 2 + 0] + sb2[col], 0.f);
                float v1 = fmaxf(c[mt][nt][half * 2 + 1] + sb2[col + 1], 0.f);
                p0v += v0 * sw3[col * 3]     + v1 * sw3[(col + 1) * 3];
                p1 += v0 * sw3[col * 3 + 1] + v1 * sw3[(col + 1) * 3 + 1];
                p2 += v0 * sw3[col * 3 + 2] + v1 * sw3[(col + 1) * 3 + 2];
            }
            int slot = wn * 4 + q;
            sred[(row_l * 8 + slot) * 3 + 0] = p0v;
            sred[(row_l * 8 + slot) * 3 + 1] = p1;
            sred[(row_l * 8 + slot) * 3 + 2] = p2;
        }
    }
    __syncthreads();
    if (t < 128) {
        float a0 = 0.f, a1 = 0.f, a2 = 0.f;
        #pragma unroll
        for (int s = 0; s < 8; s++) {
            a0 += sred[(t * 8 + s) * 3 + 0];
            a1 += sred[(t * 8 + s) * 3 + 1];
            a2 += sred[(t * 8 + s) * 3 + 2];
        }
        int row = bm + t;
        float n0 = tanhf(fmaxf(a0 + sb3[0], 0.f)) + pos[row * 3 + 0];
        float n1 = tanhf(fmaxf(a1 + sb3[1], 0.f)) + pos[row * 3 + 1];
        float n2 = tanhf(fmaxf(a2 + sb3[2], 0.f)) + pos[row * 3 + 2];
        g_npos[row * 3 + 0] = n0; g_npos[row * 3 + 1] = n1; g_npos[row * 3 + 2] = n2;
        snp[t * 3 + 0] = n0; snp[t * 3 + 1] = n1; snp[t * 3 + 2] = n2;
    }
    __syncthreads();

    // ---- phase 3: KNN for the 2 batches + U/V ----
    int b = t >> 7, i = t & 127;
    int rowl = b * 64 + (i & 63);
    float x, y, z;
    if (i < 64) {
        int gr = bm + rowl;
        x = pos[gr * 3]; y = pos[gr * 3 + 1]; z = pos[gr * 3 + 2];
    } else {
        x = snp[rowl * 3]; y = snp[rowl * 3 + 1]; z = snp[rowl * 3 + 2];
    }
    sx[b * 128 + i] = x; sy[b * 128 + i] = y; sz[b * 128 + i] = z;
    for (int e = t; e < 448; e += 256) {
        if (e < 384) scw1[e] = cw1[e]; else scb1[e - 384] = cb1[e - 384];
    }
    __syncthreads();

    unsigned long long bk[9];
    #pragma unroll
    for (int qq = 0; qq < 9; qq++) bk[qq] = 0xFFFFFFFFFFFFFFFFull;
    const float* sxb = sx + b * 128; const float* syb = sy + b * 128; const float* szb = sz + b * 128;
    for (int j = 0; j < 128; j++) {
        float dx = x - sxb[j], dy = y - syb[j], dz = z - szb[j];
        float d2 = dx * dx + dy * dy + dz * dz;
        if (d2 <= R2C) {
            unsigned long long key = ((unsigned long long)__float_as_uint(d2) << 32) | (unsigned)j;
            if (key < bk[8]) {
                bk[8] = key;
                #pragma unroll
                for (int qq = 8; qq > 0; qq--)
                    if (bk[qq] < bk[qq - 1]) {
                        unsigned long long tmp = bk[qq]; bk[qq] = bk[qq - 1]; bk[qq - 1] = tmp;
                    }
            }
        }
    }
    int ptg = (p0 + b) * 128 + i;
    int bi0 = (int)(unsigned)bk[0];   // self always present (d2=0)
    #pragma unroll
    for (int qq = 0; qq < 9; qq++)
        g_nbr[ptg * 9 + qq] = (bk[qq] != 0xFFFFFFFFFFFFFFFFull) ? (int)(unsigned)bk[qq] : bi0;

    // U/V cooperative (coalesced): e over 256 pts * 64 ch
    for (int e = t; e < 256 * 64; e += 256) {
        int ptl = e >> 6, k = e & 63;
        float xx = sx[ptl], yy = sy[ptl], zz = sz[ptl];
        float wn0 = scw1[k],       wn1 = scw1[64 + k],  wn2 = scw1[128 + k];
        float wr0 = scw1[192 + k], wr1 = scw1[256 + k], wr2 = scw1[320 + k];
        int ptgl = (p0 + (ptl >> 7)) * 128 + (ptl & 127);
        g_U[(size_t)ptgl * 64 + k] = scb1[k] + xx * (wn0 + wr0) + yy * (wn1 + wr1) + zz * (wn2 + wr2);
        g_V[(size_t)ptgl * 64 + k] = xx * wr0 + yy * wr1 + zz * wr2;
    }
}

// ------------- edge MLP phase-B: double-buffered per-qn A slices -------------
__global__ void __launch_bounds__(256)
k_edge2(const float* __restrict__ cb2)
{
    extern __shared__ unsigned esm[];
    unsigned* Bs = esm;                       // [64][136]
    unsigned* Abuf[2] = { esm + 64 * 136, esm + 64 * 136 + 64 * 68 };
    const int t = threadIdx.x;
    const int warp = t >> 5, lane = t & 31;
    const int g = lane >> 2, q = lane & 3;
    const int wm = warp >> 1, wn = warp & 1;
    const int p = blockIdx.x >> 1, half = blockIdx.x & 1;
    const int ptbase = p * 128 + half * 64;

    for (int e = t; e < 64 * 128; e += 256)
        Bs[(e >> 7) * 136 + (e & 127)] = __float_as_uint(g_wt3[e]);

    const int r4 = t >> 2, q4 = t & 3;
    float vv[16];
    {
        const float4* Vr = (const float4*)(g_V + (size_t)(ptbase + r4) * 64 + q4 * 16);
        #pragma unroll
        for (int j4 = 0; j4 < 4; j4++) {
            float4 v = Vr[j4];
            vv[j4 * 4 + 0] = v.x; vv[j4 * 4 + 1] = v.y;
            vv[j4 * 4 + 2] = v.z; vv[j4 * 4 + 3] = v.w;
        }
    }
    // fill qn=0
    {
        int nb = g_nbr[(ptbase + r4) * 9 + 0];
        const float4* Ur = (const float4*)(g_U + (size_t)(p * 128 + nb) * 64 + q4 * 16);
        #pragma unroll
        for (int j4 = 0; j4 < 4; j4++) {
            float4 u = Ur[j4];
            *(uint4*)&Abuf[0][r4 * 68 + q4 * 16 + j4 * 4] = make_uint4(
                f2tf(fmaxf(u.x - vv[j4 * 4 + 0], 0.f)),
                f2tf(fmaxf(u.y - vv[j4 * 4 + 1], 0.f)),
                f2tf(fmaxf(u.z - vv[j4 * 4 + 2], 0.f)),
                f2tf(fmaxf(u.w - vv[j4 * 4 + 3], 0.f)));
        }
    }

    float mx[8][4];
    #pragma unroll 1
    for (int qn = 0; qn < 9; qn++) {
        __syncthreads();
        if (qn < 8) {
            int nb = g_nbr[(ptbase + r4) * 9 + qn + 1];
            const float4* Ur = (const float4*)(g_U + (size_t)(p * 128 + nb) * 64 + q4 * 16);
            unsigned* dst = Abuf[(qn + 1) & 1];
            #pragma unroll
            for (int j4 = 0; j4 < 4; j4++) {
                float4 u = Ur[j4];
                *(uint4*)&dst[r4 * 68 + q4 * 16 + j4 * 4] = make_uint4(
                    f2tf(fmaxf(u.x - vv[j4 * 4 + 0], 0.f)),
                    f2tf(fmaxf(u.y - vv[j4 * 4 + 1], 0.f)),
                    f2tf(fmaxf(u.z - vv[j4 * 4 + 2], 0.f)),
                    f2tf(fmaxf(u.w - vv[j4 * 4 + 3], 0.f)));
            }
        }
        const unsigned* As = Abuf[qn & 1];
        float acc[8][4];
        #pragma unroll
        for (int nt = 0; nt < 8; nt++)
            #pragma unroll
            for (int e = 0; e < 4; e++) acc[nt][e] = 0.f;
        #pragma unroll
        for (int ks = 0; ks < 8; ks++) {
            int k8 = ks * 8;
            unsigned a[4];
            int rr = wm * 16 + g;
            a[0] = As[rr * 68 + k8 + q];
            a[1] = As[(rr + 8) * 68 + k8 + q];
            a[2] = As[rr * 68 + k8 + q + 4];
            a[3] = As[(rr + 8) * 68 + k8 + q + 4];
            #pragma unroll
            for (int nt = 0; nt < 8; nt++) {
                int cn = wn * 64 + nt * 8 + g;
                unsigned b[2];
                b[0] = Bs[(k8 + q) * 136 + cn];
                b[1] = Bs[(k8 + q + 4) * 136 + cn];
                MMA_TF32(acc[nt], a, b);
            }
        }
        if (qn == 0) {
            #pragma unroll
            for (int nt = 0; nt < 8; nt++)
                #pragma unroll
                for (int e = 0; e < 4; e++) mx[nt][e] = acc[nt][e];
        } else {
            #pragma unroll
            for (int nt = 0; nt < 8; nt++)
                #pragma unroll
                for (int e = 0; e < 4; e++) mx[nt][e] = fmaxf(mx[nt][e], acc[nt][e]);
        }
    }

    #pragma unroll
    for (int hh = 0; hh < 2; hh++) {
        int pl = wm * 16 + g + hh * 8;
        size_t row = (half == 0) ? (size_t)(p * 64 + pl)
                                 : (size_t)(NP + p * 64 + pl);
        #pragma unroll
        for (int nt = 0; nt < 8; nt++) {
            int col = wn * 64 + nt * 8 + q * 2;
            float v0 = fmaxf(mx[nt][hh * 2 + 0] + cb2[col], 0.f);
            float v1 = fmaxf(mx[nt][hh * 2 + 1] + cb2[col + 1], 0.f);
            *(float2*)&g_posfea[row * 128 + col] =
                make_float2(__uint_as_float(f2tf(v0)), __uint_as_float(f2tf(v1)));
        }
    }
}

// ------- pipelined tf32 GEMM, 128x256 tile (used for g1, K=128, Nn=512) ------
// epilogue: relu(+bias + lfE[batch(row)]), store tf32-rounded
__global__ void __launch_bounds__(256)
gemm_tcp256(const float* __restrict__ A, const float* __restrict__ B,
            const float* __restrict__ bias, const float* __restrict__ lfE,
            float* __restrict__ C, int K, int Nn)
{
    extern __shared__ float psm[];
    float* Asm[2] = { psm, psm + 128 * 36 };
    float* Bsm[2] = { psm + 2 * 128 * 36, psm + 2 * 128 * 36 + 32 * 264 };
    const int t = threadIdx.x;
    const int warp = t >> 5, lane = t & 31;
    const int g = lane >> 2, q = lane & 3;
    const int wm = warp >> 1, wn = warp & 1;
    const int bm = blockIdx.y * 128, bn = blockIdx.x * 256;
    const int T = K >> 5;

    float c[2][16][4];
    #pragma unroll
    for (int i = 0; i < 2; i++)
        #pragma unroll
        for (int j = 0; j < 16; j++)
            #pragma unroll
            for (int e = 0; e < 4; e++) c[i][j][e] = 0.f;

    {
        const float* Ab = A + (size_t)bm * K;
        const float* Bb = B + bn;
        #pragma unroll
        for (int i = 0; i < 4; i++) {
            int e = t + i * 256; int r = e >> 3, c4 = e & 7;
            cp16(&Asm[0][r * 36 + c4 * 4], Ab + (size_t)r * K + c4 * 4);
        }
        #pragma unroll
        for (int i = 0; i < 8; i++) {
            int e = t + i * 256; int r = e >> 6, c4 = e & 63;
            cp16(&Bsm[0][r * 264 + c4 * 4], Bb + (size_t)r * Nn + c4 * 4);
        }
        asm volatile("cp.async.commit_group;");
    }

    for (int tt = 0; tt < T; tt++) {
        if (tt + 1 < T) {
            int s = (tt + 1) & 1;
            const float* Ab = A + (size_t)bm * K + (tt + 1) * 32;
            const float* Bb = B + (size_t)(tt + 1) * 32 * Nn + bn;
            #pragma unroll
            for (int i = 0; i < 4; i++) {
                int e = t + i * 256; int r = e >> 3, c4 = e & 7;
                cp16(&Asm[s][r * 36 + c4 * 4], Ab + (size_t)r * K + c4 * 4);
            }
            #pragma unroll
            for (int i = 0; i < 8; i++) {
                int e = t + i * 256; int r = e >> 6, c4 = e & 63;
                cp16(&Bsm[s][r * 264 + c4 * 4], Bb + (size_t)r * Nn + c4 * 4);
            }
            asm volatile("cp.async.commit_group;");
            asm volatile("cp.async.wait_group 1;");
        } else {
            asm volatile("cp.async.wait_group 0;");
        }
        __syncthreads();
        const unsigned* As = (const unsigned*)Asm[tt & 1];
        const unsigned* Bs = (const unsigned*)Bsm[tt & 1];
        #pragma unroll
        for (int ks = 0; ks < 4; ks++) {
            int k8 = ks * 8;
            unsigned a[2][4];
            #pragma unroll
            for (int mt = 0; mt < 2; mt++) {
                int r = wm * 32 + mt * 16 + g;
                a[mt][0] = As[r * 36 + k8 + q];
                a[mt][1] = As[(r + 8) * 36 + k8 + q];
                a[mt][2] = As[r * 36 + k8 + q + 4];
                a[mt][3] = As[(r + 8) * 36 + k8 + q + 4];
            }
            #pragma unroll
            for (int nt = 0; nt < 16; nt++) {
                int cn = wn * 128 + nt * 8 + g;
                unsigned b[2];
                b[0] = Bs[(k8 + q) * 264 + cn];
                b[1] = Bs[(k8 + q + 4) * 264 + cn];
                MMA_TF32(c[0][nt], a[0], b);
                MMA_TF32(c[1][nt], a[1], b);
            }
        }
        __syncthreads();
    }

    #pragma unroll
    for (int mt = 0; mt < 2; mt++) {
        #pragma unroll
        for (int half = 0; half < 2; half++) {
            int row = bm + wm * 32 + mt * 16 + half * 8 + g;
            int rowp = (row < NP) ? (row >> 6) : ((row - NP) >> 6);
            #pragma unroll
            for (int nt = 0; nt < 16; nt++) {
                int col = bn + wn * 128 + nt * 8 + q * 2;
                float v0 = c[mt][nt][half * 2 + 0] + bias[col] + lfE[(size_t)rowp * Nn + col];
                float v1 = c[mt][nt][half * 2 + 1] + bias[col + 1] + lfE[(size_t)rowp * Nn + col + 1];
                v0 = __uint_as_float(f2tf(fmaxf(v0, 0.f)));
                v1 = __uint_as_float(f2tf(fmaxf(v1, 0.f)));
                *(float2*)&C[(size_t)row * Nn + col] = make_float2(v0, v1);
            }
        }
    }
}

// ------- g2 (128x256 tile, K=512) fused with rot + both outputs --------------
__global__ void __launch_bounds__(256)
gemm_g2rot(const float* __restrict__ A, const float* __restrict__ B,
           const float* __restrict__ mb2, const float* __restrict__ mw3,
           const float* __restrict__ mb3, const float* __restrict__ pos,
           float* __restrict__ out)
{
    extern __shared__ float psm[];
    float* Asm[2] = { psm, psm + 128 * 36 };
    float* Bsm[2] = { psm + 2 * 128 * 36, psm + 2 * 128 * 36 + 32 * 264 };
    const int t = threadIdx.x;
    const int warp = t >> 5, lane = t & 31;
    const int g = lane >> 2, q = lane & 3;
    const int wm = warp >> 1, wn = warp & 1;
    const int bm = blockIdx.x * 128;

    float c[2][16][4];
    #pragma unroll
    for (int i = 0; i < 2; i++)
        #pragma unroll
        for (int j = 0; j < 16; j++)
            #pragma unroll
            for (int e = 0; e < 4; e++) c[i][j][e] = 0.f;

    {
        const float* Ab = A + (size_t)bm * 512;
        #pragma unroll
        for (int i = 0; i < 4; i++) {
            int e = t + i * 256; int r = e >> 3, c4 = e & 7;
            cp16(&Asm[0][r * 36 + c4 * 4], Ab + (size_t)r * 512 + c4 * 4);
        }
        #pragma unroll
        for (int i = 0; i < 8; i++) {
            int e = t + i * 256; int r = e >> 6, c4 = e & 63;
            cp16(&Bsm[0][r * 264 + c4 * 4], B + (size_t)r * 256 + c4 * 4);
        }
        asm volatile("cp.async.commit_group;");
    }

    for (int tt = 0; tt < 16; tt++) {
        if (tt + 1 < 16) {
            int s = (tt + 1) & 1;
            const float* Ab = A + (size_t)bm * 512 + (tt + 1) * 32;
            const float* Bb = B + (size_t)(tt + 1) * 32 * 256;
            #pragma unroll
            for (int i = 0; i < 4; i++) {
                int e = t + i * 256; int r = e >> 3, c4 = e & 7;
                cp16(&Asm[s][r * 36 + c4 * 4], Ab + (size_t)r * 512 + c4 * 4);
            }
            #pragma unroll
            for (int i = 0; i < 8; i++) {
                int e = t + i * 256; int r = e >> 6, c4 = e & 63;
                cp16(&Bsm[s][r * 264 + c4 * 4], Bb + (size_t)r * 256 + c4 * 4);
            }
            asm volatile("cp.async.commit_group;");
            asm volatile("cp.async.wait_group 1;");
        } else {
            asm volatile("cp.async.wait_group 0;");
        }
        __syncthreads();
        const unsigned* As = (const unsigned*)Asm[tt & 1];
        const unsigned* Bs = (const unsigned*)Bsm[tt & 1];
        #pragma unroll
        for (int ks = 0; ks < 4; ks++) {
            int k8 = ks * 8;
            unsigned a[2][4];
            #pragma unroll
            for (int mt = 0; mt < 2; mt++) {
                int r = wm * 32 + mt * 16 + g;
                a[mt][0] = As[r * 36 + k8 + q];
                a[mt][1] = As[(r + 8) * 36 + k8 + q];
                a[mt][2] = As[r * 36 + k8 + q + 4];
                a[mt][3] = As[(r + 8) * 36 + k8 + q + 4];
            }
            #pragma unroll
            for (int nt = 0; nt < 16; nt++) {
                int cn = wn * 128 + nt * 8 + g;
                unsigned b[2];
                b[0] = Bs[(k8 + q) * 264 + cn];
                b[1] = Bs[(k8 + q + 4) * 264 + cn];
                MMA_TF32(c[0][nt], a[0], b);
                MMA_TF32(c[1][nt], a[1], b);
            }
        }
        __syncthreads();
    }

    // epilogue: v = relu(c + mb2); partial dots with mw3; reduce 8 slots/row
    float* sred = psm;   // 128 rows * 8 slots * 9 = 9216 floats
    #pragma unroll
    for (int mt = 0; mt < 2; mt++) {
        #pragma unroll
        for (int half = 0; half < 2; half++) {
            int row_l = wm * 32 + mt * 16 + half * 8 + g;
            float p9[9];
            #pragma unroll
            for (int j = 0; j < 9; j++) p9[j] = 0.f;
            #pragma unroll
            for (int nt = 0; nt < 16; nt++) {
                int col = wn * 128 + nt * 8 + q * 2;
                float v0 = fmaxf(c[mt][nt][half * 2 + 0] + mb2[col], 0.f);
                float v1 = fmaxf(c[mt][nt][half * 2 + 1] + mb2[col + 1], 0.f);
                #pragma unroll
                for (int j = 0; j < 9; j++)
                    p9[j] += v0 * mw3[col * 9 + j] + v1 * mw3[(col + 1) * 9 + j];
            }
            int slot = wn * 4 + q;
            #pragma unroll
            for (int j = 0; j < 9; j++)
                sred[(row_l * 8 + slot) * 9 + j] = p9[j];
        }
    }
    __syncthreads();
    if (t < 128) {
        float r9[9];
        #pragma unroll
        for (int j = 0; j < 9; j++) {
            float s = 0.f;
            #pragma unroll
            for (int sl = 0; sl < 8; sl++) s += sred[(t * 8 + sl) * 9 + j];
            r9[j] = fmaxf(s + mb3[j], 0.f);
        }
        int n = bm + t;
        // rot_constrain
        float* oc = out + (size_t)16 * M2 * 3 + (size_t)n * 9;
        #pragma unroll
        for (int i = 0; i < 3; i++)
            #pragma unroll
            for (int j = 0; j < 3; j++)
                oc[i * 3 + j] = r9[0 + i] * r9[0 + j] + r9[3 + i] * r9[3 + j] + r9[6 + i] * r9[6 + j];
        // plane_init: 16 entries for this n
        const float XV[4] = {-0.2f, -0.066666666666666666f, 0.066666666666666666f, 0.2f};
        #pragma unroll
        for (int t4 = 0; t4 < 16; t4++) {
            float nx = XV[t4 & 3], ny = XV[t4 >> 2];
            int m = (n * 16 + t4) & (M2 - 1);
            float cx, cy, cz;
            if (m < NP) { cx = pos[m * 3]; cy = pos[m * 3 + 1]; cz = pos[m * 3 + 2]; }
            else { int mm = m - NP; cx = g_npos[mm * 3]; cy = g_npos[mm * 3 + 1]; cz = g_npos[mm * 3 + 2]; }
            float* op = out + (size_t)(n * 16 + t4) * 3;
            op[0] = r9[0] * nx + r9[1] * ny + cx;
            op[1] = r9[3] * nx + r9[4] * ny + cy;
            op[2] = r9[6] * nx + r9[7] * ny + cz;
        }
    }
}

// ---------------- host launcher ----------------------------------------------
extern "C" void kernel_launch(void* const* d_in, const int* in_sizes, int n_in,
                              void* d_out, int out_size)
{
    const float* pos = (const float*)d_in[1];
    const float* lfea = (const float*)d_in[4];
    const float* sw1 = (const float*)d_in[5];
    const float* sb1 = (const float*)d_in[6];
    const float* sw2 = (const float*)d_in[7];
    const float* sb2 = (const float*)d_in[8];
    const float* sw3 = (const float*)d_in[9];
    const float* sb3 = (const float*)d_in[10];
    const float* cw1 = (const float*)d_in[11];
    const float* cb1 = (const float*)d_in[12];
    const float* cw2 = (const float*)d_in[13];
    const float* cb2 = (const float*)d_in[14];
    const float* mw1 = (const float*)d_in[15];
    const float* mb1 = (const float*)d_in[16];
    const float* mw2 = (const float*)d_in[17];
    const float* mb2 = (const float*)d_in[18];
    const float* mw3 = (const float*)d_in[19];
    const float* mb3 = (const float*)d_in[20];
    float* out = (float*)d_out;

    float *p_lf_m1, *p_posfea, *p_g1, *p_wt1, *p_wt2;
    cudaGetSymbolAddress((void**)&p_lf_m1, g_lf_m1);
    cudaGetSymbolAddress((void**)&p_posfea, g_posfea);
    cudaGetSymbolAddress((void**)&p_g1, g_g1);
    cudaGetSymbolAddress((void**)&p_wt1, g_wt1);
    cudaGetSymbolAddress((void**)&p_wt2, g_wt2);

    cudaFuncSetAttribute(tc3mega, cudaFuncAttributeMaxDynamicSharedMemorySize, 71680);
    cudaFuncSetAttribute(gemm_tcp256, cudaFuncAttributeMaxDynamicSharedMemorySize, 104448);
    cudaFuncSetAttribute(k_edge2, cudaFuncAttributeMaxDynamicSharedMemorySize, 69632);
    cudaFuncSetAttribute(gemm_g2rot, cudaFuncAttributeMaxDynamicSharedMemorySize, 104448);

    // 1. tf32 rounding + sw2 hi/lo split
    k_cvt_all<<<928, 256>>>(mw1 + 768 * 512, mw2, cw2, sw2);
    // 2-3. fused lf GEMM (virtual N=768) split-K + reduce
    gemm_sk2<<<dim3(12, 4, 6), 256>>>(lfea, sw1, mw1);
    k_red2<<<768, 256>>>();
    // 4. mega: h1 -> h2 -> n_pos -> KNN -> U/V
    tc3mega<<<dim3(1, 128), 256, 71680>>>(pos, sw1, sb1, sb2, sw3, sb3, cw1, cb1);
    // 5. edge MLP phase-B (double-buffered)
    k_edge2<<<512, 256, 69632>>>(cb2);
    // 6. g1 = relu(pos_fea @ wt1 + lf_m1[p] + mb1) — 128x256-tile tf32
    gemm_tcp256<<<dim3(2, 256), 256, 104448>>>(p_posfea, p_wt1, mb1, p_lf_m1, p_g1, 128, 512);
    // 7. g2 + rot + outputs, all fused
    gemm_g2rot<<<256, 256, 104448>>>(p_g1, p_wt2, mb2, mw3, mb3, pos, out);
}

// round 9
// speedup vs baseline: 7.8258x; 1.3138x over previous
#include <cuda_runtime.h>
#include <cuda_fp16.h>
#include <math.h>

#define PB  256
#define PTc 64
#define NP  16384      // N = P*PT
#define M2  32768      // 2N
#define R2C 0.09f

// ---------------- scratch (static device globals; no allocations) ------------
__device__ float g_lf_s1[PB * 256];
__device__ float g_lf_m1[PB * 512];
__device__ float g_npos[NP * 3];
__device__ int   g_nbr[M2 * 9];
__device__ float g_U[(size_t)M2 * 64];
__device__ float g_V[(size_t)M2 * 64];
__device__ __half2 g_posfeah[(size_t)M2 * 64];   // pos_fea, K-pair packed
__device__ __half2 g_g1h[(size_t)M2 * 256];      // g1, K-pair packed
__device__ float g_part[6 * 256 * 768];
__device__ __half2 g_wt1h[64 * 512];    // mw1[768:] K-pair packed fp16
__device__ __half2 g_wt2h[256 * 256];   // mw2 K-pair packed fp16
__device__ __half2 g_wt3h[32 * 128];    // cw2 K-pair packed fp16
__device__ __half2 g_w2hh[128 * 128];   // sw2 hi, K-pair packed
__device__ __half2 g_w2lh[128 * 128];   // sw2 lo residual, K-pair packed

#define MMA_F16(cc, aa, bb) \
    asm volatile("mma.sync.aligned.m16n8k16.row.col.f32.f16.f16.f32 " \
        "{%0,%1,%2,%3},{%4,%5,%6,%7},{%8,%9},{%0,%1,%2,%3};" \
        : "+f"(cc[0]), "+f"(cc[1]), "+f"(cc[2]), "+f"(cc[3]) \
        : "r"(aa[0]), "r"(aa[1]), "r"(aa[2]), "r"(aa[3]), "r"(bb[0]), "r"(bb[1]))

__device__ __forceinline__ void cp16(void* dst, const void* src) {
    unsigned d = (unsigned)__cvta_generic_to_shared(dst);
    asm volatile("cp.async.cg.shared.global [%0], [%1], 16;" :: "r"(d), "l"(src));
}

// ------------- cvt kernel: fp16 K-pair packing of all GEMM weights -----------
__global__ void k_cvt_all(const float* __restrict__ w1, const float* __restrict__ w2,
                          const float* __restrict__ w3, const float* __restrict__ sw2)
{
    int i = blockIdx.x * 256 + threadIdx.x;
    if (i < 32768) {                       // wt1h: [64 kk][512 n]
        int kk = i >> 9, n = i & 511;
        g_wt1h[i] = __floats2half2_rn(w1[(2 * kk) * 512 + n], w1[(2 * kk + 1) * 512 + n]);
    } else if (i < 98304) {                // wt2h: [256 kk][256 n]
        int e = i - 32768; int kk = e >> 8, n = e & 255;
        g_wt2h[e] = __floats2half2_rn(w2[(2 * kk) * 256 + n], w2[(2 * kk + 1) * 256 + n]);
    } else if (i < 102400) {               // wt3h: [32 kk][128 n]
        int e = i - 98304; int kk = e >> 7, n = e & 127;
        g_wt3h[e] = __floats2half2_rn(w3[(2 * kk) * 128 + n], w3[(2 * kk + 1) * 128 + n]);
    } else if (i < 118784) {               // sw2 hi/lo: [128 kk][128 n]
        int e = i - 102400; int kk = e >> 7, n = e & 127;
        float f0 = sw2[(2 * kk) * 128 + n], f1 = sw2[(2 * kk + 1) * 128 + n];
        __half h0 = __float2half_rn(f0), h1 = __float2half_rn(f1);
        g_w2hh[e] = __halves2half2(h0, h1);
        g_w2lh[e] = __floats2half2_rn(f0 - __half2float(h0), f1 - __half2float(h1));
    }
}

// ------- fused lf GEMM: A=lfea[256x768], virtual B = [sw1 | mw1] (N=768) -----
__global__ void gemm_sk2(const float* __restrict__ A, const float* __restrict__ sw1,
                         const float* __restrict__ mw1)
{
    __shared__ float As[64][17];
    __shared__ float Bs[16][65];
    const int bm = blockIdx.y * 64, bn = blockIdx.x * 64;
    const float* B; int Nn, coloff;
    if (bn < 256) { B = sw1; Nn = 256; coloff = bn; }
    else          { B = mw1; Nn = 512; coloff = bn - 256; }
    const int t = threadIdx.x;
    const int ty = t >> 4, tx = t & 15;
    float acc[4][4] = {};
    int kbeg = blockIdx.z * 128, kend = kbeg + 128;
    for (int k0 = kbeg; k0 < kend; k0 += 16) {
        #pragma unroll
        for (int i = 0; i < 4; i++) {
            int e = t + i * 256; int r = e >> 4, c = e & 15;
            As[r][c] = A[(size_t)(bm + r) * 768 + k0 + c];
        }
        #pragma unroll
        for (int i = 0; i < 4; i++) {
            int e = t + i * 256; int r = e >> 6, c = e & 63;
            Bs[r][c] = B[(size_t)(k0 + r) * Nn + coloff + c];
        }
        __syncthreads();
        #pragma unroll
        for (int kk = 0; kk < 16; kk++) {
            float a[4], b[4];
            #pragma unroll
            for (int i = 0; i < 4; i++) a[i] = As[ty * 4 + i][kk];
            #pragma unroll
            for (int j = 0; j < 4; j++) b[j] = Bs[kk][tx * 4 + j];
            #pragma unroll
            for (int i = 0; i < 4; i++)
                #pragma unroll
                for (int j = 0; j < 4; j++)
                    acc[i][j] += a[i] * b[j];
        }
        __syncthreads();
    }
    float* Cz = g_part + (size_t)blockIdx.z * 256 * 768;
    #pragma unroll
    for (int i = 0; i < 4; i++)
        #pragma unroll
        for (int j = 0; j < 4; j++)
            Cz[(size_t)(bm + ty * 4 + i) * 768 + bn + tx * 4 + j] = acc[i][j];
}

__global__ void k_red2()
{
    int e = blockIdx.x * 256 + threadIdx.x;   // < 256*768
    float s = 0.f;
    #pragma unroll
    for (int z = 0; z < 6; z++) s += g_part[(size_t)z * 196608 + e];
    int row = e / 768, col = e - row * 768;
    if (col < 256) g_lf_s1[row * 256 + col] = s;
    else           g_lf_m1[row * 512 + col - 256] = s;
}

// ------- mega: h1 on-the-fly -> fp16-split h2 GEMM -> n_pos -> KNN -> U/V ----
// block = 128 rows = 2 complete batches (p0, p0+1)
__global__ void __launch_bounds__(256)
tc3mega(const float* __restrict__ pos, const float* __restrict__ sw1,
        const float* __restrict__ sb1, const float* __restrict__ sb2,
        const float* __restrict__ sw3, const float* __restrict__ sb3,
        const float* __restrict__ cw1, const float* __restrict__ cb1)
{
    extern __shared__ unsigned sm3[];
    unsigned* Ah = sm3;                 // [128][20] half2
    unsigned* Al = Ah + 128 * 20;
    unsigned* Bh = Al + 128 * 20;       // [16][136] half2
    unsigned* Bl = Bh + 16 * 136;
    const int t = threadIdx.x;
    const int warp = t >> 5, lane = t & 31;
    const int g = lane >> 2, q = lane & 3;
    const int wm = warp >> 1, wn = warp & 1;
    const int bm = blockIdx.y * 128;
    const int p0 = bm >> 6;

    float c[2][8][4];
    #pragma unroll
    for (int i = 0; i < 2; i++)
        #pragma unroll
        for (int j = 0; j < 8; j++)
            #pragma unroll
            for (int e = 0; e < 4; e++) c[i][j][e] = 0.f;

    const int rA = t >> 3, c4A = (t & 7) * 4;
    float pxr[4], pyr[4], pzr[4];
    #pragma unroll
    for (int i = 0; i < 4; i++) {
        int row = bm + rA + i * 32;
        pxr[i] = pos[row * 3]; pyr[i] = pos[row * 3 + 1]; pzr[i] = pos[row * 3 + 2];
    }

    for (int k0 = 0; k0 < 256; k0 += 32) {
        int kk0 = k0 >> 1;
        // prefetch B hi/lo (pre-split half2) via cp.async
        #pragma unroll
        for (int i = 0; i < 2; i++) {
            int e = t + i * 256; int r = e >> 5, cu = (e & 31) * 4;
            cp16(&Bh[r * 136 + cu], (const unsigned*)g_w2hh + (size_t)(kk0 + r) * 128 + cu);
            cp16(&Bl[r * 136 + cu], (const unsigned*)g_w2lh + (size_t)(kk0 + r) * 128 + cu);
        }
        asm volatile("cp.async.commit_group;");
        // A fill: h1 on the fly, fp16 hi/lo split
        __half2* Ah2 = (__half2*)Ah;
        __half2* Al2 = (__half2*)Al;
        #pragma unroll
        for (int i = 0; i < 4; i++) {
            int r = rA + i * 32;
            int row = bm + r, cc = k0 + c4A;
            int p = row >> 6;
            float4 lf = *(const float4*)(g_lf_s1 + p * 256 + cc);
            float4 b1 = *(const float4*)(sb1 + cc);
            float4 w0 = *(const float4*)(sw1 + 768 * 256 + cc);
            float4 w1 = *(const float4*)(sw1 + 769 * 256 + cc);
            float4 w2 = *(const float4*)(sw1 + 770 * 256 + cc);
            float px = pxr[i], py = pyr[i], pz = pzr[i];
            float h0 = fmaxf(lf.x + b1.x + px * w0.x + py * w1.x + pz * w2.x, 0.f);
            float h1v = fmaxf(lf.y + b1.y + px * w0.y + py * w1.y + pz * w2.y, 0.f);
            float h2v = fmaxf(lf.z + b1.z + px * w0.z + py * w1.z + pz * w2.z, 0.f);
            float h3 = fmaxf(lf.w + b1.w + px * w0.w + py * w1.w + pz * w2.w, 0.f);
            __half2 hiA = __floats2half2_rn(h0, h1v);
            __half2 hiB = __floats2half2_rn(h2v, h3);
            float2 fA = __half22float2(hiA), fB = __half22float2(hiB);
            __half2 loA = __floats2half2_rn(h0 - fA.x, h1v - fA.y);
            __half2 loB = __floats2half2_rn(h2v - fB.x, h3 - fB.y);
            int idx = r * 20 + (c4A >> 1);
            Ah2[idx] = hiA; Ah2[idx + 1] = hiB;
            Al2[idx] = loA; Al2[idx + 1] = loB;
        }
        asm volatile("cp.async.wait_group 0;");
        __syncthreads();
        #pragma unroll
        for (int ks = 0; ks < 2; ks++) {
            int k8 = ks * 8;
            unsigned ah[2][4], al[2][4];
            #pragma unroll
            for (int mt = 0; mt < 2; mt++) {
                int r = wm * 32 + mt * 16 + g;
                ah[mt][0] = Ah[r * 20 + k8 + q];       al[mt][0] = Al[r * 20 + k8 + q];
                ah[mt][1] = Ah[(r + 8) * 20 + k8 + q]; al[mt][1] = Al[(r + 8) * 20 + k8 + q];
                ah[mt][2] = Ah[r * 20 + k8 + q + 4];   al[mt][2] = Al[r * 20 + k8 + q + 4];
                ah[mt][3] = Ah[(r + 8) * 20 + k8 + q + 4]; al[mt][3] = Al[(r + 8) * 20 + k8 + q + 4];
            }
            #pragma unroll
            for (int nt = 0; nt < 8; nt++) {
                int cn = wn * 64 + nt * 8 + g;
                unsigned bh[2], bl[2];
                bh[0] = Bh[(k8 + q) * 136 + cn];     bh[1] = Bh[(k8 + q + 4) * 136 + cn];
                bl[0] = Bl[(k8 + q) * 136 + cn];     bl[1] = Bl[(k8 + q + 4) * 136 + cn];
                #pragma unroll
                for (int mt = 0; mt < 2; mt++) {
                    MMA_F16(c[mt][nt], al[mt], bh);
                    MMA_F16(c[mt][nt], ah[mt], bl);
                    MMA_F16(c[mt][nt], ah[mt], bh);
                }
            }
        }
        __syncthreads();
    }

    // ---- phase 2: n_pos via smem reduction ----
    float* fsm = (float*)sm3;
    float* sred = fsm;                 // 128*8*3
    float* snp  = fsm + 3072;          // 128*3
    float* sx   = fsm + 3456;          // 256
    float* sy   = fsm + 3712;
    float* sz   = fsm + 3968;
    float* scw1 = fsm + 4224;          // 384
    float* scb1 = fsm + 4608;          // 64
    #pragma unroll
    for (int mt = 0; mt < 2; mt++) {
        #pragma unroll
        for (int half = 0; half < 2; half++) {
            int row_l = wm * 32 + mt * 16 + half * 8 + g;
            float p0v = 0.f, p1 = 0.f, p2 = 0.f;
            #pragma unroll
            for (int nt = 0; nt < 8; nt++) {
                int col = wn * 64 + nt * 8 + q * 2;
                float v0 = fmaxf(c[mt][nt][half * 2 + 0] + sb2[col], 0.f);
                float v1 = fmaxf(c[mt][nt][half * 2 + 1] + sb2[col + 1], 0.f);
                p0v += v0 * sw3[col * 3]     + v1 * sw3[(col + 1) * 3];
                p1 += v0 * sw3[col * 3 + 1] + v1 * sw3[(col + 1) * 3 + 1];
                p2 += v0 * sw3[col * 3 + 2] + v1 * sw3[(col + 1) * 3 + 2];
            }
            int slot = wn * 4 + q;
            sred[(row_l * 8 + slot) * 3 + 0] = p0v;
            sred[(row_l * 8 + slot) * 3 + 1] = p1;
            sred[(row_l * 8 + slot) * 3 + 2] = p2;
        }
    }
    __syncthreads();
    if (t < 128) {
        float a0 = 0.f, a1 = 0.f, a2 = 0.f;
        #pragma unroll
        for (int s = 0; s < 8; s++) {
            a0 += sred[(t * 8 + s) * 3 + 0];
            a1 += sred[(t * 8 + s) * 3 + 1];
            a2 += sred[(t * 8 + s) * 3 + 2];
        }
        int row = bm + t;
        float n0 = tanhf(fmaxf(a0 + sb3[0], 0.f)) + pos[row * 3 + 0];
        float n1 = tanhf(fmaxf(a1 + sb3[1], 0.f)) + pos[row * 3 + 1];
        float n2 = tanhf(fmaxf(a2 + sb3[2], 0.f)) + pos[row * 3 + 2];
        g_npos[row * 3 + 0] = n0; g_npos[row * 3 + 1] = n1; g_npos[row * 3 + 2] = n2;
        snp[t * 3 + 0] = n0; snp[t * 3 + 1] = n1; snp[t * 3 + 2] = n2;
    }
    __syncthreads();

    // ---- phase 3: KNN for the 2 batches + U/V ----
    int b = t >> 7, i = t & 127;
    int rowl = b * 64 + (i & 63);
    float x, y, z;
    if (i < 64) {
        int gr = bm + rowl;
        x = pos[gr * 3]; y = pos[gr * 3 + 1]; z = pos[gr * 3 + 2];
    } else {
        x = snp[rowl * 3]; y = snp[rowl * 3 + 1]; z = snp[rowl * 3 + 2];
    }
    sx[b * 128 + i] = x; sy[b * 128 + i] = y; sz[b * 128 + i] = z;
    for (int e = t; e < 448; e += 256) {
        if (e < 384) scw1[e] = cw1[e]; else scb1[e - 384] = cb1[e - 384];
    }
    __syncthreads();

    unsigned long long bk[9];
    #pragma unroll
    for (int qq = 0; qq < 9; qq++) bk[qq] = 0xFFFFFFFFFFFFFFFFull;
    const float* sxb = sx + b * 128; const float* syb = sy + b * 128; const float* szb = sz + b * 128;
    for (int j = 0; j < 128; j++) {
        float dx = x - sxb[j], dy = y - syb[j], dz = z - szb[j];
        float d2 = dx * dx + dy * dy + dz * dz;
        if (d2 <= R2C) {
            unsigned long long key = ((unsigned long long)__float_as_uint(d2) << 32) | (unsigned)j;
            if (key < bk[8]) {
                bk[8] = key;
                #pragma unroll
                for (int qq = 8; qq > 0; qq--)
                    if (bk[qq] < bk[qq - 1]) {
                        unsigned long long tmp = bk[qq]; bk[qq] = bk[qq - 1]; bk[qq - 1] = tmp;
                    }
            }
        }
    }
    int ptg = (p0 + b) * 128 + i;
    int bi0 = (int)(unsigned)bk[0];
    #pragma unroll
    for (int qq = 0; qq < 9; qq++)
        g_nbr[ptg * 9 + qq] = (bk[qq] != 0xFFFFFFFFFFFFFFFFull) ? (int)(unsigned)bk[qq] : bi0;

    for (int e = t; e < 256 * 64; e += 256) {
        int ptl = e >> 6, k = e & 63;
        float xx = sx[ptl], yy = sy[ptl], zz = sz[ptl];
        float wn0 = scw1[k],       wn1 = scw1[64 + k],  wn2 = scw1[128 + k];
        float wr0 = scw1[192 + k], wr1 = scw1[256 + k], wr2 = scw1[320 + k];
        int ptgl = (p0 + (ptl >> 7)) * 128 + (ptl & 127);
        g_U[(size_t)ptgl * 64 + k] = scb1[k] + xx * (wn0 + wr0) + yy * (wn1 + wr1) + zz * (wn2 + wr2);
        g_V[(size_t)ptgl * 64 + k] = xx * wr0 + yy * wr1 + zz * wr2;
    }
}

// ------------- edge MLP phase-B: fp16 mma, double-buffered per-qn A ----------
__global__ void __launch_bounds__(256)
k_edge2(const float* __restrict__ cb2)
{
    extern __shared__ unsigned esm[];
    unsigned* Bs = esm;                       // [32][136] half2
    unsigned* Abuf[2] = { esm + 32 * 136, esm + 32 * 136 + 64 * 36 };  // [64][36] half2
    const int t = threadIdx.x;
    const int warp = t >> 5, lane = t & 31;
    const int g = lane >> 2, q = lane & 3;
    const int wm = warp >> 1, wn = warp & 1;
    const int p = blockIdx.x >> 1, half = blockIdx.x & 1;
    const int ptbase = p * 128 + half * 64;

    for (int e = t; e < 32 * 128; e += 256)
        Bs[(e >> 7) * 136 + (e & 127)] = ((const unsigned*)g_wt3h)[e];

    const int r4 = t >> 2, q4 = t & 3;
    float vv[16];
    {
        const float4* Vr = (const float4*)(g_V + (size_t)(ptbase + r4) * 64 + q4 * 16);
        #pragma unroll
        for (int j4 = 0; j4 < 4; j4++) {
            float4 v = Vr[j4];
            vv[j4 * 4 + 0] = v.x; vv[j4 * 4 + 1] = v.y;
            vv[j4 * 4 + 2] = v.z; vv[j4 * 4 + 3] = v.w;
        }
    }
    // fill qn=0
    {
        int nb = g_nbr[(ptbase + r4) * 9 + 0];
        const float4* Ur = (const float4*)(g_U + (size_t)(p * 128 + nb) * 64 + q4 * 16);
        union { __half2 h[4]; uint4 u; } pk;
        #pragma unroll
        for (int j4 = 0; j4 < 2; j4++) {
            #pragma unroll
            for (int s = 0; s < 2; s++) {
                float4 u = Ur[j4 * 2 + s];
                pk.h[s * 2 + 0] = __floats2half2_rn(fmaxf(u.x - vv[(j4 * 2 + s) * 4 + 0], 0.f),
                                                    fmaxf(u.y - vv[(j4 * 2 + s) * 4 + 1], 0.f));
                pk.h[s * 2 + 1] = __floats2half2_rn(fmaxf(u.z - vv[(j4 * 2 + s) * 4 + 2], 0.f),
                                                    fmaxf(u.w - vv[(j4 * 2 + s) * 4 + 3], 0.f));
            }
            *(uint4*)&Abuf[0][r4 * 36 + q4 * 8 + j4 * 4] = pk.u;
        }
    }

    float mx[8][4];
    #pragma unroll 1
    for (int qn = 0; qn < 9; qn++) {
        __syncthreads();
        if (qn < 8) {
            int nb = g_nbr[(ptbase + r4) * 9 + qn + 1];
            const float4* Ur = (const float4*)(g_U + (size_t)(p * 128 + nb) * 64 + q4 * 16);
            unsigned* dst = Abuf[(qn + 1) & 1];
            union { __half2 h[4]; uint4 u; } pk;
            #pragma unroll
            for (int j4 = 0; j4 < 2; j4++) {
                #pragma unroll
                for (int s = 0; s < 2; s++) {
                    float4 u = Ur[j4 * 2 + s];
                    pk.h[s * 2 + 0] = __floats2half2_rn(fmaxf(u.x - vv[(j4 * 2 + s) * 4 + 0], 0.f),
                                                        fmaxf(u.y - vv[(j4 * 2 + s) * 4 + 1], 0.f));
                    pk.h[s * 2 + 1] = __floats2half2_rn(fmaxf(u.z - vv[(j4 * 2 + s) * 4 + 2], 0.f),
                                                        fmaxf(u.w - vv[(j4 * 2 + s) * 4 + 3], 0.f));
                }
                *(uint4*)&dst[r4 * 36 + q4 * 8 + j4 * 4] = pk.u;
            }
        }
        const unsigned* As = Abuf[qn & 1];
        float acc[8][4];
        #pragma unroll
        for (int nt = 0; nt < 8; nt++)
            #pragma unroll
            for (int e = 0; e < 4; e++) acc[nt][e] = 0.f;
        #pragma unroll
        for (int ks = 0; ks < 4; ks++) {
            int k8 = ks * 8;
            unsigned a[4];
            int rr = wm * 16 + g;
            a[0] = As[rr * 36 + k8 + q];
            a[1] = As[(rr + 8) * 36 + k8 + q];
            a[2] = As[rr * 36 + k8 + q + 4];
            a[3] = As[(rr + 8) * 36 + k8 + q + 4];
            #pragma unroll
            for (int nt = 0; nt < 8; nt++) {
                int cn = wn * 64 + nt * 8 + g;
                unsigned b[2];
                b[0] = Bs[(k8 + q) * 136 + cn];
                b[1] = Bs[(k8 + q + 4) * 136 + cn];
                MMA_F16(acc[nt], a, b);
            }
        }
        if (qn == 0) {
            #pragma unroll
            for (int nt = 0; nt < 8; nt++)
                #pragma unroll
                for (int e = 0; e < 4; e++) mx[nt][e] = acc[nt][e];
        } else {
            #pragma unroll
            for (int nt = 0; nt < 8; nt++)
                #pragma unroll
                for (int e = 0; e < 4; e++) mx[nt][e] = fmaxf(mx[nt][e], acc[nt][e]);
        }
    }

    #pragma unroll
    for (int hh = 0; hh < 2; hh++) {
        int pl = wm * 16 + g + hh * 8;
        size_t row = (half == 0) ? (size_t)(p * 64 + pl)
                                 : (size_t)(NP + p * 64 + pl);
        #pragma unroll
        for (int nt = 0; nt < 8; nt++) {
            int col = wn * 64 + nt * 8 + q * 2;
            float v0 = fmaxf(mx[nt][hh * 2 + 0] + cb2[col], 0.f);
            float v1 = fmaxf(mx[nt][hh * 2 + 1] + cb2[col + 1], 0.f);
            g_posfeah[row * 64 + (col >> 1)] = __floats2half2_rn(v0, v1);
        }
    }
}

// ------- pipelined fp16 GEMM, 128x256 tile (g1: K=128, Nn=512) ---------------
__global__ void __launch_bounds__(256)
gemm_g1h(const float* __restrict__ bias, const float* __restrict__ lfE)
{
    extern __shared__ float psm[];
    unsigned* Asm[2] = { (unsigned*)psm, (unsigned*)psm + 2560 };
    unsigned* Bsm[2] = { (unsigned*)psm + 5120, (unsigned*)psm + 5120 + 4224 };
    const int t = threadIdx.x;
    const int warp = t >> 5, lane = t & 31;
    const int g = lane >> 2, q = lane & 3;
    const int wm = warp >> 1, wn = warp & 1;
    const int bm = blockIdx.y * 128, bn = blockIdx.x * 256;
    const unsigned* Au = (const unsigned*)g_posfeah;   // [M2][64] half2
    const unsigned* Bu = (const unsigned*)g_wt1h;      // [64][512] half2

    float c[2][16][4];
    #pragma unroll
    for (int i = 0; i < 2; i++)
        #pragma unroll
        for (int j = 0; j < 16; j++)
            #pragma unroll
            for (int e = 0; e < 4; e++) c[i][j][e] = 0.f;

    {
        #pragma unroll
        for (int i = 0; i < 2; i++) {
            int e = t + i * 256; int r = e >> 2, cu = (e & 3) * 4;
            cp16(&Asm[0][r * 20 + cu], Au + (size_t)(bm + r) * 64 + cu);
        }
        #pragma unroll
        for (int i = 0; i < 4; i++) {
            int e = t + i * 256; int r = e >> 6, cu = (e & 63) * 4;
            cp16(&Bsm[0][r * 264 + cu], Bu + (size_t)r * 512 + bn + cu);
        }
        asm volatile("cp.async.commit_group;");
    }

    for (int tt = 0; tt < 4; tt++) {
        if (tt + 1 < 4) {
            int s = (tt + 1) & 1;
            int kk0 = (tt + 1) * 16;
            #pragma unroll
            for (int i = 0; i < 2; i++) {
                int e = t + i * 256; int r = e >> 2, cu = (e & 3) * 4;
                cp16(&Asm[s][r * 20 + cu], Au + (size_t)(bm + r) * 64 + kk0 + cu);
            }
            #pragma unroll
            for (int i = 0; i < 4; i++) {
                int e = t + i * 256; int r = e >> 6, cu = (e & 63) * 4;
                cp16(&Bsm[s][r * 264 + cu], Bu + (size_t)(kk0 + r) * 512 + bn + cu);
            }
            asm volatile("cp.async.commit_group;");
            asm volatile("cp.async.wait_group 1;");
        } else {
            asm volatile("cp.async.wait_group 0;");
        }
        __syncthreads();
        const unsigned* As = Asm[tt & 1];
        const unsigned* Bs = Bsm[tt & 1];
        #pragma unroll
        for (int ks = 0; ks < 2; ks++) {
            int k8 = ks * 8;
            unsigned a[2][4];
            #pragma unroll
            for (int mt = 0; mt < 2; mt++) {
                int r = wm * 32 + mt * 16 + g;
                a[mt][0] = As[r * 20 + k8 + q];
                a[mt][1] = As[(r + 8) * 20 + k8 + q];
                a[mt][2] = As[r * 20 + k8 + q + 4];
                a[mt][3] = As[(r + 8) * 20 + k8 + q + 4];
            }
            #pragma unroll
            for (int nt = 0; nt < 16; nt++) {
                int cn = wn * 128 + nt * 8 + g;
                unsigned b[2];
                b[0] = Bs[(k8 + q) * 264 + cn];
                b[1] = Bs[(k8 + q + 4) * 264 + cn];
                MMA_F16(c[0][nt], a[0], b);
                MMA_F16(c[1][nt], a[1], b);
            }
        }
        __syncthreads();
    }

    #pragma unroll
    for (int mt = 0; mt < 2; mt++) {
        #pragma unroll
        for (int half = 0; half < 2; half++) {
            int row = bm + wm * 32 + mt * 16 + half * 8 + g;
            int rowp = (row < NP) ? (row >> 6) : ((row - NP) >> 6);
            #pragma unroll
            for (int nt = 0; nt < 16; nt++) {
                int col = bn + wn * 128 + nt * 8 + q * 2;
                float v0 = c[mt][nt][half * 2 + 0] + bias[col] + lfE[(size_t)rowp * 512 + col];
                float v1 = c[mt][nt][half * 2 + 1] + bias[col + 1] + lfE[(size_t)rowp * 512 + col + 1];
                g_g1h[(size_t)row * 256 + (col >> 1)] =
                    __floats2half2_rn(fmaxf(v0, 0.f), fmaxf(v1, 0.f));
            }
        }
    }
}

// ------- g2 fp16 (128x256 tile, K=512) fused with rot + both outputs ---------
__global__ void __launch_bounds__(256)
gemm_g2rot(const float* __restrict__ mb2, const float* __restrict__ mw3,
           const float* __restrict__ mb3, const float* __restrict__ pos,
           float* __restrict__ out)
{
    extern __shared__ float psm[];
    unsigned* Asm[2] = { (unsigned*)psm, (unsigned*)psm + 2560 };
    unsigned* Bsm[2] = { (unsigned*)psm + 5120, (unsigned*)psm + 5120 + 4224 };
    const int t = threadIdx.x;
    const int warp = t >> 5, lane = t & 31;
    const int g = lane >> 2, q = lane & 3;
    const int wm = warp >> 1, wn = warp & 1;
    const int bm = blockIdx.x * 128;
    const unsigned* Au = (const unsigned*)g_g1h;    // [M2][256] half2
    const unsigned* Bu = (const unsigned*)g_wt2h;   // [256][256] half2

    float c[2][16][4];
    #pragma unroll
    for (int i = 0; i < 2; i++)
        #pragma unroll
        for (int j = 0; j < 16; j++)
            #pragma unroll
            for (int e = 0; e < 4; e++) c[i][j][e] = 0.f;

    {
        #pragma unroll
        for (int i = 0; i < 2; i++) {
            int e = t + i * 256; int r = e >> 2, cu = (e & 3) * 4;
            cp16(&Asm[0][r * 20 + cu], Au + (size_t)(bm + r) * 256 + cu);
        }
        #pragma unroll
        for (int i = 0; i < 4; i++) {
            int e = t + i * 256; int r = e >> 6, cu = (e & 63) * 4;
            cp16(&Bsm[0][r * 264 + cu], Bu + (size_t)r * 256 + cu);
        }
        asm volatile("cp.async.commit_group;");
    }

    for (int tt = 0; tt < 16; tt++) {
        if (tt + 1 < 16) {
            int s = (tt + 1) & 1;
            int kk0 = (tt + 1) * 16;
            #pragma unroll
            for (int i = 0; i < 2; i++) {
                int e = t + i * 256; int r = e >> 2, cu = (e & 3) * 4;
                cp16(&Asm[s][r * 20 + cu], Au + (size_t)(bm + r) * 256 + kk0 + cu);
            }
            #pragma unroll
            for (int i = 0; i < 4; i++) {
                int e = t + i * 256; int r = e >> 6, cu = (e & 63) * 4;
                cp16(&Bsm[s][r * 264 + cu], Bu + (size_t)(kk0 + r) * 256 + cu);
            }
            asm volatile("cp.async.commit_group;");
            asm volatile("cp.async.wait_group 1;");
        } else {
            asm volatile("cp.async.wait_group 0;");
        }
        __syncthreads();
        const unsigned* As = Asm[tt & 1];
        const unsigned* Bs = Bsm[tt & 1];
        #pragma unroll
        for (int ks = 0; ks < 2; ks++) {
            int k8 = ks * 8;
            unsigned a[2][4];
            #pragma unroll
            for (int mt = 0; mt < 2; mt++) {
                int r = wm * 32 + mt * 16 + g;
                a[mt][0] = As[r * 20 + k8 + q];
                a[mt][1] = As[(r + 8) * 20 + k8 + q];
                a[mt][2] = As[r * 20 + k8 + q + 4];
                a[mt][3] = As[(r + 8) * 20 + k8 + q + 4];
            }
            #pragma unroll
            for (int nt = 0; nt < 16; nt++) {
                int cn = wn * 128 + nt * 8 + g;
                unsigned b[2];
                b[0] = Bs[(k8 + q) * 264 + cn];
                b[1] = Bs[(k8 + q + 4) * 264 + cn];
                MMA_F16(c[0][nt], a[0], b);
                MMA_F16(c[1][nt], a[1], b);
            }
        }
        __syncthreads();
    }

    // epilogue: v = relu(c + mb2); partial dots with mw3; reduce 8 slots/row
    float* sred = psm;   // 128 rows * 8 slots * 9 = 9216 floats
    #pragma unroll
    for (int mt = 0; mt < 2; mt++) {
        #pragma unroll
        for (int half = 0; half < 2; half++) {
            int row_l = wm * 32 + mt * 16 + half * 8 + g;
            float p9[9];
            #pragma unroll
            for (int j = 0; j < 9; j++) p9[j] = 0.f;
            #pragma unroll
            for (int nt = 0; nt < 16; nt++) {
                int col = wn * 128 + nt * 8 + q * 2;
                float v0 = fmaxf(c[mt][nt][half * 2 + 0] + mb2[col], 0.f);
                float v1 = fmaxf(c[mt][nt][half * 2 + 1] + mb2[col + 1], 0.f);
                #pragma unroll
                for (int j = 0; j < 9; j++)
                    p9[j] += v0 * mw3[col * 9 + j] + v1 * mw3[(col + 1) * 9 + j];
            }
            int slot = wn * 4 + q;
            #pragma unroll
            for (int j = 0; j < 9; j++)
                sred[(row_l * 8 + slot) * 9 + j] = p9[j];
        }
    }
    __syncthreads();
    if (t < 128) {
        float r9[9];
        #pragma unroll
        for (int j = 0; j < 9; j++) {
            float s = 0.f;
            #pragma unroll
            for (int sl = 0; sl < 8; sl++) s += sred[(t * 8 + sl) * 9 + j];
            r9[j] = fmaxf(s + mb3[j], 0.f);
        }
        int n = bm + t;
        float* oc = out + (size_t)16 * M2 * 3 + (size_t)n * 9;
        #pragma unroll
        for (int i = 0; i < 3; i++)
            #pragma unroll
            for (int j = 0; j < 3; j++)
                oc[i * 3 + j] = r9[0 + i] * r9[0 + j] + r9[3 + i] * r9[3 + j] + r9[6 + i] * r9[6 + j];
        const float XV[4] = {-0.2f, -0.066666666666666666f, 0.066666666666666666f, 0.2f};
        #pragma unroll
        for (int t4 = 0; t4 < 16; t4++) {
            float nx = XV[t4 & 3], ny = XV[t4 >> 2];
            int m = (n * 16 + t4) & (M2 - 1);
            float cx, cy, cz;
            if (m < NP) { cx = pos[m * 3]; cy = pos[m * 3 + 1]; cz = pos[m * 3 + 2]; }
            else { int mm = m - NP; cx = g_npos[mm * 3]; cy = g_npos[mm * 3 + 1]; cz = g_npos[mm * 3 + 2]; }
            float* op = out + (size_t)(n * 16 + t4) * 3;
            op[0] = r9[0] * nx + r9[1] * ny + cx;
            op[1] = r9[3] * nx + r9[4] * ny + cy;
            op[2] = r9[6] * nx + r9[7] * ny + cz;
        }
    }
}

// ---------------- host launcher ----------------------------------------------
extern "C" void kernel_launch(void* const* d_in, const int* in_sizes, int n_in,
                              void* d_out, int out_size)
{
    const float* pos = (const float*)d_in[1];
    const float* lfea = (const float*)d_in[4];
    const float* sw1 = (const float*)d_in[5];
    const float* sb1 = (const float*)d_in[6];
    const float* sw2 = (const float*)d_in[7];
    const float* sb2 = (const float*)d_in[8];
    const float* sw3 = (const float*)d_in[9];
    const float* sb3 = (const float*)d_in[10];
    const float* cw1 = (const float*)d_in[11];
    const float* cb1 = (const float*)d_in[12];
    const float* cw2 = (const float*)d_in[13];
    const float* cb2 = (const float*)d_in[14];
    const float* mw1 = (const float*)d_in[15];
    const float* mb1 = (const float*)d_in[16];
    const float* mw2 = (const float*)d_in[17];
    const float* mb2 = (const float*)d_in[18];
    const float* mw3 = (const float*)d_in[19];
    const float* mb3 = (const float*)d_in[20];
    float* out = (float*)d_out;

    float* p_lf_m1;
    cudaGetSymbolAddress((void**)&p_lf_m1, g_lf_m1);

    cudaFuncSetAttribute(gemm_g1h, cudaFuncAttributeMaxDynamicSharedMemorySize, 54272);
    cudaFuncSetAttribute(gemm_g2rot, cudaFuncAttributeMaxDynamicSharedMemorySize, 54272);

    // 1. fp16 K-pair packing of weights (+ sw2 hi/lo split)
    k_cvt_all<<<464, 256>>>(mw1 + 768 * 512, mw2, cw2, sw2);
    // 2-3. fused lf GEMM (virtual N=768) split-K + reduce
    gemm_sk2<<<dim3(12, 4, 6), 256>>>(lfea, sw1, mw1);
    k_red2<<<768, 256>>>();
    // 4. mega: h1 -> h2 (fp16 hi/lo) -> n_pos -> KNN -> U/V
    tc3mega<<<dim3(1, 128), 256, 37888>>>(pos, sw1, sb1, sb2, sw3, sb3, cw1, cb1);
    // 5. edge MLP phase-B (fp16 mma, double-buffered)
    k_edge2<<<512, 256, 35840>>>(cb2);
    // 6. g1 = relu(pos_fea @ mw1' + lf_m1[p] + mb1) — fp16 mma
    gemm_g1h<<<dim3(2, 256), 256, 54272>>>(mb1, p_lf_m1);
    // 7. g2 + rot + outputs, all fused — fp16 mma
    gemm_g2rot<<<256, 256, 54272>>>(mb2, mw3, mb3, pos, out);
}

// round 14
// speedup vs baseline: 7.9981x; 1.0220x over previous
#include <cuda_runtime.h>
#include <cuda_fp16.h>
#include <math.h>

#define PB  256
#define PTc 64
#define NP  16384      // N = P*PT
#define M2  32768      // 2N
#define R2C 0.09f

// ---------------- scratch (static device globals; no allocations) ------------
__device__ float g_lf_s1[PB * 256];          // includes +sb1 (folded in k_red2)
__device__ float g_lf_m1[PB * 512];
__device__ float g_npos[NP * 3];
__device__ int   g_nbr[M2 * 9];
__device__ float g_U[(size_t)M2 * 64];
__device__ float g_V[(size_t)M2 * 64];
__device__ __half2 g_posfeah[(size_t)M2 * 64];   // pos_fea, K-pair packed
__device__ __half2 g_g1h[(size_t)M2 * 256];      // g1, K-pair packed
__device__ float g_part[6 * 256 * 768];
__device__ __half2 g_wt1h[64 * 512];    // mw1[768:] K-pair packed fp16
__device__ __half2 g_wt2h[256 * 256];   // mw2 K-pair packed fp16
__device__ __half2 g_wt3h[32 * 128];    // cw2 K-pair packed fp16
__device__ __half2 g_w2hh[128 * 128];   // sw2 hi, K-pair packed
__device__ __half2 g_w2lh[128 * 128];   // sw2 lo residual, K-pair packed

#define MMA_F16(cc, aa, bb) \
    asm volatile("mma.sync.aligned.m16n8k16.row.col.f32.f16.f16.f32 " \
        "{%0,%1,%2,%3},{%4,%5,%6,%7},{%8,%9},{%0,%1,%2,%3};" \
        : "+f"(cc[0]), "+f"(cc[1]), "+f"(cc[2]), "+f"(cc[3]) \
        : "r"(aa[0]), "r"(aa[1]), "r"(aa[2]), "r"(aa[3]), "r"(bb[0]), "r"(bb[1]))

__device__ __forceinline__ void cp16(void* dst, const void* src) {
    unsigned d = (unsigned)__cvta_generic_to_shared(dst);
    asm volatile("cp.async.cg.shared.global [%0], [%1], 16;" :: "r"(d), "l"(src));
}

__device__ __forceinline__ unsigned h2u(__half2 h) {
    union { __half2 h; unsigned u; } v; v.h = h; return v.u;
}

// ------- fused lf GEMM: A=lfea[256x768], virtual B = [sw1 | mw1] (N=768) -----
__global__ void gemm_sk2(const float* __restrict__ A, const float* __restrict__ sw1,
                         const float* __restrict__ mw1)
{
    __shared__ float As[64][17];
    __shared__ float Bs[16][65];
    const int bm = blockIdx.y * 64, bn = blockIdx.x * 64;
    const float* B; int Nn, coloff;
    if (bn < 256) { B = sw1; Nn = 256; coloff = bn; }
    else          { B = mw1; Nn = 512; coloff = bn - 256; }
    const int t = threadIdx.x;
    const int ty = t >> 4, tx = t & 15;
    float acc[4][4] = {};
    int kbeg = blockIdx.z * 128, kend = kbeg + 128;
    for (int k0 = kbeg; k0 < kend; k0 += 16) {
        #pragma unroll
        for (int i = 0; i < 4; i++) {
            int e = t + i * 256; int r = e >> 4, c = e & 15;
            As[r][c] = A[(size_t)(bm + r) * 768 + k0 + c];
        }
        #pragma unroll
        for (int i = 0; i < 4; i++) {
            int e = t + i * 256; int r = e >> 6, c = e & 63;
            Bs[r][c] = B[(size_t)(k0 + r) * Nn + coloff + c];
        }
        __syncthreads();
        #pragma unroll
        for (int kk = 0; kk < 16; kk++) {
            float a[4], b[4];
            #pragma unroll
            for (int i = 0; i < 4; i++) a[i] = As[ty * 4 + i][kk];
            #pragma unroll
            for (int j = 0; j < 4; j++) b[j] = Bs[kk][tx * 4 + j];
            #pragma unroll
            for (int i = 0; i < 4; i++)
                #pragma unroll
                for (int j = 0; j < 4; j++)
                    acc[i][j] += a[i] * b[j];
        }
        __syncthreads();
    }
    float* Cz = g_part + (size_t)blockIdx.z * 256 * 768;
    #pragma unroll
    for (int i = 0; i < 4; i++)
        #pragma unroll
        for (int j = 0; j < 4; j++)
            Cz[(size_t)(bm + ty * 4 + i) * 768 + bn + tx * 4 + j] = acc[i][j];
}

// ------- reduce split-K + (folded) weight packing + sb1 fold -----------------
__global__ void k_red2(const float* __restrict__ sb1, const float* __restrict__ w1,
                       const float* __restrict__ w2, const float* __restrict__ w3,
                       const float* __restrict__ sw2)
{
    int e = blockIdx.x * 256 + threadIdx.x;   // < 196608
    float s = 0.f;
    #pragma unroll
    for (int z = 0; z < 6; z++) s += g_part[(size_t)z * 196608 + e];
    int row = e / 768, col = e - row * 768;
    if (col < 256) g_lf_s1[row * 256 + col] = s + sb1[col];
    else           g_lf_m1[row * 512 + col - 256] = s;

    // folded weight packing (same thread-id space)
    int i = e;
    if (i < 32768) {                       // wt1h: [64 kk][512 n]
        int kk = i >> 9, n = i & 511;
        g_wt1h[i] = __floats2half2_rn(w1[(2 * kk) * 512 + n], w1[(2 * kk + 1) * 512 + n]);
    } else if (i < 98304) {                // wt2h: [256 kk][256 n]
        int e2 = i - 32768; int kk = e2 >> 8, n = e2 & 255;
        g_wt2h[e2] = __floats2half2_rn(w2[(2 * kk) * 256 + n], w2[(2 * kk + 1) * 256 + n]);
    } else if (i < 102400) {               // wt3h: [32 kk][128 n]
        int e2 = i - 98304; int kk = e2 >> 7, n = e2 & 127;
        g_wt3h[e2] = __floats2half2_rn(w3[(2 * kk) * 128 + n], w3[(2 * kk + 1) * 128 + n]);
    } else if (i < 118784) {               // sw2 hi/lo: [128 kk][128 n]
        int e2 = i - 102400; int kk = e2 >> 7, n = e2 & 127;
        float f0 = sw2[(2 * kk) * 128 + n], f1 = sw2[(2 * kk + 1) * 128 + n];
        __half h0 = __float2half_rn(f0), h1 = __float2half_rn(f1);
        g_w2hh[e2] = __halves2half2(h0, h1);
        g_w2lh[e2] = __floats2half2_rn(f0 - __half2float(h0), f1 - __half2float(h1));
    }
}

// ------- mega: h1 on-the-fly -> fp16-split h2 GEMM -> n_pos -> KNN -> U/V ----
// block = 128 rows = 2 complete batches; cp.async staged A-inputs + B, 2-deep
__global__ void __launch_bounds__(256)
tc3mega(const float* __restrict__ pos, const float* __restrict__ sw1,
        const float* __restrict__ sb2, const float* __restrict__ sw3,
        const float* __restrict__ sb3, const float* __restrict__ cw1,
        const float* __restrict__ cb1)
{
    extern __shared__ unsigned sm3[];
    unsigned* Ah = sm3;                        // [128][20] half2
    unsigned* Al = Ah + 2560;                  // [128][20]
    unsigned* BhB[2] = { Al + 2560, Al + 2560 + 2176 };          // each [16][136]
    unsigned* BlB[2] = { Al + 2560 + 4352, Al + 2560 + 6528 };   // each [16][136]
    float* stageB = (float*)(Al + 2560 + 8704);                  // 2 x 160 floats
    const int t = threadIdx.x;
    const int warp = t >> 5, lane = t & 31;
    const int g = lane >> 2, q = lane & 3;
    const int wm = warp >> 1, wn = warp & 1;
    const int bm = blockIdx.y * 128;
    const int p0 = bm >> 6;

    float c[2][8][4];
    #pragma unroll
    for (int i = 0; i < 2; i++)
        #pragma unroll
        for (int j = 0; j < 8; j++)
            #pragma unroll
            for (int e = 0; e < 4; e++) c[i][j][e] = 0.f;

    const int rA = t >> 3, c4A = (t & 7) * 4;
    float pxr[4], pyr[4], pzr[4];
    #pragma unroll
    for (int i = 0; i < 4; i++) {
        int row = bm + rA + i * 32;
        pxr[i] = pos[row * 3]; pyr[i] = pos[row * 3 + 1]; pzr[i] = pos[row * 3 + 2];
    }

    // cp.async issue for tile tt (k0 = 32*tt)
    auto issue = [&](int tt) {
        int s = tt & 1;
        int kk0 = tt * 16, k0 = tt * 32;
        #pragma unroll
        for (int i = 0; i < 2; i++) {
            int e = t + i * 256; int r = e >> 5, cu = (e & 31) * 4;
            cp16(&BhB[s][r * 136 + cu], (const unsigned*)g_w2hh + (size_t)(kk0 + r) * 128 + cu);
            cp16(&BlB[s][r * 136 + cu], (const unsigned*)g_w2lh + (size_t)(kk0 + r) * 128 + cu);
        }
        if (t < 40) {
            int seg = t >> 3, off = (t & 7) * 4;
            const float* src;
            if (seg == 0)      src = g_lf_s1 + p0 * 256 + k0 + off;
            else if (seg == 1) src = g_lf_s1 + (p0 + 1) * 256 + k0 + off;
            else               src = sw1 + (size_t)(768 + seg - 2) * 256 + k0 + off;
            cp16(&stageB[s * 160 + seg * 32 + off], src);
        }
    };

    issue(0);
    asm volatile("cp.async.commit_group;");

    for (int tt = 0; tt < 8; tt++) {
        asm volatile("cp.async.wait_group 0;");
        __syncthreads();        // tile tt staged data visible; prev mma done
        if (tt + 1 < 8) {
            issue(tt + 1);      // overlaps fillA + mma below
            asm volatile("cp.async.commit_group;");
        }
        // fillA from staged inputs (all smem reads)
        {
            const float* st = stageB + (tt & 1) * 160;
            float4 w0 = *(const float4*)(st + 64 + c4A);
            float4 w1 = *(const float4*)(st + 96 + c4A);
            float4 w2 = *(const float4*)(st + 128 + c4A);
            float4 lf0 = *(const float4*)(st + c4A);
            float4 lf1 = *(const float4*)(st + 32 + c4A);
            #pragma unroll
            for (int i = 0; i < 4; i++) {
                int r = rA + i * 32;
                float4 lf = (i < 2) ? lf0 : lf1;
                float px = pxr[i], py = pyr[i], pz = pzr[i];
                float h0 = fmaxf(lf.x + px * w0.x + py * w1.x + pz * w2.x, 0.f);
                float h1v = fmaxf(lf.y + px * w0.y + py * w1.y + pz * w2.y, 0.f);
                float h2v = fmaxf(lf.z + px * w0.z + py * w1.z + pz * w2.z, 0.f);
                float h3 = fmaxf(lf.w + px * w0.w + py * w1.w + pz * w2.w, 0.f);
                __half2 hiA = __floats2half2_rn(h0, h1v);
                __half2 hiB = __floats2half2_rn(h2v, h3);
                float2 fA = __half22float2(hiA), fB = __half22float2(hiB);
                __half2 loA = __floats2half2_rn(h0 - fA.x, h1v - fA.y);
                __half2 loB = __floats2half2_rn(h2v - fB.x, h3 - fB.y);
                int idx = r * 20 + (c4A >> 1);
                *(uint2*)&Ah[idx] = make_uint2(h2u(hiA), h2u(hiB));
                *(uint2*)&Al[idx] = make_uint2(h2u(loA), h2u(loB));
            }
        }
        __syncthreads();
        const unsigned* Bh = BhB[tt & 1];
        const unsigned* Bl = BlB[tt & 1];
        #pragma unroll
        for (int ks = 0; ks < 2; ks++) {
            int k8 = ks * 8;
            unsigned ah[2][4], al[2][4];
            #pragma unroll
            for (int mt = 0; mt < 2; mt++) {
                int r = wm * 32 + mt * 16 + g;
                ah[mt][0] = Ah[r * 20 + k8 + q];       al[mt][0] = Al[r * 20 + k8 + q];
                ah[mt][1] = Ah[(r + 8) * 20 + k8 + q]; al[mt][1] = Al[(r + 8) * 20 + k8 + q];
                ah[mt][2] = Ah[r * 20 + k8 + q + 4];   al[mt][2] = Al[r * 20 + k8 + q + 4];
                ah[mt][3] = Ah[(r + 8) * 20 + k8 + q + 4]; al[mt][3] = Al[(r + 8) * 20 + k8 + q + 4];
            }
            #pragma unroll
            for (int nt = 0; nt < 8; nt++) {
                int cn = wn * 64 + nt * 8 + g;
                unsigned bh[2], bl[2];
                bh[0] = Bh[(k8 + q) * 136 + cn];     bh[1] = Bh[(k8 + q + 4) * 136 + cn];
                bl[0] = Bl[(k8 + q) * 136 + cn];     bl[1] = Bl[(k8 + q + 4) * 136 + cn];
                #pragma unroll
                for (int mt = 0; mt < 2; mt++) {
                    MMA_F16(c[mt][nt], al[mt], bh);
                    MMA_F16(c[mt][nt], ah[mt], bl);
                    MMA_F16(c[mt][nt], ah[mt], bh);
                }
            }
        }
    }
    __syncthreads();   // all mma done before smem reuse

    // ---- phase 2: n_pos via smem reduction ----
    float* fsm = (float*)sm3;
    float* sred = fsm;                 // 128*8*3
    float* snp  = fsm + 3072;          // 128*3
    float* sx   = fsm + 3456;          // 256
    float* sy   = fsm + 3712;
    float* sz   = fsm + 3968;
    float* scw1 = fsm + 4224;          // 384
    float* scb1 = fsm + 4608;          // 64
    #pragma unroll
    for (int mt = 0; mt < 2; mt++) {
        #pragma unroll
        for (int half = 0; half < 2; half++) {
            int row_l = wm * 32 + mt * 16 + half * 8 + g;
            float p0v = 0.f, p1 = 0.f, p2 = 0.f;
            #pragma unroll
            for (int nt = 0; nt < 8; nt++) {
                int col = wn * 64 + nt * 8 + q * 2;
                float v0 = fmaxf(c[mt][nt][half * 2 + 0] + sb2[col], 0.f);
                float v1 = fmaxf(c[mt][nt][half * 2 + 1] + sb2[col + 1], 0.f);
                p0v += v0 * sw3[col * 3]     + v1 * sw3[(col + 1) * 3];
                p1 += v0 * sw3[col * 3 + 1] + v1 * sw3[(col + 1) * 3 + 1];
                p2 += v0 * sw3[col * 3 + 2] + v1 * sw3[(col + 1) * 3 + 2];
            }
            int slot = wn * 4 + q;
            sred[(row_l * 8 + slot) * 3 + 0] = p0v;
            sred[(row_l * 8 + slot) * 3 + 1] = p1;
            sred[(row_l * 8 + slot) * 3 + 2] = p2;
        }
    }
    __syncthreads();
    if (t < 128) {
        float a0 = 0.f, a1 = 0.f, a2 = 0.f;
        #pragma unroll
        for (int s = 0; s < 8; s++) {
            a0 += sred[(t * 8 + s) * 3 + 0];
            a1 += sred[(t * 8 + s) * 3 + 1];
            a2 += sred[(t * 8 + s) * 3 + 2];
        }
        int row = bm + t;
        float n0 = tanhf(fmaxf(a0 + sb3[0], 0.f)) + pos[row * 3 + 0];
        float n1 = tanhf(fmaxf(a1 + sb3[1], 0.f)) + pos[row * 3 + 1];
        float n2 = tanhf(fmaxf(a2 + sb3[2], 0.f)) + pos[row * 3 + 2];
        g_npos[row * 3 + 0] = n0; g_npos[row * 3 + 1] = n1; g_npos[row * 3 + 2] = n2;
        snp[t * 3 + 0] = n0; snp[t * 3 + 1] = n1; snp[t * 3 + 2] = n2;
    }
    __syncthreads();

    // ---- phase 3: KNN for the 2 batches + U/V ----
    int b = t >> 7, i = t & 127;
    int rowl = b * 64 + (i & 63);
    float x, y, z;
    if (i < 64) {
        int gr = bm + rowl;
        x = pos[gr * 3]; y = pos[gr * 3 + 1]; z = pos[gr * 3 + 2];
    } else {
        x = snp[rowl * 3]; y = snp[rowl * 3 + 1]; z = snp[rowl * 3 + 2];
    }
    sx[b * 128 + i] = x; sy[b * 128 + i] = y; sz[b * 128 + i] = z;
    for (int e = t; e < 448; e += 256) {
        if (e < 384) scw1[e] = cw1[e]; else scb1[e - 384] = cb1[e - 384];
    }
    __syncthreads();

    unsigned long long bk[9];
    #pragma unroll
    for (int qq = 0; qq < 9; qq++) bk[qq] = 0xFFFFFFFFFFFFFFFFull;
    const float* sxb = sx + b * 128; const float* syb = sy + b * 128; const float* szb = sz + b * 128;
    for (int j = 0; j < 128; j++) {
        float dx = x - sxb[j], dy = y - syb[j], dz = z - szb[j];
        float d2 = dx * dx + dy * dy + dz * dz;
        if (d2 <= R2C) {
            unsigned long long key = ((unsigned long long)__float_as_uint(d2) << 32) | (unsigned)j;
            if (key < bk[8]) {
                bk[8] = key;
                #pragma unroll
                for (int qq = 8; qq > 0; qq--)
                    if (bk[qq] < bk[qq - 1]) {
                        unsigned long long tmp = bk[qq]; bk[qq] = bk[qq - 1]; bk[qq - 1] = tmp;
                    }
            }
        }
    }
    int ptg = (p0 + b) * 128 + i;
    int bi0 = (int)(unsigned)bk[0];
    #pragma unroll
    for (int qq = 0; qq < 9; qq++)
        g_nbr[ptg * 9 + qq] = (bk[qq] != 0xFFFFFFFFFFFFFFFFull) ? (int)(unsigned)bk[qq] : bi0;

    for (int e = t; e < 256 * 64; e += 256) {
        int ptl = e >> 6, k = e & 63;
        float xx = sx[ptl], yy = sy[ptl], zz = sz[ptl];
        float wn0 = scw1[k],       wn1 = scw1[64 + k],  wn2 = scw1[128 + k];
        float wr0 = scw1[192 + k], wr1 = scw1[256 + k], wr2 = scw1[320 + k];
        int ptgl = (p0 + (ptl >> 7)) * 128 + (ptl & 127);
        g_U[(size_t)ptgl * 64 + k] = scb1[k] + xx * (wn0 + wr0) + yy * (wn1 + wr1) + zz * (wn2 + wr2);
        g_V[(size_t)ptgl * 64 + k] = xx * wr0 + yy * wr1 + zz * wr2;
    }
}

// ------------- edge MLP phase-B: fp16 mma, double-buffered per-qn A ----------
__global__ void __launch_bounds__(256)
k_edge2(const float* __restrict__ cb2)
{
    extern __shared__ unsigned esm[];
    unsigned* Bs = esm;                       // [32][136] half2
    unsigned* Abuf[2] = { esm + 32 * 136, esm + 32 * 136 + 64 * 36 };  // [64][36] half2
    const int t = threadIdx.x;
    const int warp = t >> 5, lane = t & 31;
    const int g = lane >> 2, q = lane & 3;
    const int wm = warp >> 1, wn = warp & 1;
    const int p = blockIdx.x >> 1, half = blockIdx.x & 1;
    const int ptbase = p * 128 + half * 64;

    for (int e = t; e < 32 * 128; e += 256)
        Bs[(e >> 7) * 136 + (e & 127)] = ((const unsigned*)g_wt3h)[e];

    const int r4 = t >> 2, q4 = t & 3;
    float vv[16];
    {
        const float4* Vr = (const float4*)(g_V + (size_t)(ptbase + r4) * 64 + q4 * 16);
        #pragma unroll
        for (int j4 = 0; j4 < 4; j4++) {
            float4 v = Vr[j4];
            vv[j4 * 4 + 0] = v.x; vv[j4 * 4 + 1] = v.y;
            vv[j4 * 4 + 2] = v.z; vv[j4 * 4 + 3] = v.w;
        }
    }
    // fill qn=0
    {
        int nb = g_nbr[(ptbase + r4) * 9 + 0];
        const float4* Ur = (const float4*)(g_U + (size_t)(p * 128 + nb) * 64 + q4 * 16);
        union { __half2 h[4]; uint4 u; } pk;
        #pragma unroll
        for (int j4 = 0; j4 < 2; j4++) {
            #pragma unroll
            for (int s = 0; s < 2; s++) {
                float4 u = Ur[j4 * 2 + s];
                pk.h[s * 2 + 0] = __floats2half2_rn(fmaxf(u.x - vv[(j4 * 2 + s) * 4 + 0], 0.f),
                                                    fmaxf(u.y - vv[(j4 * 2 + s) * 4 + 1], 0.f));
                pk.h[s * 2 + 1] = __floats2half2_rn(fmaxf(u.z - vv[(j4 * 2 + s) * 4 + 2], 0.f),
                                                    fmaxf(u.w - vv[(j4 * 2 + s) * 4 + 3], 0.f));
            }
            *(uint4*)&Abuf[0][r4 * 36 + q4 * 8 + j4 * 4] = pk.u;
        }
    }

    float mx[8][4];
    #pragma unroll 1
    for (int qn = 0; qn < 9; qn++) {
        __syncthreads();
        if (qn < 8) {
            int nb = g_nbr[(ptbase + r4) * 9 + qn + 1];
            const float4* Ur = (const float4*)(g_U + (size_t)(p * 128 + nb) * 64 + q4 * 16);
            unsigned* dst = Abuf[(qn + 1) & 1];
            union { __half2 h[4]; uint4 u; } pk;
            #pragma unroll
            for (int j4 = 0; j4 < 2; j4++) {
                #pragma unroll
                for (int s = 0; s < 2; s++) {
                    float4 u = Ur[j4 * 2 + s];
                    pk.h[s * 2 + 0] = __floats2half2_rn(fmaxf(u.x - vv[(j4 * 2 + s) * 4 + 0], 0.f),
                                                        fmaxf(u.y - vv[(j4 * 2 + s) * 4 + 1], 0.f));
                    pk.h[s * 2 + 1] = __floats2half2_rn(fmaxf(u.z - vv[(j4 * 2 + s) * 4 + 2], 0.f),
                                                        fmaxf(u.w - vv[(j4 * 2 + s) * 4 + 3], 0.f));
                }
                *(uint4*)&dst[r4 * 36 + q4 * 8 + j4 * 4] = pk.u;
            }
        }
        const unsigned* As = Abuf[qn & 1];
        float acc[8][4];
        #pragma unroll
        for (int nt = 0; nt < 8; nt++)
            #pragma unroll
            for (int e = 0; e < 4; e++) acc[nt][e] = 0.f;
        #pragma unroll
        for (int ks = 0; ks < 4; ks++) {
            int k8 = ks * 8;
            unsigned a[4];
            int rr = wm * 16 + g;
            a[0] = As[rr * 36 + k8 + q];
            a[1] = As[(rr + 8) * 36 + k8 + q];
            a[2] = As[rr * 36 + k8 + q + 4];
            a[3] = As[(rr + 8) * 36 + k8 + q + 4];
            #pragma unroll
            for (int nt = 0; nt < 8; nt++) {
                int cn = wn * 64 + nt * 8 + g;
                unsigned b[2];
                b[0] = Bs[(k8 + q) * 136 + cn];
                b[1] = Bs[(k8 + q + 4) * 136 + cn];
                MMA_F16(acc[nt], a, b);
            }
        }
        if (qn == 0) {
            #pragma unroll
            for (int nt = 0; nt < 8; nt++)
                #pragma unroll
                for (int e = 0; e < 4; e++) mx[nt][e] = acc[nt][e];
        } else {
            #pragma unroll
            for (int nt = 0; nt < 8; nt++)
                #pragma unroll
                for (int e = 0; e < 4; e++) mx[nt][e] = fmaxf(mx[nt][e], acc[nt][e]);
        }
    }

    #pragma unroll
    for (int hh = 0; hh < 2; hh++) {
        int pl = wm * 16 + g + hh * 8;
        size_t row = (half == 0) ? (size_t)(p * 64 + pl)
                                 : (size_t)(NP + p * 64 + pl);
        #pragma unroll
        for (int nt = 0; nt < 8; nt++) {
            int col = wn * 64 + nt * 8 + q * 2;
            float v0 = fmaxf(mx[nt][hh * 2 + 0] + cb2[col], 0.f);
            float v1 = fmaxf(mx[nt][hh * 2 + 1] + cb2[col + 1], 0.f);
            g_posfeah[row * 64 + (col >> 1)] = __floats2half2_rn(v0, v1);
        }
    }
}

// ------- pipelined fp16 GEMM, 128x256 tile (g1: K=128, Nn=512) ---------------
__global__ void __launch_bounds__(256)
gemm_g1h(const float* __restrict__ bias, const float* __restrict__ lfE)
{
    extern __shared__ float psm[];
    unsigned* Asm[2] = { (unsigned*)psm, (unsigned*)psm + 2560 };
    unsigned* Bsm[2] = { (unsigned*)psm + 5120, (unsigned*)psm + 5120 + 4224 };
    const int t = threadIdx.x;
    const int warp = t >> 5, lane = t & 31;
    const int g = lane >> 2, q = lane & 3;
    const int wm = warp >> 1, wn = warp & 1;
    const int bm = blockIdx.y * 128, bn = blockIdx.x * 256;
    const unsigned* Au = (const unsigned*)g_posfeah;   // [M2][64] half2
    const unsigned* Bu = (const unsigned*)g_wt1h;      // [64][512] half2

    float c[2][16][4];
    #pragma unroll
    for (int i = 0; i < 2; i++)
        #pragma unroll
        for (int j = 0; j < 16; j++)
            #pragma unroll
            for (int e = 0; e < 4; e++) c[i][j][e] = 0.f;

    {
        #pragma unroll
        for (int i = 0; i < 2; i++) {
            int e = t + i * 256; int r = e >> 2, cu = (e & 3) * 4;
            cp16(&Asm[0][r * 20 + cu], Au + (size_t)(bm + r) * 64 + cu);
        }
        #pragma unroll
        for (int i = 0; i < 4; i++) {
            int e = t + i * 256; int r = e >> 6, cu = (e & 63) * 4;
            cp16(&Bsm[0][r * 264 + cu], Bu + (size_t)r * 512 + bn + cu);
        }
        asm volatile("cp.async.commit_group;");
    }

    for (int tt = 0; tt < 4; tt++) {
        if (tt + 1 < 4) {
            int s = (tt + 1) & 1;
            int kk0 = (tt + 1) * 16;
            #pragma unroll
            for (int i = 0; i < 2; i++) {
                int e = t + i * 256; int r = e >> 2, cu = (e & 3) * 4;
                cp16(&Asm[s][r * 20 + cu], Au + (size_t)(bm + r) * 64 + kk0 + cu);
            }
            #pragma unroll
            for (int i = 0; i < 4; i++) {
                int e = t + i * 256; int r = e >> 6, cu = (e & 63) * 4;
                cp16(&Bsm[s][r * 264 + cu], Bu + (size_t)(kk0 + r) * 512 + bn + cu);
            }
            asm volatile("cp.async.commit_group;");
            asm volatile("cp.async.wait_group 1;");
        } else {
            asm volatile("cp.async.wait_group 0;");
        }
        __syncthreads();
        const unsigned* As = Asm[tt & 1];
        const unsigned* Bs = Bsm[tt & 1];
        #pragma unroll
        for (int ks = 0; ks < 2; ks++) {
            int k8 = ks * 8;
            unsigned a[2][4];
            #pragma unroll
            for (int mt = 0; mt < 2; mt++) {
                int r = wm * 32 + mt * 16 + g;
                a[mt][0] = As[r * 20 + k8 + q];
                a[mt][1] = As[(r + 8) * 20 + k8 + q];
                a[mt][2] = As[r * 20 + k8 + q + 4];
                a[mt][3] = As[(r + 8) * 20 + k8 + q + 4];
            }
            #pragma unroll
            for (int nt = 0; nt < 16; nt++) {
                int cn = wn * 128 + nt * 8 + g;
                unsigned b[2];
                b[0] = Bs[(k8 + q) * 264 + cn];
                b[1] = Bs[(k8 + q + 4) * 264 + cn];
                MMA_F16(c[0][nt], a[0], b);
                MMA_F16(c[1][nt], a[1], b);
            }
        }
        __syncthreads();
    }

    #pragma unroll
    for (int mt = 0; mt < 2; mt++) {
        #pragma unroll
        for (int half = 0; half < 2; half++) {
            int row = bm + wm * 32 + mt * 16 + half * 8 + g;
            int rowp = (row < NP) ? (row >> 6) : ((row - NP) >> 6);
            #pragma unroll
            for (int nt = 0; nt < 16; nt++) {
                int col = bn + wn * 128 + nt * 8 + q * 2;
                float v0 = c[mt][nt][half * 2 + 0] + bias[col] + lfE[(size_t)rowp * 512 + col];
                float v1 = c[mt][nt][half * 2 + 1] + bias[col + 1] + lfE[(size_t)rowp * 512 + col + 1];
                g_g1h[(size_t)row * 256 + (col >> 1)] =
                    __floats2half2_rn(fmaxf(v0, 0.f), fmaxf(v1, 0.f));
            }
        }
    }
}

// ------- g2 fp16 (128x256 tile, K=512, 3-stage) fused with rot + outputs -----
__global__ void __launch_bounds__(256)
gemm_g2rot(const float* __restrict__ mb2, const float* __restrict__ mw3,
           const float* __restrict__ mb3, const float* __restrict__ pos,
           float* __restrict__ out)
{
    extern __shared__ float psm[];
    unsigned* Asm[3] = { (unsigned*)psm, (unsigned*)psm + 2560, (unsigned*)psm + 5120 };
    unsigned* Bsm[3] = { (unsigned*)psm + 7680, (unsigned*)psm + 7680 + 4224,
                         (unsigned*)psm + 7680 + 8448 };
    const int t = threadIdx.x;
    const int warp = t >> 5, lane = t & 31;
    const int g = lane >> 2, q = lane & 3;
    const int wm = warp >> 1, wn = warp & 1;
    const int bm = blockIdx.x * 128;
    const unsigned* Au = (const unsigned*)g_g1h;    // [M2][256] half2
    const unsigned* Bu = (const unsigned*)g_wt2h;   // [256][256] half2

    float c[2][16][4];
    #pragma unroll
    for (int i = 0; i < 2; i++)
        #pragma unroll
        for (int j = 0; j < 16; j++)
            #pragma unroll
            for (int e = 0; e < 4; e++) c[i][j][e] = 0.f;

    auto issue = [&](int tt) {
        int s = tt % 3;
        int kk0 = tt * 16;
        #pragma unroll
        for (int i = 0; i < 2; i++) {
            int e = t + i * 256; int r = e >> 2, cu = (e & 3) * 4;
            cp16(&Asm[s][r * 20 + cu], Au + (size_t)(bm + r) * 256 + kk0 + cu);
        }
        #pragma unroll
        for (int i = 0; i < 4; i++) {
            int e = t + i * 256; int r = e >> 6, cu = (e & 63) * 4;
            cp16(&Bsm[s][r * 264 + cu], Bu + (size_t)(kk0 + r) * 256 + cu);
        }
    };

    issue(0); asm volatile("cp.async.commit_group;");
    issue(1); asm volatile("cp.async.commit_group;");

    for (int tt = 0; tt < 16; tt++) {
        if (tt + 1 < 16) { asm volatile("cp.async.wait_group 1;"); }
        else             { asm volatile("cp.async.wait_group 0;"); }
        __syncthreads();     // buf tt ready; prev mma done
        if (tt + 2 < 16) {
            issue(tt + 2);   // overlaps mma(tt)
            asm volatile("cp.async.commit_group;");
        }
        const unsigned* As = Asm[tt % 3];
        const unsigned* Bs = Bsm[tt % 3];
        #pragma unroll
        for (int ks = 0; ks < 2; ks++) {
            int k8 = ks * 8;
            unsigned a[2][4];
            #pragma unroll
            for (int mt = 0; mt < 2; mt++) {
                int r = wm * 32 + mt * 16 + g;
                a[mt][0] = As[r * 20 + k8 + q];
                a[mt][1] = As[(r + 8) * 20 + k8 + q];
                a[mt][2] = As[r * 20 + k8 + q + 4];
                a[mt][3] = As[(r + 8) * 20 + k8 + q + 4];
            }
            #pragma unroll
            for (int nt = 0; nt < 16; nt++) {
                int cn = wn * 128 + nt * 8 + g;
                unsigned b[2];
                b[0] = Bs[(k8 + q) * 264 + cn];
                b[1] = Bs[(k8 + q + 4) * 264 + cn];
                MMA_F16(c[0][nt], a[0], b);
                MMA_F16(c[1][nt], a[1], b);
            }
        }
    }
    __syncthreads();   // all mma done before smem reuse

    // epilogue: v = relu(c + mb2); partial dots with mw3; reduce 8 slots/row
    float* sred = psm;   // 128 rows * 8 slots * 9 = 9216 floats
    #pragma unroll
    for (int mt = 0; mt < 2; mt++) {
        #pragma unroll
        for (int half = 0; half < 2; half++) {
            int row_l = wm * 32 + mt * 16 + half * 8 + g;
            float p9[9];
            #pragma unroll
            for (int j = 0; j < 9; j++) p9[j] = 0.f;
            #pragma unroll
            for (int nt = 0; nt < 16; nt++) {
                int col = wn * 128 + nt * 8 + q * 2;
                float v0 = fmaxf(c[mt][nt][half * 2 + 0] + mb2[col], 0.f);
                float v1 = fmaxf(c[mt][nt][half * 2 + 1] + mb2[col + 1], 0.f);
                #pragma unroll
                for (int j = 0; j < 9; j++)
                    p9[j] += v0 * mw3[col * 9 + j] + v1 * mw3[(col + 1) * 9 + j];
            }
            int slot = wn * 4 + q;
            #pragma unroll
            for (int j = 0; j < 9; j++)
                sred[(row_l * 8 + slot) * 9 + j] = p9[j];
        }
    }
    __syncthreads();
    if (t < 128) {
        float r9[9];
        #pragma unroll
        for (int j = 0; j < 9; j++) {
            float s = 0.f;
            #pragma unroll
            for (int sl = 0; sl < 8; sl++) s += sred[(t * 8 + sl) * 9 + j];
            r9[j] = fmaxf(s + mb3[j], 0.f);
        }
        int n = bm + t;
        float* oc = out + (size_t)16 * M2 * 3 + (size_t)n * 9;
        #pragma unroll
        for (int i = 0; i < 3; i++)
            #pragma unroll
            for (int j = 0; j < 3; j++)
                oc[i * 3 + j] = r9[0 + i] * r9[0 + j] + r9[3 + i] * r9[3 + j] + r9[6 + i] * r9[6 + j];
        const float XV[4] = {-0.2f, -0.066666666666666666f, 0.066666666666666666f, 0.2f};
        #pragma unroll
        for (int t4 = 0; t4 < 16; t4++) {
            float nx = XV[t4 & 3], ny = XV[t4 >> 2];
            int m = (n * 16 + t4) & (M2 - 1);
            float cx, cy, cz;
            if (m < NP) { cx = pos[m * 3]; cy = pos[m * 3 + 1]; cz = pos[m * 3 + 2]; }
            else { int mm = m - NP; cx = g_npos[mm * 3]; cy = g_npos[mm * 3 + 1]; cz = g_npos[mm * 3 + 2]; }
            float* op = out + (size_t)(n * 16 + t4) * 3;
            op[0] = r9[0] * nx + r9[1] * ny + cx;
            op[1] = r9[3] * nx + r9[4] * ny + cy;
            op[2] = r9[6] * nx + r9[7] * ny + cz;
        }
    }
}

// ---------------- host launcher ----------------------------------------------
extern "C" void kernel_launch(void* const* d_in, const int* in_sizes, int n_in,
                              void* d_out, int out_size)
{
    const float* pos = (const float*)d_in[1];
    const float* lfea = (const float*)d_in[4];
    const float* sw1 = (const float*)d_in[5];
    const float* sb1 = (const float*)d_in[6];
    const float* sw2 = (const float*)d_in[7];
    const float* sb2 = (const float*)d_in[8];
    const float* sw3 = (const float*)d_in[9];
    const float* sb3 = (const float*)d_in[10];
    const float* cw1 = (const float*)d_in[11];
    const float* cb1 = (const float*)d_in[12];
    const float* cw2 = (const float*)d_in[13];
    const float* cb2 = (const float*)d_in[14];
    const float* mw1 = (const float*)d_in[15];
    const float* mb1 = (const float*)d_in[16];
    const float* mw2 = (const float*)d_in[17];
    const float* mb2 = (const float*)d_in[18];
    const float* mw3 = (const float*)d_in[19];
    const float* mb3 = (const float*)d_in[20];
    float* out = (float*)d_out;

    float* p_lf_m1;
    cudaGetSymbolAddress((void**)&p_lf_m1, g_lf_m1);

    cudaFuncSetAttribute(tc3mega, cudaFuncAttributeMaxDynamicSharedMemorySize, 56576);
    cudaFuncSetAttribute(gemm_g1h, cudaFuncAttributeMaxDynamicSharedMemorySize, 54272);
    cudaFuncSetAttribute(gemm_g2rot, cudaFuncAttributeMaxDynamicSharedMemorySize, 81408);

    // 1-2. fused lf GEMM (virtual N=768) split-K + reduce (+weight pack +sb1 fold)
    gemm_sk2<<<dim3(12, 4, 6), 256>>>(lfea, sw1, mw1);
    k_red2<<<768, 256>>>(sb1, mw1 + 768 * 512, mw2, cw2, sw2);
    // 3. mega: h1 -> h2 (fp16 hi/lo, staged pipeline) -> n_pos -> KNN -> U/V
    tc3mega<<<dim3(1, 128), 256, 56576>>>(pos, sw1, sb2, sw3, sb3, cw1, cb1);
    // 4. edge MLP phase-B (fp16 mma, double-buffered)
    k_edge2<<<512, 256, 35840>>>(cb2);
    // 5. g1 = relu(pos_fea @ mw1' + lf_m1[p] + mb1) — fp16 mma
    gemm_g1h<<<dim3(2, 256), 256, 54272>>>(mb1, p_lf_m1);
    // 6. g2 + rot + outputs, all fused — fp16 mma, 3-stage pipeline
    gemm_g2rot<<<256, 256, 81408>>>(mb2, mw3, mb3, pos, out);
}